// round 1
// baseline (speedup 1.0000x reference)
#include <cuda_runtime.h>
#include <math.h>
#include <stdint.h>

#define NN 40000
#define NE 640000
#define NG 128
#define NIN 64
#define NH 128
#define NO 256

// ---------------- scratch (device globals; no allocation allowed) ----------------
__device__ float g_xl[NN * NH];
__device__ float g_xr[NN * NH];
__device__ float g_agg[NN * NH];
__device__ float g_h0[NN * NH];
__device__ float g_h1[NN * NH];
__device__ float g_e[NE];
__device__ float g_ex[NE];
__device__ int   g_m[NN];
__device__ float g_s[NN];
__device__ float g_pool[NG * NH];
__device__ float g_cnt[NG];

// ---------------- helpers ----------------
__device__ __forceinline__ int encf(float f) {
    int i = __float_as_int(f);
    return i < 0 ? (i ^ 0x7FFFFFFF) : i;
}
__device__ __forceinline__ float decf(int k) {
    return __int_as_float(k < 0 ? (k ^ 0x7FFFFFFF) : k);
}
__device__ __forceinline__ float lrelu(float v) { return v > 0.f ? v : 0.2f * v; }

// ---------------- GEMM: C[M,N] = A[M,K] @ B[K,N] (+bias) (+A-residual) ----------------
// BM=64, BN=64, BK=16, 256 threads, 4x4 per thread. M%64==0, N%64==0, K%16==0.
template <bool BIAS, bool ADDIN>
__global__ void gemm64(const float* __restrict__ A, const float* __restrict__ B,
                       const float* __restrict__ bias, const float* __restrict__ add,
                       float* __restrict__ C, int M, int N, int K) {
    __shared__ float As[16][64];
    __shared__ float Bs[16][64];
    int tid = threadIdx.x;
    int tx = tid & 15, ty = tid >> 4;
    int bm = blockIdx.x * 64, bn = blockIdx.y * 64;
    float acc[4][4] = {};
    int arow = tid >> 2, ac4 = (tid & 3) * 4;
    int brow = tid >> 4, bc4 = (tid & 15) * 4;
    for (int k0 = 0; k0 < K; k0 += 16) {
        float4 av = *(const float4*)&A[(size_t)(bm + arow) * K + k0 + ac4];
        As[ac4 + 0][arow] = av.x;
        As[ac4 + 1][arow] = av.y;
        As[ac4 + 2][arow] = av.z;
        As[ac4 + 3][arow] = av.w;
        *(float4*)&Bs[brow][bc4] = *(const float4*)&B[(size_t)(k0 + brow) * N + bn + bc4];
        __syncthreads();
#pragma unroll
        for (int kk = 0; kk < 16; kk++) {
            float4 a4 = *(const float4*)&As[kk][ty * 4];
            float4 b4 = *(const float4*)&Bs[kk][tx * 4];
            float ar[4] = {a4.x, a4.y, a4.z, a4.w};
            float br[4] = {b4.x, b4.y, b4.z, b4.w};
#pragma unroll
            for (int i = 0; i < 4; i++)
#pragma unroll
                for (int j = 0; j < 4; j++) acc[i][j] += ar[i] * br[j];
        }
        __syncthreads();
    }
#pragma unroll
    for (int i = 0; i < 4; i++) {
        int r = bm + ty * 4 + i;
        int c = bn + tx * 4;
        float4 v = make_float4(acc[i][0], acc[i][1], acc[i][2], acc[i][3]);
        if (BIAS) {
            v.x += bias[c]; v.y += bias[c + 1]; v.z += bias[c + 2]; v.w += bias[c + 3];
        }
        if (ADDIN) {
            float4 w = *(const float4*)&add[(size_t)r * N + c];
            v.x += w.x; v.y += w.y; v.z += w.z; v.w += w.w;
        }
        *(float4*)&C[(size_t)r * N + c] = v;
    }
}

// ---------------- per-layer init ----------------
__global__ void init_layer_kernel(float* __restrict__ agg, float* __restrict__ s,
                                  int* __restrict__ m) {
    int i = blockIdx.x * blockDim.x + threadIdx.x;
    if (i < NN * NH) agg[i] = 0.f;
    if (i < NN) {
        s[i] = 0.f;
        m[i] = encf(-3.0e38f);
    }
}

// ---------------- edge pass 1: e = att . leaky_relu(xl[src]+xr[dst]); seg-max ----------------
__global__ void edge_e_kernel(const float* __restrict__ xl, const float* __restrict__ xr,
                              const int* __restrict__ src, const int* __restrict__ dst,
                              const float* __restrict__ att, float* __restrict__ e,
                              int* __restrict__ m) {
    int w = (blockIdx.x * blockDim.x + threadIdx.x) >> 5;
    if (w >= NE) return;
    int lane = threadIdx.x & 31;
    int sn = src[w], dn = dst[w];
    float4 a = ((const float4*)xl)[sn * 32 + lane];
    float4 b = ((const float4*)xr)[dn * 32 + lane];
    float4 t = ((const float4*)att)[lane];
    float acc = lrelu(a.x + b.x) * t.x + lrelu(a.y + b.y) * t.y +
                lrelu(a.z + b.z) * t.z + lrelu(a.w + b.w) * t.w;
#pragma unroll
    for (int o = 16; o; o >>= 1) acc += __shfl_xor_sync(0xFFFFFFFFu, acc, o);
    if (lane == 0) {
        e[w] = acc;
        atomicMax(&m[dn], encf(acc));
    }
}

// ---------------- edge pass 2: ex = exp(e - m[dst]); seg-sum ----------------
__global__ void edge_exp_kernel(const float* __restrict__ e, const int* __restrict__ dst,
                                const int* __restrict__ m, float* __restrict__ ex,
                                float* __restrict__ s) {
    int i = blockIdx.x * blockDim.x + threadIdx.x;
    if (i >= NE) return;
    int d = dst[i];
    float v = __expf(e[i] - decf(m[d]));
    ex[i] = v;
    atomicAdd(&s[d], v);
}

// ---------------- edge pass 3: agg[dst] += alpha * xl[src] ----------------
__global__ void edge_scatter_kernel(const float* __restrict__ ex, const float* __restrict__ s,
                                    const int* __restrict__ src, const int* __restrict__ dst,
                                    const float* __restrict__ xl, float* __restrict__ agg) {
    int w = (blockIdx.x * blockDim.x + threadIdx.x) >> 5;
    if (w >= NE) return;
    int lane = threadIdx.x & 31;
    int sn = src[w], dn = dst[w];
    float alpha = ex[w] / (s[dn] + 1e-16f);
    float4 v = ((const float4*)xl)[sn * 32 + lane];
    v.x *= alpha; v.y *= alpha; v.z *= alpha; v.w *= alpha;
    atomicAdd((float4*)(agg + (size_t)dn * NH + lane * 4), v);
}

// ---------------- epilogue: out = scale * relu(agg + b) ----------------
__global__ void epi_kernel(const float* __restrict__ agg, const float* __restrict__ b,
                           float* __restrict__ out, float scale) {
    int i = blockIdx.x * blockDim.x + threadIdx.x;
    if (i >= NN * NH) return;
    float v = fmaxf(agg[i] + b[i & (NH - 1)], 0.f);
    out[i] = v * scale;
}

// ---------------- pooling ----------------
__global__ void init_pool_kernel(float* __restrict__ pool, float* __restrict__ cnt) {
    int i = blockIdx.x * blockDim.x + threadIdx.x;
    if (i < NG * NH) pool[i] = 0.f;
    if (i < NG) cnt[i] = 0.f;
}

__global__ void pool_kernel(const float* __restrict__ h, const int* __restrict__ batch,
                            float* __restrict__ pool, float* __restrict__ cnt) {
    int w = (blockIdx.x * blockDim.x + threadIdx.x) >> 5;
    if (w >= NN) return;
    int lane = threadIdx.x & 31;
    int g = batch[w];
    float4 v = ((const float4*)h)[w * 32 + lane];
    atomicAdd((float4*)(pool + (size_t)g * NH + lane * 4), v);
    if (lane == 0) atomicAdd(&cnt[g], 1.f);
}

// ---------------- final MLP + layernorm: one block per graph ----------------
__global__ void mlp_kernel(const float* __restrict__ pool, const float* __restrict__ cnt,
                           const float* __restrict__ w1, const float* __restrict__ b1,
                           const float* __restrict__ w2, const float* __restrict__ b2,
                           const float* __restrict__ lng, const float* __restrict__ lnb,
                           float* __restrict__ out) {
    int g = blockIdx.x;
    int t = threadIdx.x;  // 256 threads
    __shared__ float p[NH];
    __shared__ float z1[2 * NH];
    __shared__ float rs[8], rq[8];
    float inv = 1.f / fmaxf(cnt[g], 1.f);
    if (t < NH) p[t] = pool[g * NH + t] * inv;
    __syncthreads();
    float a = 0.f;
#pragma unroll 8
    for (int k = 0; k < NH; k++) a += p[k] * w1[k * (2 * NH) + t];
    z1[t] = fmaxf(a + b1[t], 0.f);
    __syncthreads();
    float z = 0.f;
#pragma unroll 8
    for (int k = 0; k < 2 * NH; k++) z += z1[k] * w2[k * NO + t];
    z += b2[t];
    float v = z, v2 = z * z;
#pragma unroll
    for (int o = 16; o; o >>= 1) {
        v += __shfl_xor_sync(0xFFFFFFFFu, v, o);
        v2 += __shfl_xor_sync(0xFFFFFFFFu, v2, o);
    }
    int wid = t >> 5, lane = t & 31;
    if (lane == 0) { rs[wid] = v; rq[wid] = v2; }
    __syncthreads();
    if (wid == 0) {
        float sv = lane < 8 ? rs[lane] : 0.f;
        float sq = lane < 8 ? rq[lane] : 0.f;
#pragma unroll
        for (int o = 4; o; o >>= 1) {
            sv += __shfl_xor_sync(0xFFFFFFFFu, sv, o);
            sq += __shfl_xor_sync(0xFFFFFFFFu, sq, o);
        }
        if (lane == 0) { rs[0] = sv; rq[0] = sq; }
    }
    __syncthreads();
    float mu = rs[0] * (1.f / NO);
    float var = rq[0] * (1.f / NO) - mu * mu;
    out[g * NO + t] = (z - mu) * rsqrtf(var + 1e-5f) * lng[t] + lnb[t];
}

// ---------------- host ----------------
extern "C" void kernel_launch(void* const* d_in, const int* in_sizes, int n_in,
                              void* d_out, int out_size) {
    const float* x = (const float*)d_in[0];
    const int* ei = (const int*)d_in[1];
    const int* src = ei;
    const int* dst = ei + NE;
    const int* batch = (const int*)d_in[2];
    const float* Wl[4] = {(const float*)d_in[3], (const float*)d_in[7],
                          (const float*)d_in[11], (const float*)d_in[15]};
    const float* Wr[4] = {(const float*)d_in[4], (const float*)d_in[8],
                          (const float*)d_in[12], (const float*)d_in[16]};
    const float* att[4] = {(const float*)d_in[5], (const float*)d_in[9],
                           (const float*)d_in[13], (const float*)d_in[17]};
    const float* bb[4] = {(const float*)d_in[6], (const float*)d_in[10],
                          (const float*)d_in[14], (const float*)d_in[18]};
    const float* res_w0 = (const float*)d_in[19];
    const float* res_b0 = (const float*)d_in[20];
    const float* res_w2 = (const float*)d_in[21];
    const float* res_b2 = (const float*)d_in[22];
    const float* mh1_w = (const float*)d_in[23];
    const float* mh1_b = (const float*)d_in[24];
    const float* mh2_w = (const float*)d_in[25];
    const float* mh2_b = (const float*)d_in[26];
    const float* ln_g = (const float*)d_in[27];
    const float* ln_b = (const float*)d_in[28];
    float* out = (float*)d_out;

    float *xl, *xr, *agg, *h0, *h1, *e, *ex, *s, *pool, *cnt;
    int* m;
    cudaGetSymbolAddress((void**)&xl, g_xl);
    cudaGetSymbolAddress((void**)&xr, g_xr);
    cudaGetSymbolAddress((void**)&agg, g_agg);
    cudaGetSymbolAddress((void**)&h0, g_h0);
    cudaGetSymbolAddress((void**)&h1, g_h1);
    cudaGetSymbolAddress((void**)&e, g_e);
    cudaGetSymbolAddress((void**)&ex, g_ex);
    cudaGetSymbolAddress((void**)&m, g_m);
    cudaGetSymbolAddress((void**)&s, g_s);
    cudaGetSymbolAddress((void**)&pool, g_pool);
    cudaGetSymbolAddress((void**)&cnt, g_cnt);

    dim3 gg(NN / 64, NH / 64);  // 625 x 2
    const int EPI_BLK = (NN * NH + 255) / 256;
    const int EDGE_WARP_BLK = (NE * 32) / 256;  // 80000
    const int EDGE_THR_BLK = (NE + 255) / 256;

    auto gat = [&](const float* hin, int K, int li) {
        gemm64<false, false><<<gg, 256>>>(hin, Wl[li], nullptr, nullptr, xl, NN, NH, K);
        gemm64<false, false><<<gg, 256>>>(hin, Wr[li], nullptr, nullptr, xr, NN, NH, K);
        init_layer_kernel<<<EPI_BLK, 256>>>(agg, s, m);
        edge_e_kernel<<<EDGE_WARP_BLK, 256>>>(xl, xr, src, dst, att[li], e, m);
        edge_exp_kernel<<<EDGE_THR_BLK, 256>>>(e, dst, m, ex, s);
        edge_scatter_kernel<<<EDGE_WARP_BLK, 256>>>(ex, s, src, dst, xl, agg);
    };

    // layer 1: relu -> h0; h1 = h0@res_w0 + res_b0 + h0
    gat(x, NIN, 0);
    epi_kernel<<<EPI_BLK, 256>>>(agg, bb[0], h0, 1.f);
    gemm64<true, true><<<gg, 256>>>(h0, res_w0, res_b0, h0, h1, NN, NH, NH);

    // layer 2: h0 = 2*relu(gat)
    gat(h1, NH, 1);
    epi_kernel<<<EPI_BLK, 256>>>(agg, bb[1], h0, 2.f);

    // layer 3: relu -> h1; h0 = h1@res_w2 + res_b2 + h1
    gat(h0, NH, 2);
    epi_kernel<<<EPI_BLK, 256>>>(agg, bb[2], h1, 1.f);
    gemm64<true, true><<<gg, 256>>>(h1, res_w2, res_b2, h1, h0, NN, NH, NH);

    // layer 4: h1 = 2*relu(gat)
    gat(h0, NH, 3);
    epi_kernel<<<EPI_BLK, 256>>>(agg, bb[3], h1, 2.f);

    // pooling + MLP + layernorm
    init_pool_kernel<<<(NG * NH + 255) / 256, 256>>>(pool, cnt);
    pool_kernel<<<(NN * 32 + 255) / 256, 256>>>(h1, batch, pool, cnt);
    mlp_kernel<<<NG, 256>>>(pool, cnt, mh1_w, mh1_b, mh2_w, mh2_b, ln_g, ln_b, out);
}

// round 2
// speedup vs baseline: 1.0072x; 1.0072x over previous
#include <cuda_runtime.h>
#include <math.h>
#include <stdint.h>

#define NN 40000
#define NE 640000
#define NG 128
#define NIN 64
#define NH 128
#define NO 256

// ---------------- scratch (device globals; no allocation allowed) ----------------
__device__ float g_xl[NN * NH];
__device__ float g_xr[NN * NH];
__device__ float g_agg[NN * NH];
__device__ float g_h0[NN * NH];
__device__ float g_h1[NN * NH];
__device__ float g_e[NE];
__device__ float g_ex[NE];
__device__ int   g_m[NN];
__device__ float g_s[NN];
__device__ float g_pool[NG * NH];
__device__ float g_cnt[NG];

// ---------------- helpers ----------------
__device__ __forceinline__ int encf(float f) {
    int i = __float_as_int(f);
    return i < 0 ? (i ^ 0x7FFFFFFF) : i;
}
__device__ __forceinline__ float decf(int k) {
    return __int_as_float(k < 0 ? (k ^ 0x7FFFFFFF) : k);
}
__device__ __forceinline__ float lrelu(float v) { return v > 0.f ? v : 0.2f * v; }

// ---------------- GEMM: C[M,N] = A[M,K] @ B[K,N] (+bias) (+A-residual) ----------------
// BM=64, BN=64, BK=16, 256 threads, 4x4 per thread. M%64==0, N%64==0, K%16==0.
template <bool BIAS, bool ADDIN>
__global__ void gemm64(const float* __restrict__ A, const float* __restrict__ B,
                       const float* __restrict__ bias, const float* __restrict__ add,
                       float* __restrict__ C, int M, int N, int K) {
    __shared__ float As[16][64];
    __shared__ float Bs[16][64];
    int tid = threadIdx.x;
    int tx = tid & 15, ty = tid >> 4;
    int bm = blockIdx.x * 64, bn = blockIdx.y * 64;
    float acc[4][4] = {};
    int arow = tid >> 2, ac4 = (tid & 3) * 4;
    int brow = tid >> 4, bc4 = (tid & 15) * 4;
    for (int k0 = 0; k0 < K; k0 += 16) {
        float4 av = *(const float4*)&A[(size_t)(bm + arow) * K + k0 + ac4];
        As[ac4 + 0][arow] = av.x;
        As[ac4 + 1][arow] = av.y;
        As[ac4 + 2][arow] = av.z;
        As[ac4 + 3][arow] = av.w;
        *(float4*)&Bs[brow][bc4] = *(const float4*)&B[(size_t)(k0 + brow) * N + bn + bc4];
        __syncthreads();
#pragma unroll
        for (int kk = 0; kk < 16; kk++) {
            float4 a4 = *(const float4*)&As[kk][ty * 4];
            float4 b4 = *(const float4*)&Bs[kk][tx * 4];
            float ar[4] = {a4.x, a4.y, a4.z, a4.w};
            float br[4] = {b4.x, b4.y, b4.z, b4.w};
#pragma unroll
            for (int i = 0; i < 4; i++)
#pragma unroll
                for (int j = 0; j < 4; j++) acc[i][j] += ar[i] * br[j];
        }
        __syncthreads();
    }
#pragma unroll
    for (int i = 0; i < 4; i++) {
        int r = bm + ty * 4 + i;
        int c = bn + tx * 4;
        float4 v = make_float4(acc[i][0], acc[i][1], acc[i][2], acc[i][3]);
        if (BIAS) {
            v.x += bias[c]; v.y += bias[c + 1]; v.z += bias[c + 2]; v.w += bias[c + 3];
        }
        if (ADDIN) {
            float4 w = *(const float4*)&add[(size_t)r * N + c];
            v.x += w.x; v.y += w.y; v.z += w.z; v.w += w.w;
        }
        *(float4*)&C[(size_t)r * N + c] = v;
    }
}

// ---------------- per-layer init ----------------
__global__ void init_layer_kernel(float* __restrict__ agg, float* __restrict__ s,
                                  int* __restrict__ m) {
    int i = blockIdx.x * blockDim.x + threadIdx.x;
    if (i < NN * NH) agg[i] = 0.f;
    if (i < NN) {
        s[i] = 0.f;
        m[i] = encf(-3.0e38f);
    }
}

// ---------------- edge pass 1: e = att . leaky_relu(xl[src]+xr[dst]); seg-max ----------------
__global__ void edge_e_kernel(const float* __restrict__ xl, const float* __restrict__ xr,
                              const int* __restrict__ src, const int* __restrict__ dst,
                              const float* __restrict__ att, float* __restrict__ e,
                              int* __restrict__ m) {
    int w = (blockIdx.x * blockDim.x + threadIdx.x) >> 5;
    if (w >= NE) return;
    int lane = threadIdx.x & 31;
    int sn = src[w], dn = dst[w];
    float4 a = ((const float4*)xl)[sn * 32 + lane];
    float4 b = ((const float4*)xr)[dn * 32 + lane];
    float4 t = ((const float4*)att)[lane];
    float acc = lrelu(a.x + b.x) * t.x + lrelu(a.y + b.y) * t.y +
                lrelu(a.z + b.z) * t.z + lrelu(a.w + b.w) * t.w;
#pragma unroll
    for (int o = 16; o; o >>= 1) acc += __shfl_xor_sync(0xFFFFFFFFu, acc, o);
    if (lane == 0) {
        e[w] = acc;
        atomicMax(&m[dn], encf(acc));
    }
}

// ---------------- edge pass 2: ex = exp(e - m[dst]); seg-sum ----------------
__global__ void edge_exp_kernel(const float* __restrict__ e, const int* __restrict__ dst,
                                const int* __restrict__ m, float* __restrict__ ex,
                                float* __restrict__ s) {
    int i = blockIdx.x * blockDim.x + threadIdx.x;
    if (i >= NE) return;
    int d = dst[i];
    float v = __expf(e[i] - decf(m[d]));
    ex[i] = v;
    atomicAdd(&s[d], v);
}

// ---------------- edge pass 3: agg[dst] += alpha * xl[src] ----------------
__global__ void edge_scatter_kernel(const float* __restrict__ ex, const float* __restrict__ s,
                                    const int* __restrict__ src, const int* __restrict__ dst,
                                    const float* __restrict__ xl, float* __restrict__ agg) {
    int w = (blockIdx.x * blockDim.x + threadIdx.x) >> 5;
    if (w >= NE) return;
    int lane = threadIdx.x & 31;
    int sn = src[w], dn = dst[w];
    float alpha = ex[w] / (s[dn] + 1e-16f);
    float4 v = ((const float4*)xl)[sn * 32 + lane];
    v.x *= alpha; v.y *= alpha; v.z *= alpha; v.w *= alpha;
    atomicAdd((float4*)(agg + (size_t)dn * NH + lane * 4), v);
}

// ---------------- epilogue: out = scale * relu(agg + b) ----------------
__global__ void epi_kernel(const float* __restrict__ agg, const float* __restrict__ b,
                           float* __restrict__ out, float scale) {
    int i = blockIdx.x * blockDim.x + threadIdx.x;
    if (i >= NN * NH) return;
    float v = fmaxf(agg[i] + b[i & (NH - 1)], 0.f);
    out[i] = v * scale;
}

// ---------------- pooling ----------------
__global__ void init_pool_kernel(float* __restrict__ pool, float* __restrict__ cnt) {
    int i = blockIdx.x * blockDim.x + threadIdx.x;
    if (i < NG * NH) pool[i] = 0.f;
    if (i < NG) cnt[i] = 0.f;
}

__global__ void pool_kernel(const float* __restrict__ h, const int* __restrict__ batch,
                            float* __restrict__ pool, float* __restrict__ cnt) {
    int w = (blockIdx.x * blockDim.x + threadIdx.x) >> 5;
    if (w >= NN) return;
    int lane = threadIdx.x & 31;
    int g = batch[w];
    float4 v = ((const float4*)h)[w * 32 + lane];
    atomicAdd((float4*)(pool + (size_t)g * NH + lane * 4), v);
    if (lane == 0) atomicAdd(&cnt[g], 1.f);
}

// ---------------- final MLP + layernorm: one block per graph ----------------
__global__ void mlp_kernel(const float* __restrict__ pool, const float* __restrict__ cnt,
                           const float* __restrict__ w1, const float* __restrict__ b1,
                           const float* __restrict__ w2, const float* __restrict__ b2,
                           const float* __restrict__ lng, const float* __restrict__ lnb,
                           float* __restrict__ out) {
    int g = blockIdx.x;
    int t = threadIdx.x;  // 256 threads
    __shared__ float p[NH];
    __shared__ float z1[2 * NH];
    __shared__ float rs[8], rq[8];
    float inv = 1.f / fmaxf(cnt[g], 1.f);
    if (t < NH) p[t] = pool[g * NH + t] * inv;
    __syncthreads();
    float a = 0.f;
#pragma unroll 8
    for (int k = 0; k < NH; k++) a += p[k] * w1[k * (2 * NH) + t];
    z1[t] = fmaxf(a + b1[t], 0.f);
    __syncthreads();
    float z = 0.f;
#pragma unroll 8
    for (int k = 0; k < 2 * NH; k++) z += z1[k] * w2[k * NO + t];
    z += b2[t];
    float v = z, v2 = z * z;
#pragma unroll
    for (int o = 16; o; o >>= 1) {
        v += __shfl_xor_sync(0xFFFFFFFFu, v, o);
        v2 += __shfl_xor_sync(0xFFFFFFFFu, v2, o);
    }
    int wid = t >> 5, lane = t & 31;
    if (lane == 0) { rs[wid] = v; rq[wid] = v2; }
    __syncthreads();
    if (wid == 0) {
        float sv = lane < 8 ? rs[lane] : 0.f;
        float sq = lane < 8 ? rq[lane] : 0.f;
#pragma unroll
        for (int o = 4; o; o >>= 1) {
            sv += __shfl_xor_sync(0xFFFFFFFFu, sv, o);
            sq += __shfl_xor_sync(0xFFFFFFFFu, sq, o);
        }
        if (lane == 0) { rs[0] = sv; rq[0] = sq; }
    }
    __syncthreads();
    float mu = rs[0] * (1.f / NO);
    float var = rq[0] * (1.f / NO) - mu * mu;
    out[g * NO + t] = (z - mu) * rsqrtf(var + 1e-5f) * lng[t] + lnb[t];
}

// ---------------- host ----------------
extern "C" void kernel_launch(void* const* d_in, const int* in_sizes, int n_in,
                              void* d_out, int out_size) {
    const float* x = (const float*)d_in[0];
    const int* ei = (const int*)d_in[1];
    const int* src = ei;
    const int* dst = ei + NE;
    const int* batch = (const int*)d_in[2];
    const float* Wl[4] = {(const float*)d_in[3], (const float*)d_in[7],
                          (const float*)d_in[11], (const float*)d_in[15]};
    const float* Wr[4] = {(const float*)d_in[4], (const float*)d_in[8],
                          (const float*)d_in[12], (const float*)d_in[16]};
    const float* att[4] = {(const float*)d_in[5], (const float*)d_in[9],
                           (const float*)d_in[13], (const float*)d_in[17]};
    const float* bb[4] = {(const float*)d_in[6], (const float*)d_in[10],
                          (const float*)d_in[14], (const float*)d_in[18]};
    const float* res_w0 = (const float*)d_in[19];
    const float* res_b0 = (const float*)d_in[20];
    const float* res_w2 = (const float*)d_in[21];
    const float* res_b2 = (const float*)d_in[22];
    const float* mh1_w = (const float*)d_in[23];
    const float* mh1_b = (const float*)d_in[24];
    const float* mh2_w = (const float*)d_in[25];
    const float* mh2_b = (const float*)d_in[26];
    const float* ln_g = (const float*)d_in[27];
    const float* ln_b = (const float*)d_in[28];
    float* out = (float*)d_out;

    float *xl, *xr, *agg, *h0, *h1, *e, *ex, *s, *pool, *cnt;
    int* m;
    cudaGetSymbolAddress((void**)&xl, g_xl);
    cudaGetSymbolAddress((void**)&xr, g_xr);
    cudaGetSymbolAddress((void**)&agg, g_agg);
    cudaGetSymbolAddress((void**)&h0, g_h0);
    cudaGetSymbolAddress((void**)&h1, g_h1);
    cudaGetSymbolAddress((void**)&e, g_e);
    cudaGetSymbolAddress((void**)&ex, g_ex);
    cudaGetSymbolAddress((void**)&m, g_m);
    cudaGetSymbolAddress((void**)&s, g_s);
    cudaGetSymbolAddress((void**)&pool, g_pool);
    cudaGetSymbolAddress((void**)&cnt, g_cnt);

    dim3 gg(NN / 64, NH / 64);  // 625 x 2
    const int EPI_BLK = (NN * NH + 255) / 256;
    const int EDGE_WARP_BLK = (NE * 32) / 256;  // 80000
    const int EDGE_THR_BLK = (NE + 255) / 256;

    auto gat = [&](const float* hin, int K, int li) {
        gemm64<false, false><<<gg, 256>>>(hin, Wl[li], nullptr, nullptr, xl, NN, NH, K);
        gemm64<false, false><<<gg, 256>>>(hin, Wr[li], nullptr, nullptr, xr, NN, NH, K);
        init_layer_kernel<<<EPI_BLK, 256>>>(agg, s, m);
        edge_e_kernel<<<EDGE_WARP_BLK, 256>>>(xl, xr, src, dst, att[li], e, m);
        edge_exp_kernel<<<EDGE_THR_BLK, 256>>>(e, dst, m, ex, s);
        edge_scatter_kernel<<<EDGE_WARP_BLK, 256>>>(ex, s, src, dst, xl, agg);
    };

    // layer 1: relu -> h0; h1 = h0@res_w0 + res_b0 + h0
    gat(x, NIN, 0);
    epi_kernel<<<EPI_BLK, 256>>>(agg, bb[0], h0, 1.f);
    gemm64<true, true><<<gg, 256>>>(h0, res_w0, res_b0, h0, h1, NN, NH, NH);

    // layer 2: h0 = 2*relu(gat)
    gat(h1, NH, 1);
    epi_kernel<<<EPI_BLK, 256>>>(agg, bb[1], h0, 2.f);

    // layer 3: relu -> h1; h0 = h1@res_w2 + res_b2 + h1
    gat(h0, NH, 2);
    epi_kernel<<<EPI_BLK, 256>>>(agg, bb[2], h1, 1.f);
    gemm64<true, true><<<gg, 256>>>(h1, res_w2, res_b2, h1, h0, NN, NH, NH);

    // layer 4: h1 = 2*relu(gat)
    gat(h0, NH, 3);
    epi_kernel<<<EPI_BLK, 256>>>(agg, bb[3], h1, 2.f);

    // pooling + MLP + layernorm
    init_pool_kernel<<<(NG * NH + 255) / 256, 256>>>(pool, cnt);
    pool_kernel<<<(NN * 32 + 255) / 256, 256>>>(h1, batch, pool, cnt);
    mlp_kernel<<<NG, 256>>>(pool, cnt, mh1_w, mh1_b, mh2_w, mh2_b, ln_g, ln_b, out);
}

// round 3
// speedup vs baseline: 1.7224x; 1.7101x over previous
#include <cuda_runtime.h>
#include <math.h>
#include <stdint.h>

#define NN 40000
#define NE 640000
#define NG 128
#define NIN 64
#define NH 128
#define NO 256

// ---------------- scratch (device globals; no allocation allowed) ----------------
__device__ float g_xlr[NN * 2 * NH];     // fused [xl | xr], 40.96 MB
__device__ float g_h0[NN * NH];
__device__ float g_h1[NN * NH];
__device__ float g_wpack[4][128 * 256];  // packed [Wl|Wr] per layer
__device__ int   g_rowoff[NN + 1];
__device__ int   g_cursor[NN];
__device__ int   g_csrc[NE];             // CSR payload: src node per (dst-grouped) slot
__device__ float g_pool[NG * NH];
__device__ float g_cnt[NG];

__device__ __forceinline__ float lrelu(float v) { return v > 0.f ? v : 0.2f * v; }

// ---------------- CSR build ----------------
__global__ void zero_cnt_kernel(int* __restrict__ cnt) {
    int i = blockIdx.x * blockDim.x + threadIdx.x;
    if (i < NN) cnt[i] = 0;
}

__global__ void hist_kernel(const int* __restrict__ dst, int* __restrict__ cnt) {
    int i = blockIdx.x * blockDim.x + threadIdx.x;
    if (i < NE) atomicAdd(&cnt[dst[i]], 1);
}

// single-block exclusive scan of cnt -> rowoff; cursor = rowoff copy
__global__ void scan_kernel(const int* __restrict__ cnt, int* __restrict__ rowoff,
                            int* __restrict__ cursor) {
    __shared__ int s_carry;
    __shared__ int warpsums[32];
    int lane = threadIdx.x & 31, wid = threadIdx.x >> 5;
    if (threadIdx.x == 0) s_carry = 0;
    __syncthreads();
    for (int base = 0; base < NN; base += 1024) {
        int i = base + (int)threadIdx.x;
        int v = (i < NN) ? cnt[i] : 0;
        int x = v;
#pragma unroll
        for (int o = 1; o < 32; o <<= 1) {
            int y = __shfl_up_sync(0xFFFFFFFFu, x, o);
            if (lane >= o) x += y;
        }
        if (lane == 31) warpsums[wid] = x;
        __syncthreads();
        if (wid == 0) {
            int w = warpsums[lane];
#pragma unroll
            for (int o = 1; o < 32; o <<= 1) {
                int y = __shfl_up_sync(0xFFFFFFFFu, w, o);
                if (lane >= o) w += y;
            }
            warpsums[lane] = w;
        }
        __syncthreads();
        int incl = x + (wid > 0 ? warpsums[wid - 1] : 0) + s_carry;
        int excl = incl - v;
        if (i < NN) { rowoff[i] = excl; cursor[i] = excl; }
        __syncthreads();
        if (threadIdx.x == 1023) s_carry = incl;
        __syncthreads();
    }
    if (threadIdx.x == 0) rowoff[NN] = NE;
}

__global__ void fill_kernel(const int* __restrict__ src, const int* __restrict__ dst,
                            int* __restrict__ cursor, int* __restrict__ csrc) {
    int i = blockIdx.x * blockDim.x + threadIdx.x;
    if (i >= NE) return;
    int pos = atomicAdd(&cursor[dst[i]], 1);
    csrc[pos] = src[i];
}

// ---------------- weight packing: Bp[k, 0:128]=Wl, Bp[k, 128:256]=Wr ----------------
__global__ void pack_w_kernel(const float* __restrict__ Wl, const float* __restrict__ Wr,
                              float* __restrict__ Bp, int K) {
    int i = blockIdx.x * blockDim.x + threadIdx.x;
    if (i >= K * 256) return;
    int r = i >> 8, c = i & 255;
    Bp[i] = (c < 128) ? Wl[r * 128 + c] : Wr[r * 128 + (c - 128)];
}

// ---------------- GEMM: C[M,N] = A[M,K] @ B[K,N] (+bias) (+A-residual) ----------------
template <bool BIAS, bool ADDIN>
__global__ void gemm64(const float* __restrict__ A, const float* __restrict__ B,
                       const float* __restrict__ bias, const float* __restrict__ add,
                       float* __restrict__ C, int M, int N, int K) {
    __shared__ float As[16][64];
    __shared__ float Bs[16][64];
    int tid = threadIdx.x;
    int tx = tid & 15, ty = tid >> 4;
    int bm = blockIdx.x * 64, bn = blockIdx.y * 64;
    float acc[4][4] = {};
    int arow = tid >> 2, ac4 = (tid & 3) * 4;
    int brow = tid >> 4, bc4 = (tid & 15) * 4;
    for (int k0 = 0; k0 < K; k0 += 16) {
        float4 av = *(const float4*)&A[(size_t)(bm + arow) * K + k0 + ac4];
        As[ac4 + 0][arow] = av.x;
        As[ac4 + 1][arow] = av.y;
        As[ac4 + 2][arow] = av.z;
        As[ac4 + 3][arow] = av.w;
        *(float4*)&Bs[brow][bc4] = *(const float4*)&B[(size_t)(k0 + brow) * N + bn + bc4];
        __syncthreads();
#pragma unroll
        for (int kk = 0; kk < 16; kk++) {
            float4 a4 = *(const float4*)&As[kk][ty * 4];
            float4 b4 = *(const float4*)&Bs[kk][tx * 4];
            float ar[4] = {a4.x, a4.y, a4.z, a4.w};
            float br[4] = {b4.x, b4.y, b4.z, b4.w};
#pragma unroll
            for (int i = 0; i < 4; i++)
#pragma unroll
                for (int j = 0; j < 4; j++) acc[i][j] += ar[i] * br[j];
        }
        __syncthreads();
    }
#pragma unroll
    for (int i = 0; i < 4; i++) {
        int r = bm + ty * 4 + i;
        int c = bn + tx * 4;
        float4 v = make_float4(acc[i][0], acc[i][1], acc[i][2], acc[i][3]);
        if (BIAS) {
            v.x += bias[c]; v.y += bias[c + 1]; v.z += bias[c + 2]; v.w += bias[c + 3];
        }
        if (ADDIN) {
            float4 w = *(const float4*)&add[(size_t)r * N + c];
            v.x += w.x; v.y += w.y; v.z += w.z; v.w += w.w;
        }
        *(float4*)&C[(size_t)r * N + c] = v;
    }
}

// ---------------- fused GAT aggregation: warp per node, online softmax ----------------
// out[i] = scale * relu( (sum_j exp(e_j - m) * xl_j) / (sum_j exp(e_j - m) + 1e-16) + bias )
__global__ void gat_agg_kernel(const float* __restrict__ xlr, const int* __restrict__ rowoff,
                               const int* __restrict__ csrc, const float* __restrict__ att,
                               const float* __restrict__ bias, float* __restrict__ out,
                               float scale) {
    int node = blockIdx.x * 8 + (threadIdx.x >> 5);
    if (node >= NN) return;
    int lane = threadIdx.x & 31;
    const float4* X = (const float4*)xlr;  // row = 64 float4s; [0,32)=xl, [32,64)=xr
    float4 xr = X[(size_t)node * 64 + 32 + lane];
    float4 t = ((const float4*)att)[lane];
    int k = rowoff[node];
    int end = rowoff[node + 1];
    float m0 = -3.0e38f, s0 = 0.f, m1 = -3.0e38f, s1 = 0.f;
    float4 a0 = {0.f, 0.f, 0.f, 0.f}, a1 = {0.f, 0.f, 0.f, 0.f};
    for (; k + 2 <= end; k += 2) {
        int sa = csrc[k], sb = csrc[k + 1];
        float4 xA = X[(size_t)sa * 64 + lane];
        float4 xB = X[(size_t)sb * 64 + lane];
        float eA = lrelu(xA.x + xr.x) * t.x + lrelu(xA.y + xr.y) * t.y +
                   lrelu(xA.z + xr.z) * t.z + lrelu(xA.w + xr.w) * t.w;
        float eB = lrelu(xB.x + xr.x) * t.x + lrelu(xB.y + xr.y) * t.y +
                   lrelu(xB.z + xr.z) * t.z + lrelu(xB.w + xr.w) * t.w;
#pragma unroll
        for (int o = 16; o; o >>= 1) {
            eA += __shfl_xor_sync(0xFFFFFFFFu, eA, o);
            eB += __shfl_xor_sync(0xFFFFFFFFu, eB, o);
        }
        {
            float nm = fmaxf(m0, eA);
            float fo = __expf(m0 - nm), fe = __expf(eA - nm);
            s0 = s0 * fo + fe;
            a0.x = a0.x * fo + fe * xA.x;
            a0.y = a0.y * fo + fe * xA.y;
            a0.z = a0.z * fo + fe * xA.z;
            a0.w = a0.w * fo + fe * xA.w;
            m0 = nm;
        }
        {
            float nm = fmaxf(m1, eB);
            float fo = __expf(m1 - nm), fe = __expf(eB - nm);
            s1 = s1 * fo + fe;
            a1.x = a1.x * fo + fe * xB.x;
            a1.y = a1.y * fo + fe * xB.y;
            a1.z = a1.z * fo + fe * xB.z;
            a1.w = a1.w * fo + fe * xB.w;
            m1 = nm;
        }
    }
    if (k < end) {
        int sa = csrc[k];
        float4 xA = X[(size_t)sa * 64 + lane];
        float eA = lrelu(xA.x + xr.x) * t.x + lrelu(xA.y + xr.y) * t.y +
                   lrelu(xA.z + xr.z) * t.z + lrelu(xA.w + xr.w) * t.w;
#pragma unroll
        for (int o = 16; o; o >>= 1) eA += __shfl_xor_sync(0xFFFFFFFFu, eA, o);
        float nm = fmaxf(m0, eA);
        float fo = __expf(m0 - nm), fe = __expf(eA - nm);
        s0 = s0 * fo + fe;
        a0.x = a0.x * fo + fe * xA.x;
        a0.y = a0.y * fo + fe * xA.y;
        a0.z = a0.z * fo + fe * xA.z;
        a0.w = a0.w * fo + fe * xA.w;
        m0 = nm;
    }
    // merge the two accumulators
    float m = fmaxf(m0, m1);
    float f0 = __expf(m0 - m), f1 = __expf(m1 - m);
    float s = s0 * f0 + s1 * f1;
    float inv = 1.f / (s + 1e-16f);
    float4 b4 = ((const float4*)bias)[lane];
    float4 r;
    r.x = fmaxf((a0.x * f0 + a1.x * f1) * inv + b4.x, 0.f) * scale;
    r.y = fmaxf((a0.y * f0 + a1.y * f1) * inv + b4.y, 0.f) * scale;
    r.z = fmaxf((a0.z * f0 + a1.z * f1) * inv + b4.z, 0.f) * scale;
    r.w = fmaxf((a0.w * f0 + a1.w * f1) * inv + b4.w, 0.f) * scale;
    ((float4*)out)[(size_t)node * 32 + lane] = r;
}

// ---------------- pooling ----------------
__global__ void init_pool_kernel(float* __restrict__ pool, float* __restrict__ cnt) {
    int i = blockIdx.x * blockDim.x + threadIdx.x;
    if (i < NG * NH) pool[i] = 0.f;
    if (i < NG) cnt[i] = 0.f;
}

__global__ void pool_kernel(const float* __restrict__ h, const int* __restrict__ batch,
                            float* __restrict__ pool, float* __restrict__ cnt) {
    int w = (blockIdx.x * blockDim.x + threadIdx.x) >> 5;
    if (w >= NN) return;
    int lane = threadIdx.x & 31;
    int g = batch[w];
    float4 v = ((const float4*)h)[(size_t)w * 32 + lane];
    atomicAdd((float4*)(pool + (size_t)g * NH + lane * 4), v);
    if (lane == 0) atomicAdd(&cnt[g], 1.f);
}

// ---------------- final MLP + layernorm: one block per graph ----------------
__global__ void mlp_kernel(const float* __restrict__ pool, const float* __restrict__ cnt,
                           const float* __restrict__ w1, const float* __restrict__ b1,
                           const float* __restrict__ w2, const float* __restrict__ b2,
                           const float* __restrict__ lng, const float* __restrict__ lnb,
                           float* __restrict__ out) {
    int g = blockIdx.x;
    int t = threadIdx.x;  // 256 threads
    __shared__ float p[NH];
    __shared__ float z1[2 * NH];
    __shared__ float rs[8], rq[8];
    float inv = 1.f / fmaxf(cnt[g], 1.f);
    if (t < NH) p[t] = pool[g * NH + t] * inv;
    __syncthreads();
    float a = 0.f;
#pragma unroll 8
    for (int k = 0; k < NH; k++) a += p[k] * w1[k * (2 * NH) + t];
    z1[t] = fmaxf(a + b1[t], 0.f);
    __syncthreads();
    float z = 0.f;
#pragma unroll 8
    for (int k = 0; k < 2 * NH; k++) z += z1[k] * w2[k * NO + t];
    z += b2[t];
    float v = z, v2 = z * z;
#pragma unroll
    for (int o = 16; o; o >>= 1) {
        v += __shfl_xor_sync(0xFFFFFFFFu, v, o);
        v2 += __shfl_xor_sync(0xFFFFFFFFu, v2, o);
    }
    int wid = t >> 5, lane = t & 31;
    if (lane == 0) { rs[wid] = v; rq[wid] = v2; }
    __syncthreads();
    if (wid == 0) {
        float sv = lane < 8 ? rs[lane] : 0.f;
        float sq = lane < 8 ? rq[lane] : 0.f;
#pragma unroll
        for (int o = 4; o; o >>= 1) {
            sv += __shfl_xor_sync(0xFFFFFFFFu, sv, o);
            sq += __shfl_xor_sync(0xFFFFFFFFu, sq, o);
        }
        if (lane == 0) { rs[0] = sv; rq[0] = sq; }
    }
    __syncthreads();
    float mu = rs[0] * (1.f / NO);
    float var = rq[0] * (1.f / NO) - mu * mu;
    out[g * NO + t] = (z - mu) * rsqrtf(var + 1e-5f) * lng[t] + lnb[t];
}

// ---------------- host ----------------
extern "C" void kernel_launch(void* const* d_in, const int* in_sizes, int n_in,
                              void* d_out, int out_size) {
    const float* x = (const float*)d_in[0];
    const int* ei = (const int*)d_in[1];
    const int* src = ei;
    const int* dst = ei + NE;
    const int* batch = (const int*)d_in[2];
    const float* Wl[4] = {(const float*)d_in[3], (const float*)d_in[7],
                          (const float*)d_in[11], (const float*)d_in[15]};
    const float* Wr[4] = {(const float*)d_in[4], (const float*)d_in[8],
                          (const float*)d_in[12], (const float*)d_in[16]};
    const float* att[4] = {(const float*)d_in[5], (const float*)d_in[9],
                           (const float*)d_in[13], (const float*)d_in[17]};
    const float* bb[4] = {(const float*)d_in[6], (const float*)d_in[10],
                          (const float*)d_in[14], (const float*)d_in[18]};
    const float* res_w0 = (const float*)d_in[19];
    const float* res_b0 = (const float*)d_in[20];
    const float* res_w2 = (const float*)d_in[21];
    const float* res_b2 = (const float*)d_in[22];
    const float* mh1_w = (const float*)d_in[23];
    const float* mh1_b = (const float*)d_in[24];
    const float* mh2_w = (const float*)d_in[25];
    const float* mh2_b = (const float*)d_in[26];
    const float* ln_g = (const float*)d_in[27];
    const float* ln_b = (const float*)d_in[28];
    float* out = (float*)d_out;

    float *xlr, *h0, *h1, *wpack, *pool, *cnt;
    int *rowoff, *cursor, *csrc;
    cudaGetSymbolAddress((void**)&xlr, g_xlr);
    cudaGetSymbolAddress((void**)&h0, g_h0);
    cudaGetSymbolAddress((void**)&h1, g_h1);
    cudaGetSymbolAddress((void**)&wpack, g_wpack);
    cudaGetSymbolAddress((void**)&rowoff, g_rowoff);
    cudaGetSymbolAddress((void**)&cursor, g_cursor);
    cudaGetSymbolAddress((void**)&csrc, g_csrc);
    cudaGetSymbolAddress((void**)&pool, g_pool);
    cudaGetSymbolAddress((void**)&cnt, g_cnt);

    // ---- CSR build (once, reused for all 4 layers) ----
    zero_cnt_kernel<<<(NN + 255) / 256, 256>>>(cursor);
    hist_kernel<<<(NE + 255) / 256, 256>>>(dst, cursor);
    scan_kernel<<<1, 1024>>>(cursor, rowoff, cursor);
    fill_kernel<<<(NE + 255) / 256, 256>>>(src, dst, cursor, csrc);

    // ---- pack fused weights ----
    const int Kdims[4] = {NIN, NH, NH, NH};
    for (int li = 0; li < 4; li++) {
        pack_w_kernel<<<(Kdims[li] * 256 + 255) / 256, 256>>>(
            Wl[li], Wr[li], wpack + (size_t)li * 128 * 256, Kdims[li]);
    }

    dim3 ggf(NN / 64, 4);      // fused GEMM: N=256
    dim3 ggr(NN / 64, 2);      // residual GEMM: N=128
    const int AGG_BLK = (NN + 7) / 8;

    auto gat = [&](const float* hin, int li, const float* biasv, float* hout, float scale) {
        gemm64<false, false><<<ggf, 256>>>(hin, wpack + (size_t)li * 128 * 256, nullptr,
                                           nullptr, xlr, NN, 256, Kdims[li]);
        gat_agg_kernel<<<AGG_BLK, 256>>>(xlr, rowoff, csrc, att[li], biasv, hout, scale);
    };

    // layer 1: relu -> h0; h1 = h0@res_w0 + res_b0 + h0
    gat(x, 0, bb[0], h0, 1.f);
    gemm64<true, true><<<ggr, 256>>>(h0, res_w0, res_b0, h0, h1, NN, NH, NH);
    // layer 2: h0 = 2*relu(gat(h1))
    gat(h1, 1, bb[1], h0, 2.f);
    // layer 3: relu -> h1; h0 = h1@res_w2 + res_b2 + h1
    gat(h0, 2, bb[2], h1, 1.f);
    gemm64<true, true><<<ggr, 256>>>(h1, res_w2, res_b2, h1, h0, NN, NH, NH);
    // layer 4: h1 = 2*relu(gat(h0))
    gat(h0, 3, bb[3], h1, 2.f);

    // pooling + MLP + layernorm
    init_pool_kernel<<<(NG * NH + 255) / 256, 256>>>(pool, cnt);
    pool_kernel<<<(NN * 32 + 255) / 256, 256>>>(h1, batch, pool, cnt);
    mlp_kernel<<<NG, 256>>>(pool, cnt, mh1_w, mh1_b, mh2_w, mh2_b, ln_g, ln_b, out);
}

// round 5
// speedup vs baseline: 2.1445x; 1.2451x over previous
#include <cuda_runtime.h>
#include <cuda_bf16.h>
#include <math.h>
#include <stdint.h>

#define NN 40000
#define NP 40064          // padded rows (313 * 128)
#define NE 640000
#define NG 128
#define NIN 64
#define NH 128
#define NO 256

// ---------------- scratch (device globals; no allocation allowed) ----------------
__device__ float g_xlr[NP * 256];
__device__ float g_h0[NP * NH];
__device__ float g_h1[NP * NH];
__device__ __align__(16) __nv_bfloat16 g_h0hi[NP * NH];
__device__ __align__(16) __nv_bfloat16 g_h0lo[NP * NH];
__device__ __align__(16) __nv_bfloat16 g_h1hi[NP * NH];
__device__ __align__(16) __nv_bfloat16 g_h1lo[NP * NH];
__device__ __align__(16) __nv_bfloat16 g_xhi[NP * NIN];
__device__ __align__(16) __nv_bfloat16 g_xlo[NP * NIN];
__device__ __align__(16) __nv_bfloat16 g_bfh[4][256 * 128];  // fused [Wl|Wr]^T hi ([N,K])
__device__ __align__(16) __nv_bfloat16 g_bfl[4][256 * 128];  // fused lo
__device__ __align__(16) __nv_bfloat16 g_brh[2][128 * 128];  // res W^T hi
__device__ __align__(16) __nv_bfloat16 g_brl[2][128 * 128];  // res lo
__device__ int   g_rowoff[NN + 1];
__device__ int   g_cursor[NN];
__device__ int   g_csrc[NE];
__device__ float g_pool[NG * NH];
__device__ float g_cnt[NG];

__device__ __forceinline__ float lrelu(float v) { return v > 0.f ? v : 0.2f * v; }

__device__ __forceinline__ uint32_t smem_u32(const void* p) {
    uint32_t a;
    asm("{ .reg .u64 t; cvta.to.shared.u64 t, %1; cvt.u32.u64 %0, t; }" : "=r"(a) : "l"(p));
    return a;
}
__device__ __forceinline__ void ldsm4(uint32_t* r, uint32_t addr) {
    asm volatile("ldmatrix.sync.aligned.m8n8.x4.shared.b16 {%0,%1,%2,%3}, [%4];"
                 : "=r"(r[0]), "=r"(r[1]), "=r"(r[2]), "=r"(r[3]) : "r"(addr));
}
__device__ __forceinline__ void mma_bf16(float* d, const uint32_t* a, uint32_t b0, uint32_t b1) {
    asm volatile(
        "mma.sync.aligned.m16n8k16.row.col.f32.bf16.bf16.f32 "
        "{%0,%1,%2,%3}, {%4,%5,%6,%7}, {%8,%9}, {%0,%1,%2,%3};"
        : "+f"(d[0]), "+f"(d[1]), "+f"(d[2]), "+f"(d[3])
        : "r"(a[0]), "r"(a[1]), "r"(a[2]), "r"(a[3]), "r"(b0), "r"(b1));
}

// ---------------- CSR build ----------------
__global__ void zero_cnt_kernel(int* __restrict__ cnt) {
    int i = blockIdx.x * blockDim.x + threadIdx.x;
    if (i < NN) cnt[i] = 0;
}
__global__ void hist_kernel(const int* __restrict__ dst, int* __restrict__ cnt) {
    int i = blockIdx.x * blockDim.x + threadIdx.x;
    if (i < NE) atomicAdd(&cnt[dst[i]], 1);
}
__global__ void scan_kernel(const int* __restrict__ cnt, int* __restrict__ rowoff,
                            int* __restrict__ cursor) {
    __shared__ int s_carry;
    __shared__ int warpsums[32];
    int lane = threadIdx.x & 31, wid = threadIdx.x >> 5;
    if (threadIdx.x == 0) s_carry = 0;
    __syncthreads();
    for (int base = 0; base < NN; base += 1024) {
        int i = base + (int)threadIdx.x;
        int v = (i < NN) ? cnt[i] : 0;
        int x = v;
#pragma unroll
        for (int o = 1; o < 32; o <<= 1) {
            int y = __shfl_up_sync(0xFFFFFFFFu, x, o);
            if (lane >= o) x += y;
        }
        if (lane == 31) warpsums[wid] = x;
        __syncthreads();
        if (wid == 0) {
            int w = warpsums[lane];
#pragma unroll
            for (int o = 1; o < 32; o <<= 1) {
                int y = __shfl_up_sync(0xFFFFFFFFu, w, o);
                if (lane >= o) w += y;
            }
            warpsums[lane] = w;
        }
        __syncthreads();
        int incl = x + (wid > 0 ? warpsums[wid - 1] : 0) + s_carry;
        int excl = incl - v;
        if (i < NN) { rowoff[i] = excl; cursor[i] = excl; }
        __syncthreads();
        if (threadIdx.x == 1023) s_carry = incl;
        __syncthreads();
    }
    if (threadIdx.x == 0) rowoff[NN] = NE;
}
__global__ void fill_kernel(const int* __restrict__ src, const int* __restrict__ dst,
                            int* __restrict__ cursor, int* __restrict__ csrc) {
    int i = blockIdx.x * blockDim.x + threadIdx.x;
    if (i >= NE) return;
    int pos = atomicAdd(&cursor[dst[i]], 1);
    csrc[pos] = src[i];
}

// ---------------- weight pack+split (transposed to [N,K]) ----------------
__global__ void pack_fused_kernel(const float* __restrict__ Wl, const float* __restrict__ Wr,
                                  __nv_bfloat16* __restrict__ bh, __nv_bfloat16* __restrict__ bl,
                                  int K) {
    int i = blockIdx.x * blockDim.x + threadIdx.x;
    if (i >= 256 * K) return;
    int n = i / K, k = i % K;
    float v = (n < 128) ? Wl[k * 128 + n] : Wr[k * 128 + (n - 128)];
    __nv_bfloat16 h = __float2bfloat16(v);
    bh[i] = h;
    bl[i] = __float2bfloat16(v - __bfloat162float(h));
}
__global__ void pack_res_kernel(const float* __restrict__ W, __nv_bfloat16* __restrict__ bh,
                                __nv_bfloat16* __restrict__ bl) {
    int i = blockIdx.x * blockDim.x + threadIdx.x;
    if (i >= 128 * 128) return;
    int n = i >> 7, k = i & 127;
    float v = W[k * 128 + n];
    __nv_bfloat16 h = __float2bfloat16(v);
    bh[i] = h;
    bl[i] = __float2bfloat16(v - __bfloat162float(h));
}
__global__ void split_x_kernel(const float* __restrict__ x, __nv_bfloat16* __restrict__ hi,
                               __nv_bfloat16* __restrict__ lo) {
    int i = blockIdx.x * blockDim.x + threadIdx.x;
    if (i >= NN * NIN) return;
    float f = x[i];
    __nv_bfloat16 h = __float2bfloat16(f);
    hi[i] = h;
    lo[i] = __float2bfloat16(f - __bfloat162float(h));
}

// ---------------- tensor-core GEMM via mma.sync (bf16 3-term split) ----------------
// out[NP, NT] (+bias) (+add) = A[NP, K] @ B[NT, K]^T
// block tile 128x128, 8 warps (4 m x 2 n), each warp 32x64; K-chunks of 64.
template <int K, int NT, bool BIAS, bool ADDIN, bool WSPLIT>
__global__ void __launch_bounds__(256, 1) mm_gemm(
    const __nv_bfloat16* __restrict__ Ah, const __nv_bfloat16* __restrict__ Al,
    const __nv_bfloat16* __restrict__ Bh, const __nv_bfloat16* __restrict__ Bl,
    const float* __restrict__ bias, const float* __restrict__ add, float* __restrict__ out,
    __nv_bfloat16* __restrict__ ohi, __nv_bfloat16* __restrict__ olo) {
    extern __shared__ char smem[];
    constexpr int KC = 64, ST = 72;           // padded stride (bf16 elems)
    constexpr int TB = 128 * ST;              // tile elems
    __nv_bfloat16* sAh = (__nv_bfloat16*)smem;
    __nv_bfloat16* sAl = sAh + TB;
    __nv_bfloat16* sBh = sAl + TB;
    __nv_bfloat16* sBl = sBh + TB;
    int tid = threadIdx.x, lane = tid & 31, wid = tid >> 5;
    int warp_m = wid & 3, warp_n = wid >> 2;
    int bm = blockIdx.x * 128, bn = blockIdx.y * 128;
    const __nv_bfloat16* Bh_blk = Bh + (size_t)bn * K;
    const __nv_bfloat16* Bl_blk = Bl + (size_t)bn * K;

    float acc[2][8][4];
#pragma unroll
    for (int i = 0; i < 2; i++)
#pragma unroll
        for (int j = 0; j < 8; j++)
#pragma unroll
            for (int q = 0; q < 4; q++) acc[i][j][q] = 0.f;

    // ldmatrix lane addressing (shared by A and B fragments)
    int g = lane >> 3, lr = lane & 7;
    int frow = lr + ((g & 1) << 3);      // row within 16-row tile
    int fcol = (g >> 1) << 3;            // col offset within 16-col k-step

    for (int kc = 0; kc < K; kc += KC) {
        if (kc) __syncthreads();
#pragma unroll
        for (int idx = tid; idx < 1024; idx += 256) {
            int r = idx >> 3, c = (idx & 7) * 8;
            *(uint4*)&sAh[r * ST + c] = *(const uint4*)&Ah[(size_t)(bm + r) * K + kc + c];
            *(uint4*)&sAl[r * ST + c] = *(const uint4*)&Al[(size_t)(bm + r) * K + kc + c];
            *(uint4*)&sBh[r * ST + c] = *(const uint4*)&Bh_blk[(size_t)r * K + kc + c];
            *(uint4*)&sBl[r * ST + c] = *(const uint4*)&Bl_blk[(size_t)r * K + kc + c];
        }
        __syncthreads();
#pragma unroll
        for (int ks = 0; ks < 4; ks++) {
            int kcol = ks * 16 + fcol;
            uint32_t ah0[4], ah1[4], al0[4], al1[4];
            ldsm4(ah0, smem_u32(&sAh[(warp_m * 32 + frow) * ST + kcol]));
            ldsm4(ah1, smem_u32(&sAh[(warp_m * 32 + 16 + frow) * ST + kcol]));
            ldsm4(al0, smem_u32(&sAl[(warp_m * 32 + frow) * ST + kcol]));
            ldsm4(al1, smem_u32(&sAl[(warp_m * 32 + 16 + frow) * ST + kcol]));
#pragma unroll
            for (int tp = 0; tp < 4; tp++) {
                int brow = warp_n * 64 + tp * 16 + frow;
                uint32_t bh[4], bl[4];
                ldsm4(bh, smem_u32(&sBh[brow * ST + kcol]));
                ldsm4(bl, smem_u32(&sBl[brow * ST + kcol]));
                // n-tile pair: frag(tn even)={r0,r2}, frag(tn odd)={r1,r3}
                mma_bf16(acc[0][tp * 2 + 0], ah0, bh[0], bh[2]);
                mma_bf16(acc[0][tp * 2 + 1], ah0, bh[1], bh[3]);
                mma_bf16(acc[1][tp * 2 + 0], ah1, bh[0], bh[2]);
                mma_bf16(acc[1][tp * 2 + 1], ah1, bh[1], bh[3]);
                mma_bf16(acc[0][tp * 2 + 0], ah0, bl[0], bl[2]);
                mma_bf16(acc[0][tp * 2 + 1], ah0, bl[1], bl[3]);
                mma_bf16(acc[1][tp * 2 + 0], ah1, bl[0], bl[2]);
                mma_bf16(acc[1][tp * 2 + 1], ah1, bl[1], bl[3]);
                mma_bf16(acc[0][tp * 2 + 0], al0, bh[0], bh[2]);
                mma_bf16(acc[0][tp * 2 + 1], al0, bh[1], bh[3]);
                mma_bf16(acc[1][tp * 2 + 0], al1, bh[0], bh[2]);
                mma_bf16(acc[1][tp * 2 + 1], al1, bh[1], bh[3]);
            }
        }
    }

    // epilogue: d0,d1 -> (row, col..col+1); d2,d3 -> (row+8, ...)
    int lr4 = lane >> 2, lc = (lane & 3) * 2;
#pragma unroll
    for (int tm = 0; tm < 2; tm++) {
#pragma unroll
        for (int half = 0; half < 2; half++) {
            int row = bm + warp_m * 32 + tm * 16 + lr4 + half * 8;
            bool valid = row < NN;
#pragma unroll
            for (int tn = 0; tn < 8; tn++) {
                int gc = bn + warp_n * 64 + tn * 8 + lc;
                float v0 = acc[tm][tn][half * 2 + 0];
                float v1 = acc[tm][tn][half * 2 + 1];
                if (BIAS) { v0 += bias[gc]; v1 += bias[gc + 1]; }
                if (ADDIN) {
                    float2 a2 = *(const float2*)&add[(size_t)row * NT + gc];
                    v0 += a2.x; v1 += a2.y;
                }
                *(float2*)&out[(size_t)row * NT + gc] = make_float2(v0, v1);
                if (WSPLIT && valid) {
                    __nv_bfloat162 hv = __floats2bfloat162_rn(v0, v1);
                    float l0 = v0 - __bfloat162float(hv.x);
                    float l1 = v1 - __bfloat162float(hv.y);
                    __nv_bfloat162 lv = __floats2bfloat162_rn(l0, l1);
                    *(uint32_t*)&ohi[(size_t)row * NT + gc] = *(uint32_t*)&hv;
                    *(uint32_t*)&olo[(size_t)row * NT + gc] = *(uint32_t*)&lv;
                }
            }
        }
    }
}

// ---------------- fused GAT aggregation: warp per node, online softmax ----------------
__global__ void gat_agg_kernel(const float* __restrict__ xlr, const int* __restrict__ rowoff,
                               const int* __restrict__ csrc, const float* __restrict__ att,
                               const float* __restrict__ bias, float* __restrict__ out,
                               __nv_bfloat16* __restrict__ ohi, __nv_bfloat16* __restrict__ olo,
                               float scale) {
    int node = blockIdx.x * 8 + (threadIdx.x >> 5);
    if (node >= NN) return;
    int lane = threadIdx.x & 31;
    const float4* X = (const float4*)xlr;
    float4 xr = X[(size_t)node * 64 + 32 + lane];
    float4 t = ((const float4*)att)[lane];
    int k = rowoff[node];
    int end = rowoff[node + 1];
    float m0 = -3.0e38f, s0 = 0.f, m1 = -3.0e38f, s1 = 0.f;
    float4 a0 = {0.f, 0.f, 0.f, 0.f}, a1 = {0.f, 0.f, 0.f, 0.f};
    for (; k + 2 <= end; k += 2) {
        int sa = csrc[k], sb = csrc[k + 1];
        float4 xA = X[(size_t)sa * 64 + lane];
        float4 xB = X[(size_t)sb * 64 + lane];
        float eA = lrelu(xA.x + xr.x) * t.x + lrelu(xA.y + xr.y) * t.y +
                   lrelu(xA.z + xr.z) * t.z + lrelu(xA.w + xr.w) * t.w;
        float eB = lrelu(xB.x + xr.x) * t.x + lrelu(xB.y + xr.y) * t.y +
                   lrelu(xB.z + xr.z) * t.z + lrelu(xB.w + xr.w) * t.w;
#pragma unroll
        for (int o = 16; o; o >>= 1) {
            eA += __shfl_xor_sync(0xFFFFFFFFu, eA, o);
            eB += __shfl_xor_sync(0xFFFFFFFFu, eB, o);
        }
        {
            float nm = fmaxf(m0, eA);
            float fo = __expf(m0 - nm), fe = __expf(eA - nm);
            s0 = s0 * fo + fe;
            a0.x = a0.x * fo + fe * xA.x;
            a0.y = a0.y * fo + fe * xA.y;
            a0.z = a0.z * fo + fe * xA.z;
            a0.w = a0.w * fo + fe * xA.w;
            m0 = nm;
        }
        {
            float nm = fmaxf(m1, eB);
            float fo = __expf(m1 - nm), fe = __expf(eB - nm);
            s1 = s1 * fo + fe;
            a1.x = a1.x * fo + fe * xB.x;
            a1.y = a1.y * fo + fe * xB.y;
            a1.z = a1.z * fo + fe * xB.z;
            a1.w = a1.w * fo + fe * xB.w;
            m1 = nm;
        }
    }
    if (k < end) {
        int sa = csrc[k];
        float4 xA = X[(size_t)sa * 64 + lane];
        float eA = lrelu(xA.x + xr.x) * t.x + lrelu(xA.y + xr.y) * t.y +
                   lrelu(xA.z + xr.z) * t.z + lrelu(xA.w + xr.w) * t.w;
#pragma unroll
        for (int o = 16; o; o >>= 1) eA += __shfl_xor_sync(0xFFFFFFFFu, eA, o);
        float nm = fmaxf(m0, eA);
        float fo = __expf(m0 - nm), fe = __expf(eA - nm);
        s0 = s0 * fo + fe;
        a0.x = a0.x * fo + fe * xA.x;
        a0.y = a0.y * fo + fe * xA.y;
        a0.z = a0.z * fo + fe * xA.z;
        a0.w = a0.w * fo + fe * xA.w;
        m0 = nm;
    }
    float m = fmaxf(m0, m1);
    float f0 = __expf(m0 - m), f1 = __expf(m1 - m);
    float s = s0 * f0 + s1 * f1;
    float inv = 1.f / (s + 1e-16f);
    float4 b4 = ((const float4*)bias)[lane];
    float4 r;
    r.x = fmaxf((a0.x * f0 + a1.x * f1) * inv + b4.x, 0.f) * scale;
    r.y = fmaxf((a0.y * f0 + a1.y * f1) * inv + b4.y, 0.f) * scale;
    r.z = fmaxf((a0.z * f0 + a1.z * f1) * inv + b4.z, 0.f) * scale;
    r.w = fmaxf((a0.w * f0 + a1.w * f1) * inv + b4.w, 0.f) * scale;
    ((float4*)out)[(size_t)node * 32 + lane] = r;
    __nv_bfloat162 h01 = __floats2bfloat162_rn(r.x, r.y);
    __nv_bfloat162 h23 = __floats2bfloat162_rn(r.z, r.w);
    float lx = r.x - __bfloat162float(h01.x);
    float ly = r.y - __bfloat162float(h01.y);
    float lz = r.z - __bfloat162float(h23.x);
    float lw = r.w - __bfloat162float(h23.y);
    __nv_bfloat162 l01 = __floats2bfloat162_rn(lx, ly);
    __nv_bfloat162 l23 = __floats2bfloat162_rn(lz, lw);
    uint2 uh, ul;
    uh.x = *(uint32_t*)&h01; uh.y = *(uint32_t*)&h23;
    ul.x = *(uint32_t*)&l01; ul.y = *(uint32_t*)&l23;
    ((uint2*)ohi)[(size_t)node * 32 + lane] = uh;
    ((uint2*)olo)[(size_t)node * 32 + lane] = ul;
}

// ---------------- pooling ----------------
__global__ void init_pool_kernel(float* __restrict__ pool, float* __restrict__ cnt) {
    int i = blockIdx.x * blockDim.x + threadIdx.x;
    if (i < NG * NH) pool[i] = 0.f;
    if (i < NG) cnt[i] = 0.f;
}
__global__ void pool_kernel(const float* __restrict__ h, const int* __restrict__ batch,
                            float* __restrict__ pool, float* __restrict__ cnt) {
    int w = (blockIdx.x * blockDim.x + threadIdx.x) >> 5;
    if (w >= NN) return;
    int lane = threadIdx.x & 31;
    int g = batch[w];
    float4 v = ((const float4*)h)[(size_t)w * 32 + lane];
    atomicAdd((float4*)(pool + (size_t)g * NH + lane * 4), v);
    if (lane == 0) atomicAdd(&cnt[g], 1.f);
}

// ---------------- final MLP + layernorm ----------------
__global__ void mlp_kernel(const float* __restrict__ pool, const float* __restrict__ cnt,
                           const float* __restrict__ w1, const float* __restrict__ b1,
                           const float* __restrict__ w2, const float* __restrict__ b2,
                           const float* __restrict__ lng, const float* __restrict__ lnb,
                           float* __restrict__ out) {
    int g = blockIdx.x;
    int t = threadIdx.x;
    __shared__ float p[NH];
    __shared__ float z1[2 * NH];
    __shared__ float rs[8], rq[8];
    float inv = 1.f / fmaxf(cnt[g], 1.f);
    if (t < NH) p[t] = pool[g * NH + t] * inv;
    __syncthreads();
    float a = 0.f;
#pragma unroll 8
    for (int k = 0; k < NH; k++) a += p[k] * w1[k * (2 * NH) + t];
    z1[t] = fmaxf(a + b1[t], 0.f);
    __syncthreads();
    float z = 0.f;
#pragma unroll 8
    for (int k = 0; k < 2 * NH; k++) z += z1[k] * w2[k * NO + t];
    z += b2[t];
    float v = z, v2 = z * z;
#pragma unroll
    for (int o = 16; o; o >>= 1) {
        v += __shfl_xor_sync(0xFFFFFFFFu, v, o);
        v2 += __shfl_xor_sync(0xFFFFFFFFu, v2, o);
    }
    int wid = t >> 5, lane = t & 31;
    if (lane == 0) { rs[wid] = v; rq[wid] = v2; }
    __syncthreads();
    if (wid == 0) {
        float sv = lane < 8 ? rs[lane] : 0.f;
        float sq = lane < 8 ? rq[lane] : 0.f;
#pragma unroll
        for (int o = 4; o; o >>= 1) {
            sv += __shfl_xor_sync(0xFFFFFFFFu, sv, o);
            sq += __shfl_xor_sync(0xFFFFFFFFu, sq, o);
        }
        if (lane == 0) { rs[0] = sv; rq[0] = sq; }
    }
    __syncthreads();
    float mu = rs[0] * (1.f / NO);
    float var = rq[0] * (1.f / NO) - mu * mu;
    out[g * NO + t] = (z - mu) * rsqrtf(var + 1e-5f) * lng[t] + lnb[t];
}

// ---------------- host ----------------
extern "C" void kernel_launch(void* const* d_in, const int* in_sizes, int n_in,
                              void* d_out, int out_size) {
    const float* x = (const float*)d_in[0];
    const int* ei = (const int*)d_in[1];
    const int* src = ei;
    const int* dst = ei + NE;
    const int* batch = (const int*)d_in[2];
    const float* Wl[4] = {(const float*)d_in[3], (const float*)d_in[7],
                          (const float*)d_in[11], (const float*)d_in[15]};
    const float* Wr[4] = {(const float*)d_in[4], (const float*)d_in[8],
                          (const float*)d_in[12], (const float*)d_in[16]};
    const float* att[4] = {(const float*)d_in[5], (const float*)d_in[9],
                           (const float*)d_in[13], (const float*)d_in[17]};
    const float* bb[4] = {(const float*)d_in[6], (const float*)d_in[10],
                          (const float*)d_in[14], (const float*)d_in[18]};
    const float* res_w0 = (const float*)d_in[19];
    const float* res_b0 = (const float*)d_in[20];
    const float* res_w2 = (const float*)d_in[21];
    const float* res_b2 = (const float*)d_in[22];
    const float* mh1_w = (const float*)d_in[23];
    const float* mh1_b = (const float*)d_in[24];
    const float* mh2_w = (const float*)d_in[25];
    const float* mh2_b = (const float*)d_in[26];
    const float* ln_g = (const float*)d_in[27];
    const float* ln_b = (const float*)d_in[28];
    float* out = (float*)d_out;

    float *xlr, *h0, *h1, *pool, *cnt;
    __nv_bfloat16 *h0hi, *h0lo, *h1hi, *h1lo, *xhi, *xlo, *bfh, *bfl, *brh, *brl;
    int *rowoff, *cursor, *csrc;
    cudaGetSymbolAddress((void**)&xlr, g_xlr);
    cudaGetSymbolAddress((void**)&h0, g_h0);
    cudaGetSymbolAddress((void**)&h1, g_h1);
    cudaGetSymbolAddress((void**)&h0hi, g_h0hi);
    cudaGetSymbolAddress((void**)&h0lo, g_h0lo);
    cudaGetSymbolAddress((void**)&h1hi, g_h1hi);
    cudaGetSymbolAddress((void**)&h1lo, g_h1lo);
    cudaGetSymbolAddress((void**)&xhi, g_xhi);
    cudaGetSymbolAddress((void**)&xlo, g_xlo);
    cudaGetSymbolAddress((void**)&bfh, g_bfh);
    cudaGetSymbolAddress((void**)&bfl, g_bfl);
    cudaGetSymbolAddress((void**)&brh, g_brh);
    cudaGetSymbolAddress((void**)&brl, g_brl);
    cudaGetSymbolAddress((void**)&rowoff, g_rowoff);
    cudaGetSymbolAddress((void**)&cursor, g_cursor);
    cudaGetSymbolAddress((void**)&csrc, g_csrc);
    cudaGetSymbolAddress((void**)&pool, g_pool);
    cudaGetSymbolAddress((void**)&cnt, g_cnt);

    // ---- CSR build ----
    zero_cnt_kernel<<<(NN + 255) / 256, 256>>>(cursor);
    hist_kernel<<<(NE + 255) / 256, 256>>>(dst, cursor);
    scan_kernel<<<1, 1024>>>(cursor, rowoff, cursor);
    fill_kernel<<<(NE + 255) / 256, 256>>>(src, dst, cursor, csrc);

    // ---- weight pack + split ----
    const int Kd[4] = {NIN, NH, NH, NH};
    for (int li = 0; li < 4; li++) {
        pack_fused_kernel<<<(256 * Kd[li] + 255) / 256, 256>>>(
            Wl[li], Wr[li], bfh + (size_t)li * 256 * 128, bfl + (size_t)li * 256 * 128, Kd[li]);
    }
    pack_res_kernel<<<(128 * 128 + 255) / 256, 256>>>(res_w0, brh, brl);
    pack_res_kernel<<<(128 * 128 + 255) / 256, 256>>>(res_w2, brh + 128 * 128, brl + 128 * 128);
    split_x_kernel<<<(NN * NIN + 255) / 256, 256>>>(x, xhi, xlo);

    // ---- smem ----
    const int SMEM_MM = 4 * 128 * 72 * 2;  // 73728
    cudaFuncSetAttribute(mm_gemm<64, 256, false, false, false>,
                         cudaFuncAttributeMaxDynamicSharedMemorySize, SMEM_MM);
    cudaFuncSetAttribute(mm_gemm<128, 256, false, false, false>,
                         cudaFuncAttributeMaxDynamicSharedMemorySize, SMEM_MM);
    cudaFuncSetAttribute(mm_gemm<128, 128, true, true, true>,
                         cudaFuncAttributeMaxDynamicSharedMemorySize, SMEM_MM);

    const int GT = NP / 128;  // 313
    dim3 gf(GT, 2), gr(GT, 1);
    const int AGG_BLK = (NN + 7) / 8;

    // layer 1
    mm_gemm<64, 256, false, false, false><<<gf, 256, SMEM_MM>>>(
        xhi, xlo, bfh, bfl, nullptr, nullptr, xlr, nullptr, nullptr);
    gat_agg_kernel<<<AGG_BLK, 256>>>(xlr, rowoff, csrc, att[0], bb[0], h0, h0hi, h0lo, 1.f);
    mm_gemm<128, 128, true, true, true><<<gr, 256, SMEM_MM>>>(
        h0hi, h0lo, brh, brl, res_b0, h0, h1, h1hi, h1lo);
    // layer 2
    mm_gemm<128, 256, false, false, false><<<gf, 256, SMEM_MM>>>(
        h1hi, h1lo, bfh + 256 * 128, bfl + 256 * 128, nullptr, nullptr, xlr, nullptr, nullptr);
    gat_agg_kernel<<<AGG_BLK, 256>>>(xlr, rowoff, csrc, att[1], bb[1], h0, h0hi, h0lo, 2.f);
    // layer 3
    mm_gemm<128, 256, false, false, false><<<gf, 256, SMEM_MM>>>(
        h0hi, h0lo, bfh + 2 * 256 * 128, bfl + 2 * 256 * 128, nullptr, nullptr, xlr, nullptr,
        nullptr);
    gat_agg_kernel<<<AGG_BLK, 256>>>(xlr, rowoff, csrc, att[2], bb[2], h1, h1hi, h1lo, 1.f);
    mm_gemm<128, 128, true, true, true><<<gr, 256, SMEM_MM>>>(
        h1hi, h1lo, brh + 128 * 128, brl + 128 * 128, res_b2, h1, h0, h0hi, h0lo);
    // layer 4
    mm_gemm<128, 256, false, false, false><<<gf, 256, SMEM_MM>>>(
        h0hi, h0lo, bfh + 3 * 256 * 128, bfl + 3 * 256 * 128, nullptr, nullptr, xlr, nullptr,
        nullptr);
    gat_agg_kernel<<<AGG_BLK, 256>>>(xlr, rowoff, csrc, att[3], bb[3], h1, h0hi, h0lo, 2.f);

    // pooling + MLP + layernorm
    init_pool_kernel<<<(NG * NH + 255) / 256, 256>>>(pool, cnt);
    pool_kernel<<<(NN * 32 + 255) / 256, 256>>>(h1, batch, pool, cnt);
    mlp_kernel<<<NG, 256>>>(pool, cnt, mh1_w, mh1_b, mh2_w, mh2_b, ln_g, ln_b, out);
}

// round 6
// speedup vs baseline: 2.3273x; 1.0852x over previous
#include <cuda_runtime.h>
#include <cuda_bf16.h>
#include <math.h>
#include <stdint.h>

#define NN 40000
#define NP 40064          // padded rows (313 * 128)
#define NE 640000
#define NG 128
#define NIN 64
#define NH 128
#define NO 256

// ---------------- scratch (device globals; no allocation allowed) ----------------
__device__ float g_xlr[NP * 256];
__device__ float g_h0[NP * NH];
__device__ float g_h1[NP * NH];
__device__ __align__(16) __nv_bfloat16 g_h0hi[NP * NH];
__device__ __align__(16) __nv_bfloat16 g_h0lo[NP * NH];
__device__ __align__(16) __nv_bfloat16 g_h1hi[NP * NH];
__device__ __align__(16) __nv_bfloat16 g_h1lo[NP * NH];
__device__ __align__(16) __nv_bfloat16 g_xhi[NP * NIN];
__device__ __align__(16) __nv_bfloat16 g_xlo[NP * NIN];
__device__ __align__(16) __nv_bfloat16 g_bfh[4][256 * 128];  // fused [Wl|Wr]^T hi ([N,K])
__device__ __align__(16) __nv_bfloat16 g_bfl[4][256 * 128];  // fused lo
__device__ __align__(16) __nv_bfloat16 g_brh[2][128 * 128];  // res W^T hi
__device__ __align__(16) __nv_bfloat16 g_brl[2][128 * 128];  // res lo
__device__ int   g_rowoff[NN + 1];
__device__ int   g_cursor[NN];
__device__ int   g_csrc[NE];
__device__ float g_pool[NG * NH];
__device__ float g_cnt[NG];

__device__ __forceinline__ float lrelu(float v) { return v > 0.f ? v : 0.2f * v; }

__device__ __forceinline__ uint32_t smem_u32(const void* p) {
    uint32_t a;
    asm("{ .reg .u64 t; cvta.to.shared.u64 t, %1; cvt.u32.u64 %0, t; }" : "=r"(a) : "l"(p));
    return a;
}
__device__ __forceinline__ void ldsm4(uint32_t* r, uint32_t addr) {
    asm volatile("ldmatrix.sync.aligned.m8n8.x4.shared.b16 {%0,%1,%2,%3}, [%4];"
                 : "=r"(r[0]), "=r"(r[1]), "=r"(r[2]), "=r"(r[3]) : "r"(addr));
}
__device__ __forceinline__ void mma_bf16(float* d, const uint32_t* a, uint32_t b0, uint32_t b1) {
    asm volatile(
        "mma.sync.aligned.m16n8k16.row.col.f32.bf16.bf16.f32 "
        "{%0,%1,%2,%3}, {%4,%5,%6,%7}, {%8,%9}, {%0,%1,%2,%3};"
        : "+f"(d[0]), "+f"(d[1]), "+f"(d[2]), "+f"(d[3])
        : "r"(a[0]), "r"(a[1]), "r"(a[2]), "r"(a[3]), "r"(b0), "r"(b1));
}
__device__ __forceinline__ void cp16(uint32_t dst, const void* src) {
    asm volatile("cp.async.cg.shared.global [%0], [%1], 16;" :: "r"(dst), "l"(src));
}
#define CP_COMMIT_WAIT() \
    asm volatile("cp.async.commit_group;\ncp.async.wait_group 0;" ::: "memory")

// ---------------- CSR build ----------------
__global__ void hist_kernel(const int* __restrict__ dst, int* __restrict__ cnt) {
    int i = blockIdx.x * blockDim.x + threadIdx.x;
    if (i < NE) atomicAdd(&cnt[dst[i]], 1);
}
__global__ void scan_kernel(const int* __restrict__ cnt, int* __restrict__ rowoff,
                            int* __restrict__ cursor) {
    __shared__ int s_carry;
    __shared__ int warpsums[32];
    int lane = threadIdx.x & 31, wid = threadIdx.x >> 5;
    if (threadIdx.x == 0) s_carry = 0;
    __syncthreads();
    for (int base = 0; base < NN; base += 1024) {
        int i = base + (int)threadIdx.x;
        int v = (i < NN) ? cnt[i] : 0;
        int x = v;
#pragma unroll
        for (int o = 1; o < 32; o <<= 1) {
            int y = __shfl_up_sync(0xFFFFFFFFu, x, o);
            if (lane >= o) x += y;
        }
        if (lane == 31) warpsums[wid] = x;
        __syncthreads();
        if (wid == 0) {
            int w = warpsums[lane];
#pragma unroll
            for (int o = 1; o < 32; o <<= 1) {
                int y = __shfl_up_sync(0xFFFFFFFFu, w, o);
                if (lane >= o) w += y;
            }
            warpsums[lane] = w;
        }
        __syncthreads();
        int incl = x + (wid > 0 ? warpsums[wid - 1] : 0) + s_carry;
        int excl = incl - v;
        if (i < NN) { rowoff[i] = excl; cursor[i] = excl; }
        __syncthreads();
        if (threadIdx.x == 1023) s_carry = incl;
        __syncthreads();
    }
    if (threadIdx.x == 0) rowoff[NN] = NE;
}
__global__ void fill_kernel(const int* __restrict__ src, const int* __restrict__ dst,
                            int* __restrict__ cursor, int* __restrict__ csrc) {
    int i = blockIdx.x * blockDim.x + threadIdx.x;
    if (i >= NE) return;
    int pos = atomicAdd(&cursor[dst[i]], 1);
    csrc[pos] = src[i];
}

// ---------------- weight pack+split (transposed to [N,K]) ----------------
__global__ void pack_fused_kernel(const float* __restrict__ Wl, const float* __restrict__ Wr,
                                  __nv_bfloat16* __restrict__ bh, __nv_bfloat16* __restrict__ bl,
                                  int K) {
    int i = blockIdx.x * blockDim.x + threadIdx.x;
    if (i >= 256 * K) return;
    int n = i / K, k = i % K;
    float v = (n < 128) ? Wl[k * 128 + n] : Wr[k * 128 + (n - 128)];
    __nv_bfloat16 h = __float2bfloat16(v);
    bh[i] = h;
    bl[i] = __float2bfloat16(v - __bfloat162float(h));
}
__global__ void pack_res_kernel(const float* __restrict__ W, __nv_bfloat16* __restrict__ bh,
                                __nv_bfloat16* __restrict__ bl) {
    int i = blockIdx.x * blockDim.x + threadIdx.x;
    if (i >= 128 * 128) return;
    int n = i >> 7, k = i & 127;
    float v = W[k * 128 + n];
    __nv_bfloat16 h = __float2bfloat16(v);
    bh[i] = h;
    bl[i] = __float2bfloat16(v - __bfloat162float(h));
}
__global__ void split_x_kernel(const float* __restrict__ x, __nv_bfloat16* __restrict__ hi,
                               __nv_bfloat16* __restrict__ lo) {
    int i = blockIdx.x * blockDim.x + threadIdx.x;
    if (i >= NN * NIN) return;
    float f = x[i];
    __nv_bfloat16 h = __float2bfloat16(f);
    hi[i] = h;
    lo[i] = __float2bfloat16(f - __bfloat162float(h));
}

// ---------------- tensor-core GEMM via mma.sync (bf16 3-term split) ----------------
// out[NP, NT] (+bias) (+add) = A[NP, K] @ B[NT, K]^T
// block tile 128x128, 8 warps (4 m x 2 n), each warp 32x64; K-chunks of 64.
// 2 CTAs/SM for load/compute overlap; cp.async loads.
template <int K, int NT, bool BIAS, bool ADDIN, bool WSPLIT>
__global__ void __launch_bounds__(256, 2) mm_gemm(
    const __nv_bfloat16* __restrict__ Ah, const __nv_bfloat16* __restrict__ Al,
    const __nv_bfloat16* __restrict__ Bh, const __nv_bfloat16* __restrict__ Bl,
    const float* __restrict__ bias, const float* __restrict__ add, float* __restrict__ out,
    __nv_bfloat16* __restrict__ ohi, __nv_bfloat16* __restrict__ olo) {
    extern __shared__ char smem[];
    constexpr int KC = 64, ST = 72;           // padded stride (bf16 elems)
    constexpr int TB = 128 * ST;              // tile elems
    __nv_bfloat16* sAh = (__nv_bfloat16*)smem;
    __nv_bfloat16* sAl = sAh + TB;
    __nv_bfloat16* sBh = sAl + TB;
    __nv_bfloat16* sBl = sBh + TB;
    int tid = threadIdx.x, lane = tid & 31, wid = tid >> 5;
    int warp_m = wid & 3, warp_n = wid >> 2;
    int bm = blockIdx.x * 128, bn = blockIdx.y * 128;
    const __nv_bfloat16* Bh_blk = Bh + (size_t)bn * K;
    const __nv_bfloat16* Bl_blk = Bl + (size_t)bn * K;

    float acc[2][8][4];
#pragma unroll
    for (int i = 0; i < 2; i++)
#pragma unroll
        for (int j = 0; j < 8; j++)
#pragma unroll
            for (int q = 0; q < 4; q++) acc[i][j][q] = 0.f;

    int g = lane >> 3, lr = lane & 7;
    int frow = lr + ((g & 1) << 3);
    int fcol = (g >> 1) << 3;

    for (int kc = 0; kc < K; kc += KC) {
        if (kc) __syncthreads();
#pragma unroll
        for (int idx = tid; idx < 1024; idx += 256) {
            int r = idx >> 3, c = (idx & 7) * 8;
            cp16(smem_u32(&sAh[r * ST + c]), &Ah[(size_t)(bm + r) * K + kc + c]);
            cp16(smem_u32(&sAl[r * ST + c]), &Al[(size_t)(bm + r) * K + kc + c]);
            cp16(smem_u32(&sBh[r * ST + c]), &Bh_blk[(size_t)r * K + kc + c]);
            cp16(smem_u32(&sBl[r * ST + c]), &Bl_blk[(size_t)r * K + kc + c]);
        }
        CP_COMMIT_WAIT();
        __syncthreads();
#pragma unroll
        for (int ks = 0; ks < 4; ks++) {
            int kcol = ks * 16 + fcol;
            uint32_t ah0[4], ah1[4], al0[4], al1[4];
            ldsm4(ah0, smem_u32(&sAh[(warp_m * 32 + frow) * ST + kcol]));
            ldsm4(ah1, smem_u32(&sAh[(warp_m * 32 + 16 + frow) * ST + kcol]));
            ldsm4(al0, smem_u32(&sAl[(warp_m * 32 + frow) * ST + kcol]));
            ldsm4(al1, smem_u32(&sAl[(warp_m * 32 + 16 + frow) * ST + kcol]));
#pragma unroll
            for (int tp = 0; tp < 4; tp++) {
                int brow = warp_n * 64 + tp * 16 + frow;
                uint32_t bh[4], bl[4];
                ldsm4(bh, smem_u32(&sBh[brow * ST + kcol]));
                ldsm4(bl, smem_u32(&sBl[brow * ST + kcol]));
                mma_bf16(acc[0][tp * 2 + 0], ah0, bh[0], bh[2]);
                mma_bf16(acc[0][tp * 2 + 1], ah0, bh[1], bh[3]);
                mma_bf16(acc[1][tp * 2 + 0], ah1, bh[0], bh[2]);
                mma_bf16(acc[1][tp * 2 + 1], ah1, bh[1], bh[3]);
                mma_bf16(acc[0][tp * 2 + 0], ah0, bl[0], bl[2]);
                mma_bf16(acc[0][tp * 2 + 1], ah0, bl[1], bl[3]);
                mma_bf16(acc[1][tp * 2 + 0], ah1, bl[0], bl[2]);
                mma_bf16(acc[1][tp * 2 + 1], ah1, bl[1], bl[3]);
                mma_bf16(acc[0][tp * 2 + 0], al0, bh[0], bh[2]);
                mma_bf16(acc[0][tp * 2 + 1], al0, bh[1], bh[3]);
                mma_bf16(acc[1][tp * 2 + 0], al1, bh[0], bh[2]);
                mma_bf16(acc[1][tp * 2 + 1], al1, bh[1], bh[3]);
            }
        }
    }

    int lr4 = lane >> 2, lc = (lane & 3) * 2;
#pragma unroll
    for (int tm = 0; tm < 2; tm++) {
#pragma unroll
        for (int half = 0; half < 2; half++) {
            int row = bm + warp_m * 32 + tm * 16 + lr4 + half * 8;
            bool valid = row < NN;
#pragma unroll
            for (int tn = 0; tn < 8; tn++) {
                int gc = bn + warp_n * 64 + tn * 8 + lc;
                float v0 = acc[tm][tn][half * 2 + 0];
                float v1 = acc[tm][tn][half * 2 + 1];
                if (BIAS) { v0 += bias[gc]; v1 += bias[gc + 1]; }
                if (ADDIN) {
                    float2 a2 = *(const float2*)&add[(size_t)row * NT + gc];
                    v0 += a2.x; v1 += a2.y;
                }
                *(float2*)&out[(size_t)row * NT + gc] = make_float2(v0, v1);
                if (WSPLIT && valid) {
                    __nv_bfloat162 hv = __floats2bfloat162_rn(v0, v1);
                    float l0 = v0 - __bfloat162float(hv.x);
                    float l1 = v1 - __bfloat162float(hv.y);
                    __nv_bfloat162 lv = __floats2bfloat162_rn(l0, l1);
                    *(uint32_t*)&ohi[(size_t)row * NT + gc] = *(uint32_t*)&hv;
                    *(uint32_t*)&olo[(size_t)row * NT + gc] = *(uint32_t*)&lv;
                }
            }
        }
    }
}

// ---------------- fused GAT aggregation: warp per node, online softmax ----------------
__device__ __forceinline__ void ol_merge(float& m, float& s, float4& a, float e,
                                         const float4& x) {
    float nm = fmaxf(m, e);
    float fo = __expf(m - nm), fe = __expf(e - nm);
    s = s * fo + fe;
    a.x = a.x * fo + fe * x.x;
    a.y = a.y * fo + fe * x.y;
    a.z = a.z * fo + fe * x.z;
    a.w = a.w * fo + fe * x.w;
    m = nm;
}
__global__ void gat_agg_kernel(const float* __restrict__ xlr, const int* __restrict__ rowoff,
                               const int* __restrict__ csrc, const float* __restrict__ att,
                               const float* __restrict__ bias, float* __restrict__ out,
                               __nv_bfloat16* __restrict__ ohi, __nv_bfloat16* __restrict__ olo,
                               float scale) {
    int node = blockIdx.x * 8 + (threadIdx.x >> 5);
    if (node >= NN) return;
    int lane = threadIdx.x & 31;
    const float4* X = (const float4*)xlr;
    float4 xr = X[(size_t)node * 64 + 32 + lane];
    float4 t = ((const float4*)att)[lane];
    int k = rowoff[node];
    int end = rowoff[node + 1];
    float m0 = -3.0e38f, s0 = 0.f, m1 = -3.0e38f, s1 = 0.f;
    float4 a0 = {0.f, 0.f, 0.f, 0.f}, a1 = {0.f, 0.f, 0.f, 0.f};
    for (; k + 4 <= end; k += 4) {
        int sa = csrc[k], sb = csrc[k + 1], sc = csrc[k + 2], sd = csrc[k + 3];
        float4 xA = X[(size_t)sa * 64 + lane];
        float4 xB = X[(size_t)sb * 64 + lane];
        float4 xC = X[(size_t)sc * 64 + lane];
        float4 xD = X[(size_t)sd * 64 + lane];
        float eA = lrelu(xA.x + xr.x) * t.x + lrelu(xA.y + xr.y) * t.y +
                   lrelu(xA.z + xr.z) * t.z + lrelu(xA.w + xr.w) * t.w;
        float eB = lrelu(xB.x + xr.x) * t.x + lrelu(xB.y + xr.y) * t.y +
                   lrelu(xB.z + xr.z) * t.z + lrelu(xB.w + xr.w) * t.w;
        float eC = lrelu(xC.x + xr.x) * t.x + lrelu(xC.y + xr.y) * t.y +
                   lrelu(xC.z + xr.z) * t.z + lrelu(xC.w + xr.w) * t.w;
        float eD = lrelu(xD.x + xr.x) * t.x + lrelu(xD.y + xr.y) * t.y +
                   lrelu(xD.z + xr.z) * t.z + lrelu(xD.w + xr.w) * t.w;
#pragma unroll
        for (int o = 16; o; o >>= 1) {
            eA += __shfl_xor_sync(0xFFFFFFFFu, eA, o);
            eB += __shfl_xor_sync(0xFFFFFFFFu, eB, o);
            eC += __shfl_xor_sync(0xFFFFFFFFu, eC, o);
            eD += __shfl_xor_sync(0xFFFFFFFFu, eD, o);
        }
        ol_merge(m0, s0, a0, eA, xA);
        ol_merge(m1, s1, a1, eB, xB);
        ol_merge(m0, s0, a0, eC, xC);
        ol_merge(m1, s1, a1, eD, xD);
    }
    for (; k < end; k++) {
        int sa = csrc[k];
        float4 xA = X[(size_t)sa * 64 + lane];
        float eA = lrelu(xA.x + xr.x) * t.x + lrelu(xA.y + xr.y) * t.y +
                   lrelu(xA.z + xr.z) * t.z + lrelu(xA.w + xr.w) * t.w;
#pragma unroll
        for (int o = 16; o; o >>= 1) eA += __shfl_xor_sync(0xFFFFFFFFu, eA, o);
        ol_merge(m0, s0, a0, eA, xA);
    }
    float m = fmaxf(m0, m1);
    float f0 = __expf(m0 - m), f1 = __expf(m1 - m);
    float s = s0 * f0 + s1 * f1;
    float inv = 1.f / (s + 1e-16f);
    float4 b4 = ((const float4*)bias)[lane];
    float4 r;
    r.x = fmaxf((a0.x * f0 + a1.x * f1) * inv + b4.x, 0.f) * scale;
    r.y = fmaxf((a0.y * f0 + a1.y * f1) * inv + b4.y, 0.f) * scale;
    r.z = fmaxf((a0.z * f0 + a1.z * f1) * inv + b4.z, 0.f) * scale;
    r.w = fmaxf((a0.w * f0 + a1.w * f1) * inv + b4.w, 0.f) * scale;
    ((float4*)out)[(size_t)node * 32 + lane] = r;
    __nv_bfloat162 h01 = __floats2bfloat162_rn(r.x, r.y);
    __nv_bfloat162 h23 = __floats2bfloat162_rn(r.z, r.w);
    float lx = r.x - __bfloat162float(h01.x);
    float ly = r.y - __bfloat162float(h01.y);
    float lz = r.z - __bfloat162float(h23.x);
    float lw = r.w - __bfloat162float(h23.y);
    __nv_bfloat162 l01 = __floats2bfloat162_rn(lx, ly);
    __nv_bfloat162 l23 = __floats2bfloat162_rn(lz, lw);
    uint2 uh, ul;
    uh.x = *(uint32_t*)&h01; uh.y = *(uint32_t*)&h23;
    ul.x = *(uint32_t*)&l01; ul.y = *(uint32_t*)&l23;
    ((uint2*)ohi)[(size_t)node * 32 + lane] = uh;
    ((uint2*)olo)[(size_t)node * 32 + lane] = ul;
}

// ---------------- pooling ----------------
__global__ void pool_kernel(const float* __restrict__ h, const int* __restrict__ batch,
                            float* __restrict__ pool, float* __restrict__ cnt) {
    int w = (blockIdx.x * blockDim.x + threadIdx.x) >> 5;
    if (w >= NN) return;
    int lane = threadIdx.x & 31;
    int g = batch[w];
    float4 v = ((const float4*)h)[(size_t)w * 32 + lane];
    atomicAdd((float4*)(pool + (size_t)g * NH + lane * 4), v);
    if (lane == 0) atomicAdd(&cnt[g], 1.f);
}

// ---------------- final MLP + layernorm ----------------
__global__ void mlp_kernel(const float* __restrict__ pool, const float* __restrict__ cnt,
                           const float* __restrict__ w1, const float* __restrict__ b1,
                           const float* __restrict__ w2, const float* __restrict__ b2,
                           const float* __restrict__ lng, const float* __restrict__ lnb,
                           float* __restrict__ out) {
    int g = blockIdx.x;
    int t = threadIdx.x;
    __shared__ float p[NH];
    __shared__ float z1[2 * NH];
    __shared__ float rs[8], rq[8];
    float inv = 1.f / fmaxf(cnt[g], 1.f);
    if (t < NH) p[t] = pool[g * NH + t] * inv;
    __syncthreads();
    float a = 0.f;
#pragma unroll 8
    for (int k = 0; k < NH; k++) a += p[k] * w1[k * (2 * NH) + t];
    z1[t] = fmaxf(a + b1[t], 0.f);
    __syncthreads();
    float z = 0.f;
#pragma unroll 8
    for (int k = 0; k < 2 * NH; k++) z += z1[k] * w2[k * NO + t];
    z += b2[t];
    float v = z, v2 = z * z;
#pragma unroll
    for (int o = 16; o; o >>= 1) {
        v += __shfl_xor_sync(0xFFFFFFFFu, v, o);
        v2 += __shfl_xor_sync(0xFFFFFFFFu, v2, o);
    }
    int wid = t >> 5, lane = t & 31;
    if (lane == 0) { rs[wid] = v; rq[wid] = v2; }
    __syncthreads();
    if (wid == 0) {
        float sv = lane < 8 ? rs[lane] : 0.f;
        float sq = lane < 8 ? rq[lane] : 0.f;
#pragma unroll
        for (int o = 4; o; o >>= 1) {
            sv += __shfl_xor_sync(0xFFFFFFFFu, sv, o);
            sq += __shfl_xor_sync(0xFFFFFFFFu, sq, o);
        }
        if (lane == 0) { rs[0] = sv; rq[0] = sq; }
    }
    __syncthreads();
    float mu = rs[0] * (1.f / NO);
    float var = rq[0] * (1.f / NO) - mu * mu;
    out[g * NO + t] = (z - mu) * rsqrtf(var + 1e-5f) * lng[t] + lnb[t];
}

// ---------------- host ----------------
extern "C" void kernel_launch(void* const* d_in, const int* in_sizes, int n_in,
                              void* d_out, int out_size) {
    const float* x = (const float*)d_in[0];
    const int* ei = (const int*)d_in[1];
    const int* src = ei;
    const int* dst = ei + NE;
    const int* batch = (const int*)d_in[2];
    const float* Wl[4] = {(const float*)d_in[3], (const float*)d_in[7],
                          (const float*)d_in[11], (const float*)d_in[15]};
    const float* Wr[4] = {(const float*)d_in[4], (const float*)d_in[8],
                          (const float*)d_in[12], (const float*)d_in[16]};
    const float* att[4] = {(const float*)d_in[5], (const float*)d_in[9],
                           (const float*)d_in[13], (const float*)d_in[17]};
    const float* bb[4] = {(const float*)d_in[6], (const float*)d_in[10],
                          (const float*)d_in[14], (const float*)d_in[18]};
    const float* res_w0 = (const float*)d_in[19];
    const float* res_b0 = (const float*)d_in[20];
    const float* res_w2 = (const float*)d_in[21];
    const float* res_b2 = (const float*)d_in[22];
    const float* mh1_w = (const float*)d_in[23];
    const float* mh1_b = (const float*)d_in[24];
    const float* mh2_w = (const float*)d_in[25];
    const float* mh2_b = (const float*)d_in[26];
    const float* ln_g = (const float*)d_in[27];
    const float* ln_b = (const float*)d_in[28];
    float* out = (float*)d_out;

    float *xlr, *h0, *h1, *pool, *cnt;
    __nv_bfloat16 *h0hi, *h0lo, *h1hi, *h1lo, *xhi, *xlo, *bfh, *bfl, *brh, *brl;
    int *rowoff, *cursor, *csrc;
    cudaGetSymbolAddress((void**)&xlr, g_xlr);
    cudaGetSymbolAddress((void**)&h0, g_h0);
    cudaGetSymbolAddress((void**)&h1, g_h1);
    cudaGetSymbolAddress((void**)&h0hi, g_h0hi);
    cudaGetSymbolAddress((void**)&h0lo, g_h0lo);
    cudaGetSymbolAddress((void**)&h1hi, g_h1hi);
    cudaGetSymbolAddress((void**)&h1lo, g_h1lo);
    cudaGetSymbolAddress((void**)&xhi, g_xhi);
    cudaGetSymbolAddress((void**)&xlo, g_xlo);
    cudaGetSymbolAddress((void**)&bfh, g_bfh);
    cudaGetSymbolAddress((void**)&bfl, g_bfl);
    cudaGetSymbolAddress((void**)&brh, g_brh);
    cudaGetSymbolAddress((void**)&brl, g_brl);
    cudaGetSymbolAddress((void**)&rowoff, g_rowoff);
    cudaGetSymbolAddress((void**)&cursor, g_cursor);
    cudaGetSymbolAddress((void**)&csrc, g_csrc);
    cudaGetSymbolAddress((void**)&pool, g_pool);
    cudaGetSymbolAddress((void**)&cnt, g_cnt);

    // ---- CSR build ----
    cudaMemsetAsync(cursor, 0, NN * sizeof(int), 0);
    hist_kernel<<<(NE + 255) / 256, 256>>>(dst, cursor);
    scan_kernel<<<1, 1024>>>(cursor, rowoff, cursor);
    fill_kernel<<<(NE + 255) / 256, 256>>>(src, dst, cursor, csrc);

    // ---- weight pack + split ----
    const int Kd[4] = {NIN, NH, NH, NH};
    for (int li = 0; li < 4; li++) {
        pack_fused_kernel<<<(256 * Kd[li] + 255) / 256, 256>>>(
            Wl[li], Wr[li], bfh + (size_t)li * 256 * 128, bfl + (size_t)li * 256 * 128, Kd[li]);
    }
    pack_res_kernel<<<(128 * 128 + 255) / 256, 256>>>(res_w0, brh, brl);
    pack_res_kernel<<<(128 * 128 + 255) / 256, 256>>>(res_w2, brh + 128 * 128, brl + 128 * 128);
    split_x_kernel<<<(NN * NIN + 255) / 256, 256>>>(x, xhi, xlo);

    // ---- smem ----
    const int SMEM_MM = 4 * 128 * 72 * 2;  // 73728
    cudaFuncSetAttribute(mm_gemm<64, 256, false, false, false>,
                         cudaFuncAttributeMaxDynamicSharedMemorySize, SMEM_MM);
    cudaFuncSetAttribute(mm_gemm<128, 256, false, false, false>,
                         cudaFuncAttributeMaxDynamicSharedMemorySize, SMEM_MM);
    cudaFuncSetAttribute(mm_gemm<128, 128, true, true, true>,
                         cudaFuncAttributeMaxDynamicSharedMemorySize, SMEM_MM);

    const int GT = NP / 128;  // 313
    dim3 gf(GT, 2), gr(GT, 1);
    const int AGG_BLK = (NN + 7) / 8;

    // layer 1
    mm_gemm<64, 256, false, false, false><<<gf, 256, SMEM_MM>>>(
        xhi, xlo, bfh, bfl, nullptr, nullptr, xlr, nullptr, nullptr);
    gat_agg_kernel<<<AGG_BLK, 256>>>(xlr, rowoff, csrc, att[0], bb[0], h0, h0hi, h0lo, 1.f);
    mm_gemm<128, 128, true, true, true><<<gr, 256, SMEM_MM>>>(
        h0hi, h0lo, brh, brl, res_b0, h0, h1, h1hi, h1lo);
    // layer 2
    mm_gemm<128, 256, false, false, false><<<gf, 256, SMEM_MM>>>(
        h1hi, h1lo, bfh + 256 * 128, bfl + 256 * 128, nullptr, nullptr, xlr, nullptr, nullptr);
    gat_agg_kernel<<<AGG_BLK, 256>>>(xlr, rowoff, csrc, att[1], bb[1], h0, h0hi, h0lo, 2.f);
    // layer 3
    mm_gemm<128, 256, false, false, false><<<gf, 256, SMEM_MM>>>(
        h0hi, h0lo, bfh + 2 * 256 * 128, bfl + 2 * 256 * 128, nullptr, nullptr, xlr, nullptr,
        nullptr);
    gat_agg_kernel<<<AGG_BLK, 256>>>(xlr, rowoff, csrc, att[2], bb[2], h1, h1hi, h1lo, 1.f);
    mm_gemm<128, 128, true, true, true><<<gr, 256, SMEM_MM>>>(
        h1hi, h1lo, brh + 128 * 128, brl + 128 * 128, res_b2, h1, h0, h0hi, h0lo);
    // layer 4
    mm_gemm<128, 256, false, false, false><<<gf, 256, SMEM_MM>>>(
        h0hi, h0lo, bfh + 3 * 256 * 128, bfl + 3 * 256 * 128, nullptr, nullptr, xlr, nullptr,
        nullptr);
    gat_agg_kernel<<<AGG_BLK, 256>>>(xlr, rowoff, csrc, att[3], bb[3], h1, h0hi, h0lo, 2.f);

    // pooling + MLP + layernorm
    cudaMemsetAsync(pool, 0, (NG * NH + NG) * 0 + NG * NH * sizeof(float), 0);
    cudaMemsetAsync(cnt, 0, NG * sizeof(float), 0);
    pool_kernel<<<(NN * 32 + 255) / 256, 256>>>(h1, batch, pool, cnt);
    mlp_kernel<<<NG, 256>>>(pool, cnt, mh1_w, mh1_b, mh2_w, mh2_b, ln_g, ln_b, out);
}

// round 7
// speedup vs baseline: 2.4072x; 1.0343x over previous
#include <cuda_runtime.h>
#include <cuda_bf16.h>
#include <math.h>
#include <stdint.h>

#define NN 40000
#define NP 40064          // padded rows (313 * 128)
#define NE 640000
#define NG 128
#define NIN 64
#define NH 128
#define NO 256

// ---------------- scratch (device globals; no allocation allowed) ----------------
__device__ float g_xlr[NP * 256];
__device__ float g_h0[NP * NH];
__device__ float g_h1[NP * NH];
__device__ __align__(16) __nv_bfloat16 g_h0hi[NP * NH];
__device__ __align__(16) __nv_bfloat16 g_h0lo[NP * NH];
__device__ __align__(16) __nv_bfloat16 g_h1hi[NP * NH];
__device__ __align__(16) __nv_bfloat16 g_h1lo[NP * NH];
__device__ __align__(16) __nv_bfloat16 g_xhi[NP * NIN];
__device__ __align__(16) __nv_bfloat16 g_xlo[NP * NIN];
__device__ __align__(16) __nv_bfloat16 g_bfh[4][256 * 128];  // fused [Wl|Wr]^T hi ([N,K])
__device__ __align__(16) __nv_bfloat16 g_bfl[4][256 * 128];  // fused lo
__device__ __align__(16) __nv_bfloat16 g_brh[2][128 * 128];  // res W^T hi
__device__ __align__(16) __nv_bfloat16 g_brl[2][128 * 128];  // res lo
__device__ int   g_rowoff[NN + 1];
__device__ int   g_cursor[NN];
__device__ int   g_csrc[NE];
__device__ float g_pool[NG * NH];
__device__ float g_cnt[NG];

__device__ __forceinline__ float lrelu(float v) { return v > 0.f ? v : 0.2f * v; }

__device__ __forceinline__ uint32_t smem_u32(const void* p) {
    uint32_t a;
    asm("{ .reg .u64 t; cvta.to.shared.u64 t, %1; cvt.u32.u64 %0, t; }" : "=r"(a) : "l"(p));
    return a;
}
__device__ __forceinline__ void ldsm4(uint32_t* r, uint32_t addr) {
    asm volatile("ldmatrix.sync.aligned.m8n8.x4.shared.b16 {%0,%1,%2,%3}, [%4];"
                 : "=r"(r[0]), "=r"(r[1]), "=r"(r[2]), "=r"(r[3]) : "r"(addr));
}
__device__ __forceinline__ void mma_bf16(float* d, const uint32_t* a, uint32_t b0, uint32_t b1) {
    asm volatile(
        "mma.sync.aligned.m16n8k16.row.col.f32.bf16.bf16.f32 "
        "{%0,%1,%2,%3}, {%4,%5,%6,%7}, {%8,%9}, {%0,%1,%2,%3};"
        : "+f"(d[0]), "+f"(d[1]), "+f"(d[2]), "+f"(d[3])
        : "r"(a[0]), "r"(a[1]), "r"(a[2]), "r"(a[3]), "r"(b0), "r"(b1));
}
__device__ __forceinline__ void cp16(uint32_t dst, const void* src) {
    asm volatile("cp.async.cg.shared.global [%0], [%1], 16;" :: "r"(dst), "l"(src));
}
#define CP_COMMIT_WAIT() \
    asm volatile("cp.async.commit_group;\ncp.async.wait_group 0;" ::: "memory")

// ---------------- CSR build ----------------
__global__ void hist_kernel(const int* __restrict__ dst, int* __restrict__ cnt) {
    int i = blockIdx.x * blockDim.x + threadIdx.x;
    if (i < NE) atomicAdd(&cnt[dst[i]], 1);
}
__global__ void scan_kernel(const int* __restrict__ cnt, int* __restrict__ rowoff,
                            int* __restrict__ cursor) {
    __shared__ int s_carry;
    __shared__ int warpsums[32];
    int lane = threadIdx.x & 31, wid = threadIdx.x >> 5;
    if (threadIdx.x == 0) s_carry = 0;
    __syncthreads();
    for (int base = 0; base < NN; base += 1024) {
        int i = base + (int)threadIdx.x;
        int v = (i < NN) ? cnt[i] : 0;
        int x = v;
#pragma unroll
        for (int o = 1; o < 32; o <<= 1) {
            int y = __shfl_up_sync(0xFFFFFFFFu, x, o);
            if (lane >= o) x += y;
        }
        if (lane == 31) warpsums[wid] = x;
        __syncthreads();
        if (wid == 0) {
            int w = warpsums[lane];
#pragma unroll
            for (int o = 1; o < 32; o <<= 1) {
                int y = __shfl_up_sync(0xFFFFFFFFu, w, o);
                if (lane >= o) w += y;
            }
            warpsums[lane] = w;
        }
        __syncthreads();
        int incl = x + (wid > 0 ? warpsums[wid - 1] : 0) + s_carry;
        int excl = incl - v;
        if (i < NN) { rowoff[i] = excl; cursor[i] = excl; }
        __syncthreads();
        if (threadIdx.x == 1023) s_carry = incl;
        __syncthreads();
    }
    if (threadIdx.x == 0) rowoff[NN] = NE;
}
__global__ void fill_kernel(const int* __restrict__ src, const int* __restrict__ dst,
                            int* __restrict__ cursor, int* __restrict__ csrc) {
    int i = blockIdx.x * blockDim.x + threadIdx.x;
    if (i >= NE) return;
    int pos = atomicAdd(&cursor[dst[i]], 1);
    csrc[pos] = src[i];
}

// ---------------- weight pack+split (transposed to [N,K]) ----------------
__global__ void pack_fused_kernel(const float* __restrict__ Wl, const float* __restrict__ Wr,
                                  __nv_bfloat16* __restrict__ bh, __nv_bfloat16* __restrict__ bl,
                                  int K) {
    int i = blockIdx.x * blockDim.x + threadIdx.x;
    if (i >= 256 * K) return;
    int n = i / K, k = i % K;
    float v = (n < 128) ? Wl[k * 128 + n] : Wr[k * 128 + (n - 128)];
    __nv_bfloat16 h = __float2bfloat16(v);
    bh[i] = h;
    bl[i] = __float2bfloat16(v - __bfloat162float(h));
}
__global__ void pack_res_kernel(const float* __restrict__ W, __nv_bfloat16* __restrict__ bh,
                                __nv_bfloat16* __restrict__ bl) {
    int i = blockIdx.x * blockDim.x + threadIdx.x;
    if (i >= 128 * 128) return;
    int n = i >> 7, k = i & 127;
    float v = W[k * 128 + n];
    __nv_bfloat16 h = __float2bfloat16(v);
    bh[i] = h;
    bl[i] = __float2bfloat16(v - __bfloat162float(h));
}
__global__ void split_x_kernel(const float* __restrict__ x, __nv_bfloat16* __restrict__ hi,
                               __nv_bfloat16* __restrict__ lo) {
    int i = blockIdx.x * blockDim.x + threadIdx.x;
    if (i >= NN * NIN) return;
    float f = x[i];
    __nv_bfloat16 h = __float2bfloat16(f);
    hi[i] = h;
    lo[i] = __float2bfloat16(f - __bfloat162float(h));
}

// ---------------- tensor-core GEMM via mma.sync (bf16 3-term split) ----------------
template <int K, int NT, bool BIAS, bool ADDIN, bool WSPLIT>
__global__ void __launch_bounds__(256, 2) mm_gemm(
    const __nv_bfloat16* __restrict__ Ah, const __nv_bfloat16* __restrict__ Al,
    const __nv_bfloat16* __restrict__ Bh, const __nv_bfloat16* __restrict__ Bl,
    const float* __restrict__ bias, const float* __restrict__ add, float* __restrict__ out,
    __nv_bfloat16* __restrict__ ohi, __nv_bfloat16* __restrict__ olo) {
    extern __shared__ char smem[];
    constexpr int KC = 64, ST = 72;
    constexpr int TB = 128 * ST;
    __nv_bfloat16* sAh = (__nv_bfloat16*)smem;
    __nv_bfloat16* sAl = sAh + TB;
    __nv_bfloat16* sBh = sAl + TB;
    __nv_bfloat16* sBl = sBh + TB;
    int tid = threadIdx.x, lane = tid & 31, wid = tid >> 5;
    int warp_m = wid & 3, warp_n = wid >> 2;
    int bm = blockIdx.x * 128, bn = blockIdx.y * 128;
    const __nv_bfloat16* Bh_blk = Bh + (size_t)bn * K;
    const __nv_bfloat16* Bl_blk = Bl + (size_t)bn * K;

    float acc[2][8][4];
#pragma unroll
    for (int i = 0; i < 2; i++)
#pragma unroll
        for (int j = 0; j < 8; j++)
#pragma unroll
            for (int q = 0; q < 4; q++) acc[i][j][q] = 0.f;

    int g = lane >> 3, lr = lane & 7;
    int frow = lr + ((g & 1) << 3);
    int fcol = (g >> 1) << 3;

    for (int kc = 0; kc < K; kc += KC) {
        if (kc) __syncthreads();
#pragma unroll
        for (int idx = tid; idx < 1024; idx += 256) {
            int r = idx >> 3, c = (idx & 7) * 8;
            cp16(smem_u32(&sAh[r * ST + c]), &Ah[(size_t)(bm + r) * K + kc + c]);
            cp16(smem_u32(&sAl[r * ST + c]), &Al[(size_t)(bm + r) * K + kc + c]);
            cp16(smem_u32(&sBh[r * ST + c]), &Bh_blk[(size_t)r * K + kc + c]);
            cp16(smem_u32(&sBl[r * ST + c]), &Bl_blk[(size_t)r * K + kc + c]);
        }
        CP_COMMIT_WAIT();
        __syncthreads();
#pragma unroll
        for (int ks = 0; ks < 4; ks++) {
            int kcol = ks * 16 + fcol;
            uint32_t ah0[4], ah1[4], al0[4], al1[4];
            ldsm4(ah0, smem_u32(&sAh[(warp_m * 32 + frow) * ST + kcol]));
            ldsm4(ah1, smem_u32(&sAh[(warp_m * 32 + 16 + frow) * ST + kcol]));
            ldsm4(al0, smem_u32(&sAl[(warp_m * 32 + frow) * ST + kcol]));
            ldsm4(al1, smem_u32(&sAl[(warp_m * 32 + 16 + frow) * ST + kcol]));
#pragma unroll
            for (int tp = 0; tp < 4; tp++) {
                int brow = warp_n * 64 + tp * 16 + frow;
                uint32_t bh[4], bl[4];
                ldsm4(bh, smem_u32(&sBh[brow * ST + kcol]));
                ldsm4(bl, smem_u32(&sBl[brow * ST + kcol]));
                mma_bf16(acc[0][tp * 2 + 0], ah0, bh[0], bh[2]);
                mma_bf16(acc[0][tp * 2 + 1], ah0, bh[1], bh[3]);
                mma_bf16(acc[1][tp * 2 + 0], ah1, bh[0], bh[2]);
                mma_bf16(acc[1][tp * 2 + 1], ah1, bh[1], bh[3]);
                mma_bf16(acc[0][tp * 2 + 0], ah0, bl[0], bl[2]);
                mma_bf16(acc[0][tp * 2 + 1], ah0, bl[1], bl[3]);
                mma_bf16(acc[1][tp * 2 + 0], ah1, bl[0], bl[2]);
                mma_bf16(acc[1][tp * 2 + 1], ah1, bl[1], bl[3]);
                mma_bf16(acc[0][tp * 2 + 0], al0, bh[0], bh[2]);
                mma_bf16(acc[0][tp * 2 + 1], al0, bh[1], bh[3]);
                mma_bf16(acc[1][tp * 2 + 0], al1, bh[0], bh[2]);
                mma_bf16(acc[1][tp * 2 + 1], al1, bh[1], bh[3]);
            }
        }
    }

    int lr4 = lane >> 2, lc = (lane & 3) * 2;
#pragma unroll
    for (int tm = 0; tm < 2; tm++) {
#pragma unroll
        for (int half = 0; half < 2; half++) {
            int row = bm + warp_m * 32 + tm * 16 + lr4 + half * 8;
            bool valid = row < NN;
#pragma unroll
            for (int tn = 0; tn < 8; tn++) {
                int gc = bn + warp_n * 64 + tn * 8 + lc;
                float v0 = acc[tm][tn][half * 2 + 0];
                float v1 = acc[tm][tn][half * 2 + 1];
                if (BIAS) { v0 += bias[gc]; v1 += bias[gc + 1]; }
                if (ADDIN) {
                    float2 a2 = *(const float2*)&add[(size_t)row * NT + gc];
                    v0 += a2.x; v1 += a2.y;
                }
                *(float2*)&out[(size_t)row * NT + gc] = make_float2(v0, v1);
                if (WSPLIT && valid) {
                    __nv_bfloat162 hv = __floats2bfloat162_rn(v0, v1);
                    float l0 = v0 - __bfloat162float(hv.x);
                    float l1 = v1 - __bfloat162float(hv.y);
                    __nv_bfloat162 lv = __floats2bfloat162_rn(l0, l1);
                    *(uint32_t*)&ohi[(size_t)row * NT + gc] = *(uint32_t*)&hv;
                    *(uint32_t*)&olo[(size_t)row * NT + gc] = *(uint32_t*)&lv;
                }
            }
        }
    }
}

// ---------------- fused GAT aggregation: warp per node, online softmax ----------------
__device__ __forceinline__ void ol_merge(float& m, float& s, float4& a, float e,
                                         const float4& x) {
    float nm = fmaxf(m, e);
    float fo = __expf(m - nm), fe = __expf(e - nm);
    s = s * fo + fe;
    a.x = a.x * fo + fe * x.x;
    a.y = a.y * fo + fe * x.y;
    a.z = a.z * fo + fe * x.z;
    a.w = a.w * fo + fe * x.w;
    m = nm;
}
__global__ void gat_agg_kernel(const float* __restrict__ xlr, const int* __restrict__ rowoff,
                               const int* __restrict__ csrc, const float* __restrict__ att,
                               const float* __restrict__ bias, float* __restrict__ out,
                               __nv_bfloat16* __restrict__ ohi, __nv_bfloat16* __restrict__ olo,
                               float scale) {
    int node = blockIdx.x * 8 + (threadIdx.x >> 5);
    if (node >= NN) return;
    int lane = threadIdx.x & 31;
    const float4* X = (const float4*)xlr;
    float4 xr = X[(size_t)node * 64 + 32 + lane];
    float4 t = ((const float4*)att)[lane];
    int k = rowoff[node];
    int end = rowoff[node + 1];
    float m0 = -3.0e38f, s0 = 0.f, m1 = -3.0e38f, s1 = 0.f;
    float4 a0 = {0.f, 0.f, 0.f, 0.f}, a1 = {0.f, 0.f, 0.f, 0.f};
    for (; k + 4 <= end; k += 4) {
        int sa = csrc[k], sb = csrc[k + 1], sc = csrc[k + 2], sd = csrc[k + 3];
        float4 xA = X[(size_t)sa * 64 + lane];
        float4 xB = X[(size_t)sb * 64 + lane];
        float4 xC = X[(size_t)sc * 64 + lane];
        float4 xD = X[(size_t)sd * 64 + lane];
        float eA = lrelu(xA.x + xr.x) * t.x + lrelu(xA.y + xr.y) * t.y +
                   lrelu(xA.z + xr.z) * t.z + lrelu(xA.w + xr.w) * t.w;
        float eB = lrelu(xB.x + xr.x) * t.x + lrelu(xB.y + xr.y) * t.y +
                   lrelu(xB.z + xr.z) * t.z + lrelu(xB.w + xr.w) * t.w;
        float eC = lrelu(xC.x + xr.x) * t.x + lrelu(xC.y + xr.y) * t.y +
                   lrelu(xC.z + xr.z) * t.z + lrelu(xC.w + xr.w) * t.w;
        float eD = lrelu(xD.x + xr.x) * t.x + lrelu(xD.y + xr.y) * t.y +
                   lrelu(xD.z + xr.z) * t.z + lrelu(xD.w + xr.w) * t.w;
#pragma unroll
        for (int o = 16; o; o >>= 1) {
            eA += __shfl_xor_sync(0xFFFFFFFFu, eA, o);
            eB += __shfl_xor_sync(0xFFFFFFFFu, eB, o);
            eC += __shfl_xor_sync(0xFFFFFFFFu, eC, o);
            eD += __shfl_xor_sync(0xFFFFFFFFu, eD, o);
        }
        ol_merge(m0, s0, a0, eA, xA);
        ol_merge(m1, s1, a1, eB, xB);
        ol_merge(m0, s0, a0, eC, xC);
        ol_merge(m1, s1, a1, eD, xD);
    }
    for (; k < end; k++) {
        int sa = csrc[k];
        float4 xA = X[(size_t)sa * 64 + lane];
        float eA = lrelu(xA.x + xr.x) * t.x + lrelu(xA.y + xr.y) * t.y +
                   lrelu(xA.z + xr.z) * t.z + lrelu(xA.w + xr.w) * t.w;
#pragma unroll
        for (int o = 16; o; o >>= 1) eA += __shfl_xor_sync(0xFFFFFFFFu, eA, o);
        ol_merge(m0, s0, a0, eA, xA);
    }
    float m = fmaxf(m0, m1);
    float f0 = __expf(m0 - m), f1 = __expf(m1 - m);
    float s = s0 * f0 + s1 * f1;
    float inv = 1.f / (s + 1e-16f);
    float4 b4 = ((const float4*)bias)[lane];
    float4 r;
    r.x = fmaxf((a0.x * f0 + a1.x * f1) * inv + b4.x, 0.f) * scale;
    r.y = fmaxf((a0.y * f0 + a1.y * f1) * inv + b4.y, 0.f) * scale;
    r.z = fmaxf((a0.z * f0 + a1.z * f1) * inv + b4.z, 0.f) * scale;
    r.w = fmaxf((a0.w * f0 + a1.w * f1) * inv + b4.w, 0.f) * scale;
    ((float4*)out)[(size_t)node * 32 + lane] = r;
    __nv_bfloat162 h01 = __floats2bfloat162_rn(r.x, r.y);
    __nv_bfloat162 h23 = __floats2bfloat162_rn(r.z, r.w);
    float lx = r.x - __bfloat162float(h01.x);
    float ly = r.y - __bfloat162float(h01.y);
    float lz = r.z - __bfloat162float(h23.x);
    float lw = r.w - __bfloat162float(h23.y);
    __nv_bfloat162 l01 = __floats2bfloat162_rn(lx, ly);
    __nv_bfloat162 l23 = __floats2bfloat162_rn(lz, lw);
    uint2 uh, ul;
    uh.x = *(uint32_t*)&h01; uh.y = *(uint32_t*)&h23;
    ul.x = *(uint32_t*)&l01; ul.y = *(uint32_t*)&l23;
    ((uint2*)ohi)[(size_t)node * 32 + lane] = uh;
    ((uint2*)olo)[(size_t)node * 32 + lane] = ul;
}

// ---------------- pooling ----------------
__global__ void pool_kernel(const float* __restrict__ h, const int* __restrict__ batch,
                            float* __restrict__ pool, float* __restrict__ cnt) {
    int w = (blockIdx.x * blockDim.x + threadIdx.x) >> 5;
    if (w >= NN) return;
    int lane = threadIdx.x & 31;
    int g = batch[w];
    float4 v = ((const float4*)h)[(size_t)w * 32 + lane];
    atomicAdd((float4*)(pool + (size_t)g * NH + lane * 4), v);
    if (lane == 0) atomicAdd(&cnt[g], 1.f);
}

// ---------------- final MLP + layernorm ----------------
__global__ void mlp_kernel(const float* __restrict__ pool, const float* __restrict__ cnt,
                           const float* __restrict__ w1, const float* __restrict__ b1,
                           const float* __restrict__ w2, const float* __restrict__ b2,
                           const float* __restrict__ lng, const float* __restrict__ lnb,
                           float* __restrict__ out) {
    int g = blockIdx.x;
    int t = threadIdx.x;
    __shared__ float p[NH];
    __shared__ float z1[2 * NH];
    __shared__ float rs[8], rq[8];
    float inv = 1.f / fmaxf(cnt[g], 1.f);
    if (t < NH) p[t] = pool[g * NH + t] * inv;
    __syncthreads();
    float a = 0.f;
#pragma unroll 8
    for (int k = 0; k < NH; k++) a += p[k] * w1[k * (2 * NH) + t];
    z1[t] = fmaxf(a + b1[t], 0.f);
    __syncthreads();
    float z = 0.f;
#pragma unroll 8
    for (int k = 0; k < 2 * NH; k++) z += z1[k] * w2[k * NO + t];
    z += b2[t];
    float v = z, v2 = z * z;
#pragma unroll
    for (int o = 16; o; o >>= 1) {
        v += __shfl_xor_sync(0xFFFFFFFFu, v, o);
        v2 += __shfl_xor_sync(0xFFFFFFFFu, v2, o);
    }
    int wid = t >> 5, lane = t & 31;
    if (lane == 0) { rs[wid] = v; rq[wid] = v2; }
    __syncthreads();
    if (wid == 0) {
        float sv = lane < 8 ? rs[lane] : 0.f;
        float sq = lane < 8 ? rq[lane] : 0.f;
#pragma unroll
        for (int o = 4; o; o >>= 1) {
            sv += __shfl_xor_sync(0xFFFFFFFFu, sv, o);
            sq += __shfl_xor_sync(0xFFFFFFFFu, sq, o);
        }
        if (lane == 0) { rs[0] = sv; rq[0] = sq; }
    }
    __syncthreads();
    float mu = rs[0] * (1.f / NO);
    float var = rq[0] * (1.f / NO) - mu * mu;
    out[g * NO + t] = (z - mu) * rsqrtf(var + 1e-5f) * lng[t] + lnb[t];
}

// ---------------- host ----------------
extern "C" void kernel_launch(void* const* d_in, const int* in_sizes, int n_in,
                              void* d_out, int out_size) {
    const float* x = (const float*)d_in[0];
    const int* ei = (const int*)d_in[1];
    const int* src = ei;
    const int* dst = ei + NE;
    const int* batch = (const int*)d_in[2];
    const float* Wl[4] = {(const float*)d_in[3], (const float*)d_in[7],
                          (const float*)d_in[11], (const float*)d_in[15]};
    const float* Wr[4] = {(const float*)d_in[4], (const float*)d_in[8],
                          (const float*)d_in[12], (const float*)d_in[16]};
    const float* att[4] = {(const float*)d_in[5], (const float*)d_in[9],
                           (const float*)d_in[13], (const float*)d_in[17]};
    const float* bb[4] = {(const float*)d_in[6], (const float*)d_in[10],
                          (const float*)d_in[14], (const float*)d_in[18]};
    const float* res_w0 = (const float*)d_in[19];
    const float* res_b0 = (const float*)d_in[20];
    const float* res_w2 = (const float*)d_in[21];
    const float* res_b2 = (const float*)d_in[22];
    const float* mh1_w = (const float*)d_in[23];
    const float* mh1_b = (const float*)d_in[24];
    const float* mh2_w = (const float*)d_in[25];
    const float* mh2_b = (const float*)d_in[26];
    const float* ln_g = (const float*)d_in[27];
    const float* ln_b = (const float*)d_in[28];
    float* out = (float*)d_out;

    float *xlr, *h0, *h1, *pool, *cnt;
    __nv_bfloat16 *h0hi, *h0lo, *h1hi, *h1lo, *xhi, *xlo, *bfh, *bfl, *brh, *brl;
    int *rowoff, *cursor, *csrc;
    cudaGetSymbolAddress((void**)&xlr, g_xlr);
    cudaGetSymbolAddress((void**)&h0, g_h0);
    cudaGetSymbolAddress((void**)&h1, g_h1);
    cudaGetSymbolAddress((void**)&h0hi, g_h0hi);
    cudaGetSymbolAddress((void**)&h0lo, g_h0lo);
    cudaGetSymbolAddress((void**)&h1hi, g_h1hi);
    cudaGetSymbolAddress((void**)&h1lo, g_h1lo);
    cudaGetSymbolAddress((void**)&xhi, g_xhi);
    cudaGetSymbolAddress((void**)&xlo, g_xlo);
    cudaGetSymbolAddress((void**)&bfh, g_bfh);
    cudaGetSymbolAddress((void**)&bfl, g_bfl);
    cudaGetSymbolAddress((void**)&brh, g_brh);
    cudaGetSymbolAddress((void**)&brl, g_brl);
    cudaGetSymbolAddress((void**)&rowoff, g_rowoff);
    cudaGetSymbolAddress((void**)&cursor, g_cursor);
    cudaGetSymbolAddress((void**)&csrc, g_csrc);
    cudaGetSymbolAddress((void**)&pool, g_pool);
    cudaGetSymbolAddress((void**)&cnt, g_cnt);

    // ---- smem attrs (idempotent) ----
    const int SMEM_MM = 4 * 128 * 72 * 2;  // 73728
    cudaFuncSetAttribute(mm_gemm<64, 256, false, false, false>,
                         cudaFuncAttributeMaxDynamicSharedMemorySize, SMEM_MM);
    cudaFuncSetAttribute(mm_gemm<128, 256, false, false, false>,
                         cudaFuncAttributeMaxDynamicSharedMemorySize, SMEM_MM);
    cudaFuncSetAttribute(mm_gemm<128, 128, true, true, true>,
                         cudaFuncAttributeMaxDynamicSharedMemorySize, SMEM_MM);

    const int Kd[4] = {NIN, NH, NH, NH};
    const int GT = NP / 128;  // 313
    dim3 gf(GT, 2), gr(GT, 1);
    const int AGG_BLK = (NN + 7) / 8;

    // ---- fork a side stream for the independent prologue chain ----
    cudaStream_t s2;
    cudaEvent_t evF, evJ;
    cudaStreamCreateWithFlags(&s2, cudaStreamNonBlocking);
    cudaEventCreateWithFlags(&evF, cudaEventDisableTiming);
    cudaEventCreateWithFlags(&evJ, cudaEventDisableTiming);
    cudaEventRecord(evF, 0);
    cudaStreamWaitEvent(s2, evF, 0);

    // s2: CSR build + pool init + packs for layers 2-4 and res
    cudaMemsetAsync(cursor, 0, NN * sizeof(int), s2);
    hist_kernel<<<(NE + 255) / 256, 256, 0, s2>>>(dst, cursor);
    scan_kernel<<<1, 1024, 0, s2>>>(cursor, rowoff, cursor);
    fill_kernel<<<(NE + 255) / 256, 256, 0, s2>>>(src, dst, cursor, csrc);
    cudaMemsetAsync(pool, 0, NG * NH * sizeof(float), s2);
    cudaMemsetAsync(cnt, 0, NG * sizeof(float), s2);
    for (int li = 1; li < 4; li++) {
        pack_fused_kernel<<<(256 * Kd[li] + 255) / 256, 256, 0, s2>>>(
            Wl[li], Wr[li], bfh + (size_t)li * 256 * 128, bfl + (size_t)li * 256 * 128, Kd[li]);
    }
    pack_res_kernel<<<(128 * 128 + 255) / 256, 256, 0, s2>>>(res_w0, brh, brl);
    pack_res_kernel<<<(128 * 128 + 255) / 256, 256, 0, s2>>>(res_w2, brh + 128 * 128,
                                                             brl + 128 * 128);
    cudaEventRecord(evJ, s2);

    // main stream: layer-1 dependencies + layer-1 GEMM (overlaps with s2)
    pack_fused_kernel<<<(256 * Kd[0] + 255) / 256, 256>>>(Wl[0], Wr[0], bfh, bfl, Kd[0]);
    split_x_kernel<<<(NN * NIN + 255) / 256, 256>>>(x, xhi, xlo);
    mm_gemm<64, 256, false, false, false><<<gf, 256, SMEM_MM>>>(
        xhi, xlo, bfh, bfl, nullptr, nullptr, xlr, nullptr, nullptr);

    // join: everything after needs CSR / packed weights
    cudaStreamWaitEvent(0, evJ, 0);

    // layer 1 agg + residual
    gat_agg_kernel<<<AGG_BLK, 256>>>(xlr, rowoff, csrc, att[0], bb[0], h0, h0hi, h0lo, 1.f);
    mm_gemm<128, 128, true, true, true><<<gr, 256, SMEM_MM>>>(
        h0hi, h0lo, brh, brl, res_b0, h0, h1, h1hi, h1lo);
    // layer 2
    mm_gemm<128, 256, false, false, false><<<gf, 256, SMEM_MM>>>(
        h1hi, h1lo, bfh + 256 * 128, bfl + 256 * 128, nullptr, nullptr, xlr, nullptr, nullptr);
    gat_agg_kernel<<<AGG_BLK, 256>>>(xlr, rowoff, csrc, att[1], bb[1], h0, h0hi, h0lo, 2.f);
    // layer 3
    mm_gemm<128, 256, false, false, false><<<gf, 256, SMEM_MM>>>(
        h0hi, h0lo, bfh + 2 * 256 * 128, bfl + 2 * 256 * 128, nullptr, nullptr, xlr, nullptr,
        nullptr);
    gat_agg_kernel<<<AGG_BLK, 256>>>(xlr, rowoff, csrc, att[2], bb[2], h1, h1hi, h1lo, 1.f);
    mm_gemm<128, 128, true, true, true><<<gr, 256, SMEM_MM>>>(
        h1hi, h1lo, brh + 128 * 128, brl + 128 * 128, res_b2, h1, h0, h0hi, h0lo);
    // layer 4
    mm_gemm<128, 256, false, false, false><<<gf, 256, SMEM_MM>>>(
        h0hi, h0lo, bfh + 3 * 256 * 128, bfl + 3 * 256 * 128, nullptr, nullptr, xlr, nullptr,
        nullptr);
    gat_agg_kernel<<<AGG_BLK, 256>>>(xlr, rowoff, csrc, att[3], bb[3], h1, h0hi, h0lo, 2.f);

    // pooling + MLP + layernorm
    pool_kernel<<<(NN * 32 + 255) / 256, 256>>>(h1, batch, pool, cnt);
    mlp_kernel<<<NG, 256>>>(pool, cnt, mh1_w, mh1_b, mh2_w, mh2_b, ln_g, ln_b, out);
}

// round 8
// speedup vs baseline: 2.4579x; 1.0211x over previous
#include <cuda_runtime.h>
#include <cuda_bf16.h>
#include <math.h>
#include <stdint.h>

#define NN 40000
#define NP 40064          // padded rows (313 * 128)
#define NE 640000
#define NG 128
#define NIN 64
#define NH 128
#define NO 256

// ---------------- scratch (device globals; no allocation allowed) ----------------
__device__ __align__(16) __nv_bfloat16 g_xlb[NP * NH];   // xl in bf16 (gathered per edge)
__device__ float g_xr[NP * NH];                          // xr in fp32 (read per node)
__device__ float g_h0[NP * NH];
__device__ float g_h1[NP * NH];
__device__ __align__(16) __nv_bfloat16 g_h0hi[NP * NH];
__device__ __align__(16) __nv_bfloat16 g_h0lo[NP * NH];
__device__ __align__(16) __nv_bfloat16 g_h1hi[NP * NH];
__device__ __align__(16) __nv_bfloat16 g_h1lo[NP * NH];
__device__ __align__(16) __nv_bfloat16 g_xhi[NP * NIN];
__device__ __align__(16) __nv_bfloat16 g_xlo[NP * NIN];
__device__ __align__(16) __nv_bfloat16 g_bfh[4][256 * 128];  // fused [Wl|Wr]^T hi ([N,K])
__device__ __align__(16) __nv_bfloat16 g_bfl[4][256 * 128];  // fused lo
__device__ __align__(16) __nv_bfloat16 g_brh[2][128 * 128];  // res W^T hi
__device__ __align__(16) __nv_bfloat16 g_brl[2][128 * 128];  // res lo
__device__ int   g_rowoff[NN + 1];
__device__ int   g_cursor[NN];
__device__ int   g_csrc[NE];
__device__ float g_pool[NG * NH];
__device__ float g_cnt[NG];

__device__ __forceinline__ float lrelu(float v) { return v > 0.f ? v : 0.2f * v; }

__device__ __forceinline__ uint32_t smem_u32(const void* p) {
    uint32_t a;
    asm("{ .reg .u64 t; cvta.to.shared.u64 t, %1; cvt.u32.u64 %0, t; }" : "=r"(a) : "l"(p));
    return a;
}
__device__ __forceinline__ void ldsm4(uint32_t* r, uint32_t addr) {
    asm volatile("ldmatrix.sync.aligned.m8n8.x4.shared.b16 {%0,%1,%2,%3}, [%4];"
                 : "=r"(r[0]), "=r"(r[1]), "=r"(r[2]), "=r"(r[3]) : "r"(addr));
}
__device__ __forceinline__ void mma_bf16(float* d, const uint32_t* a, uint32_t b0, uint32_t b1) {
    asm volatile(
        "mma.sync.aligned.m16n8k16.row.col.f32.bf16.bf16.f32 "
        "{%0,%1,%2,%3}, {%4,%5,%6,%7}, {%8,%9}, {%0,%1,%2,%3};"
        : "+f"(d[0]), "+f"(d[1]), "+f"(d[2]), "+f"(d[3])
        : "r"(a[0]), "r"(a[1]), "r"(a[2]), "r"(a[3]), "r"(b0), "r"(b1));
}
__device__ __forceinline__ void cp16(uint32_t dst, const void* src) {
    asm volatile("cp.async.cg.shared.global [%0], [%1], 16;" :: "r"(dst), "l"(src));
}
#define CP_COMMIT_WAIT() \
    asm volatile("cp.async.commit_group;\ncp.async.wait_group 0;" ::: "memory")

// ---------------- CSR build ----------------
__global__ void hist_kernel(const int* __restrict__ dst, int* __restrict__ cnt) {
    int i = blockIdx.x * blockDim.x + threadIdx.x;
    if (i < NE) atomicAdd(&cnt[dst[i]], 1);
}
__global__ void scan_kernel(const int* __restrict__ cnt, int* __restrict__ rowoff,
                            int* __restrict__ cursor) {
    __shared__ int s_carry;
    __shared__ int warpsums[32];
    int lane = threadIdx.x & 31, wid = threadIdx.x >> 5;
    if (threadIdx.x == 0) s_carry = 0;
    __syncthreads();
    for (int base = 0; base < NN; base += 1024) {
        int i = base + (int)threadIdx.x;
        int v = (i < NN) ? cnt[i] : 0;
        int x = v;
#pragma unroll
        for (int o = 1; o < 32; o <<= 1) {
            int y = __shfl_up_sync(0xFFFFFFFFu, x, o);
            if (lane >= o) x += y;
        }
        if (lane == 31) warpsums[wid] = x;
        __syncthreads();
        if (wid == 0) {
            int w = warpsums[lane];
#pragma unroll
            for (int o = 1; o < 32; o <<= 1) {
                int y = __shfl_up_sync(0xFFFFFFFFu, w, o);
                if (lane >= o) w += y;
            }
            warpsums[lane] = w;
        }
        __syncthreads();
        int incl = x + (wid > 0 ? warpsums[wid - 1] : 0) + s_carry;
        int excl = incl - v;
        if (i < NN) { rowoff[i] = excl; cursor[i] = excl; }
        __syncthreads();
        if (threadIdx.x == 1023) s_carry = incl;
        __syncthreads();
    }
    if (threadIdx.x == 0) rowoff[NN] = NE;
}
__global__ void fill_kernel(const int* __restrict__ src, const int* __restrict__ dst,
                            int* __restrict__ cursor, int* __restrict__ csrc) {
    int i = blockIdx.x * blockDim.x + threadIdx.x;
    if (i >= NE) return;
    int pos = atomicAdd(&cursor[dst[i]], 1);
    csrc[pos] = src[i];
}

// ---------------- weight pack+split (transposed to [N,K]) ----------------
__global__ void pack_fused_kernel(const float* __restrict__ Wl, const float* __restrict__ Wr,
                                  __nv_bfloat16* __restrict__ bh, __nv_bfloat16* __restrict__ bl,
                                  int K) {
    int i = blockIdx.x * blockDim.x + threadIdx.x;
    if (i >= 256 * K) return;
    int n = i / K, k = i % K;
    float v = (n < 128) ? Wl[k * 128 + n] : Wr[k * 128 + (n - 128)];
    __nv_bfloat16 h = __float2bfloat16(v);
    bh[i] = h;
    bl[i] = __float2bfloat16(v - __bfloat162float(h));
}
__global__ void pack_res_kernel(const float* __restrict__ W, __nv_bfloat16* __restrict__ bh,
                                __nv_bfloat16* __restrict__ bl) {
    int i = blockIdx.x * blockDim.x + threadIdx.x;
    if (i >= 128 * 128) return;
    int n = i >> 7, k = i & 127;
    float v = W[k * 128 + n];
    __nv_bfloat16 h = __float2bfloat16(v);
    bh[i] = h;
    bl[i] = __float2bfloat16(v - __bfloat162float(h));
}
__global__ void split_x_kernel(const float* __restrict__ x, __nv_bfloat16* __restrict__ hi,
                               __nv_bfloat16* __restrict__ lo) {
    int i = blockIdx.x * blockDim.x + threadIdx.x;
    if (i >= NN * NIN) return;
    float f = x[i];
    __nv_bfloat16 h = __float2bfloat16(f);
    hi[i] = h;
    lo[i] = __float2bfloat16(f - __bfloat162float(h));
}

// ---------------- tensor-core GEMM via mma.sync (bf16 3-term split) ----------------
// MODE 0 (fused, NT=256): cols 0-127 -> bf16 xl (ohi), cols 128-255 -> fp32 xr (outF)
// MODE 1 (res,   NT=128): bias + add, fp32 out + hi/lo split
template <int K, int MODE>
__global__ void __launch_bounds__(256, 2) mm_gemm(
    const __nv_bfloat16* __restrict__ Ah, const __nv_bfloat16* __restrict__ Al,
    const __nv_bfloat16* __restrict__ Bh, const __nv_bfloat16* __restrict__ Bl,
    const float* __restrict__ bias, const float* __restrict__ add, float* __restrict__ outF,
    __nv_bfloat16* __restrict__ ohi, __nv_bfloat16* __restrict__ olo) {
    extern __shared__ char smem[];
    constexpr int KC = 64, ST = 72;
    constexpr int TB = 128 * ST;
    __nv_bfloat16* sAh = (__nv_bfloat16*)smem;
    __nv_bfloat16* sAl = sAh + TB;
    __nv_bfloat16* sBh = sAl + TB;
    __nv_bfloat16* sBl = sBh + TB;
    int tid = threadIdx.x, lane = tid & 31, wid = tid >> 5;
    int warp_m = wid & 3, warp_n = wid >> 2;
    int bm = blockIdx.x * 128, bn = blockIdx.y * 128;
    const __nv_bfloat16* Bh_blk = Bh + (size_t)bn * K;
    const __nv_bfloat16* Bl_blk = Bl + (size_t)bn * K;

    float acc[2][8][4];
#pragma unroll
    for (int i = 0; i < 2; i++)
#pragma unroll
        for (int j = 0; j < 8; j++)
#pragma unroll
            for (int q = 0; q < 4; q++) acc[i][j][q] = 0.f;

    int g = lane >> 3, lr = lane & 7;
    int frow = lr + ((g & 1) << 3);
    int fcol = (g >> 1) << 3;

    for (int kc = 0; kc < K; kc += KC) {
        if (kc) __syncthreads();
#pragma unroll
        for (int idx = tid; idx < 1024; idx += 256) {
            int r = idx >> 3, c = (idx & 7) * 8;
            cp16(smem_u32(&sAh[r * ST + c]), &Ah[(size_t)(bm + r) * K + kc + c]);
            cp16(smem_u32(&sAl[r * ST + c]), &Al[(size_t)(bm + r) * K + kc + c]);
            cp16(smem_u32(&sBh[r * ST + c]), &Bh_blk[(size_t)r * K + kc + c]);
            cp16(smem_u32(&sBl[r * ST + c]), &Bl_blk[(size_t)r * K + kc + c]);
        }
        CP_COMMIT_WAIT();
        __syncthreads();
#pragma unroll
        for (int ks = 0; ks < 4; ks++) {
            int kcol = ks * 16 + fcol;
            uint32_t ah0[4], ah1[4], al0[4], al1[4];
            ldsm4(ah0, smem_u32(&sAh[(warp_m * 32 + frow) * ST + kcol]));
            ldsm4(ah1, smem_u32(&sAh[(warp_m * 32 + 16 + frow) * ST + kcol]));
            ldsm4(al0, smem_u32(&sAl[(warp_m * 32 + frow) * ST + kcol]));
            ldsm4(al1, smem_u32(&sAl[(warp_m * 32 + 16 + frow) * ST + kcol]));
#pragma unroll
            for (int tp = 0; tp < 4; tp++) {
                int brow = warp_n * 64 + tp * 16 + frow;
                uint32_t bh[4], bl[4];
                ldsm4(bh, smem_u32(&sBh[brow * ST + kcol]));
                ldsm4(bl, smem_u32(&sBl[brow * ST + kcol]));
                mma_bf16(acc[0][tp * 2 + 0], ah0, bh[0], bh[2]);
                mma_bf16(acc[0][tp * 2 + 1], ah0, bh[1], bh[3]);
                mma_bf16(acc[1][tp * 2 + 0], ah1, bh[0], bh[2]);
                mma_bf16(acc[1][tp * 2 + 1], ah1, bh[1], bh[3]);
                mma_bf16(acc[0][tp * 2 + 0], ah0, bl[0], bl[2]);
                mma_bf16(acc[0][tp * 2 + 1], ah0, bl[1], bl[3]);
                mma_bf16(acc[1][tp * 2 + 0], ah1, bl[0], bl[2]);
                mma_bf16(acc[1][tp * 2 + 1], ah1, bl[1], bl[3]);
                mma_bf16(acc[0][tp * 2 + 0], al0, bh[0], bh[2]);
                mma_bf16(acc[0][tp * 2 + 1], al0, bh[1], bh[3]);
                mma_bf16(acc[1][tp * 2 + 0], al1, bh[0], bh[2]);
                mma_bf16(acc[1][tp * 2 + 1], al1, bh[1], bh[3]);
            }
        }
    }

    int lr4 = lane >> 2, lc = (lane & 3) * 2;
#pragma unroll
    for (int tm = 0; tm < 2; tm++) {
#pragma unroll
        for (int half = 0; half < 2; half++) {
            int row = bm + warp_m * 32 + tm * 16 + lr4 + half * 8;
#pragma unroll
            for (int tn = 0; tn < 8; tn++) {
                int gc = bn + warp_n * 64 + tn * 8 + lc;
                float v0 = acc[tm][tn][half * 2 + 0];
                float v1 = acc[tm][tn][half * 2 + 1];
                if (MODE == 0) {
                    if (gc < 128) {  // xl half -> bf16
                        __nv_bfloat162 hv = __floats2bfloat162_rn(v0, v1);
                        *(uint32_t*)&ohi[(size_t)row * NH + gc] = *(uint32_t*)&hv;
                    } else {         // xr half -> fp32
                        *(float2*)&outF[(size_t)row * NH + (gc - 128)] = make_float2(v0, v1);
                    }
                } else {
                    v0 += bias[gc];
                    v1 += bias[gc + 1];
                    float2 a2 = *(const float2*)&add[(size_t)row * NH + gc];
                    v0 += a2.x;
                    v1 += a2.y;
                    *(float2*)&outF[(size_t)row * NH + gc] = make_float2(v0, v1);
                    __nv_bfloat162 hv = __floats2bfloat162_rn(v0, v1);
                    float l0 = v0 - __bfloat162float(hv.x);
                    float l1 = v1 - __bfloat162float(hv.y);
                    __nv_bfloat162 lv = __floats2bfloat162_rn(l0, l1);
                    *(uint32_t*)&ohi[(size_t)row * NH + gc] = *(uint32_t*)&hv;
                    *(uint32_t*)&olo[(size_t)row * NH + gc] = *(uint32_t*)&lv;
                }
            }
        }
    }
}

// ---------------- fused GAT aggregation: warp per node, online softmax, bf16 gathers ----------------
__device__ __forceinline__ void ol_merge(float& m, float& s, float4& a, float e,
                                         const float4& x) {
    float nm = fmaxf(m, e);
    float fo = __expf(m - nm), fe = __expf(e - nm);
    s = s * fo + fe;
    a.x = a.x * fo + fe * x.x;
    a.y = a.y * fo + fe * x.y;
    a.z = a.z * fo + fe * x.z;
    a.w = a.w * fo + fe * x.w;
    m = nm;
}
__device__ __forceinline__ float4 bf2f4(uint2 u) {
    __nv_bfloat162 p0 = *(__nv_bfloat162*)&u.x;
    __nv_bfloat162 p1 = *(__nv_bfloat162*)&u.y;
    float4 r;
    r.x = __bfloat162float(p0.x);
    r.y = __bfloat162float(p0.y);
    r.z = __bfloat162float(p1.x);
    r.w = __bfloat162float(p1.y);
    return r;
}
__global__ void gat_agg_kernel(const __nv_bfloat16* __restrict__ xlb,
                               const float* __restrict__ xr, const int* __restrict__ rowoff,
                               const int* __restrict__ csrc, const float* __restrict__ att,
                               const float* __restrict__ bias, float* __restrict__ outF,
                               __nv_bfloat16* __restrict__ ohi, __nv_bfloat16* __restrict__ olo,
                               const int* __restrict__ batch, float* __restrict__ pool,
                               float* __restrict__ cnt, float scale) {
    int node = blockIdx.x * 8 + (threadIdx.x >> 5);
    if (node >= NN) return;
    int lane = threadIdx.x & 31;
    const uint2* XB = (const uint2*)xlb;  // row = 32 uint2 (4 bf16 per lane)
    float4 xr4 = ((const float4*)xr)[(size_t)node * 32 + lane];
    float4 t = ((const float4*)att)[lane];
    int k = rowoff[node];
    int end = rowoff[node + 1];
    float m0 = -3.0e38f, s0 = 0.f, m1 = -3.0e38f, s1 = 0.f;
    float4 a0 = {0.f, 0.f, 0.f, 0.f}, a1 = {0.f, 0.f, 0.f, 0.f};
    for (; k + 4 <= end; k += 4) {
        int sa = csrc[k], sb = csrc[k + 1], sc = csrc[k + 2], sd = csrc[k + 3];
        float4 xA = bf2f4(XB[(size_t)sa * 32 + lane]);
        float4 xB = bf2f4(XB[(size_t)sb * 32 + lane]);
        float4 xC = bf2f4(XB[(size_t)sc * 32 + lane]);
        float4 xD = bf2f4(XB[(size_t)sd * 32 + lane]);
        float eA = lrelu(xA.x + xr4.x) * t.x + lrelu(xA.y + xr4.y) * t.y +
                   lrelu(xA.z + xr4.z) * t.z + lrelu(xA.w + xr4.w) * t.w;
        float eB = lrelu(xB.x + xr4.x) * t.x + lrelu(xB.y + xr4.y) * t.y +
                   lrelu(xB.z + xr4.z) * t.z + lrelu(xB.w + xr4.w) * t.w;
        float eC = lrelu(xC.x + xr4.x) * t.x + lrelu(xC.y + xr4.y) * t.y +
                   lrelu(xC.z + xr4.z) * t.z + lrelu(xC.w + xr4.w) * t.w;
        float eD = lrelu(xD.x + xr4.x) * t.x + lrelu(xD.y + xr4.y) * t.y +
                   lrelu(xD.z + xr4.z) * t.z + lrelu(xD.w + xr4.w) * t.w;
#pragma unroll
        for (int o = 16; o; o >>= 1) {
            eA += __shfl_xor_sync(0xFFFFFFFFu, eA, o);
            eB += __shfl_xor_sync(0xFFFFFFFFu, eB, o);
            eC += __shfl_xor_sync(0xFFFFFFFFu, eC, o);
            eD += __shfl_xor_sync(0xFFFFFFFFu, eD, o);
        }
        ol_merge(m0, s0, a0, eA, xA);
        ol_merge(m1, s1, a1, eB, xB);
        ol_merge(m0, s0, a0, eC, xC);
        ol_merge(m1, s1, a1, eD, xD);
    }
    for (; k < end; k++) {
        int sa = csrc[k];
        float4 xA = bf2f4(XB[(size_t)sa * 32 + lane]);
        float eA = lrelu(xA.x + xr4.x) * t.x + lrelu(xA.y + xr4.y) * t.y +
                   lrelu(xA.z + xr4.z) * t.z + lrelu(xA.w + xr4.w) * t.w;
#pragma unroll
        for (int o = 16; o; o >>= 1) eA += __shfl_xor_sync(0xFFFFFFFFu, eA, o);
        ol_merge(m0, s0, a0, eA, xA);
    }
    float m = fmaxf(m0, m1);
    float f0 = __expf(m0 - m), f1 = __expf(m1 - m);
    float s = s0 * f0 + s1 * f1;
    float inv = 1.f / (s + 1e-16f);
    float4 b4 = ((const float4*)bias)[lane];
    float4 r;
    r.x = fmaxf((a0.x * f0 + a1.x * f1) * inv + b4.x, 0.f) * scale;
    r.y = fmaxf((a0.y * f0 + a1.y * f1) * inv + b4.y, 0.f) * scale;
    r.z = fmaxf((a0.z * f0 + a1.z * f1) * inv + b4.z, 0.f) * scale;
    r.w = fmaxf((a0.w * f0 + a1.w * f1) * inv + b4.w, 0.f) * scale;
    if (outF) ((float4*)outF)[(size_t)node * 32 + lane] = r;
    if (ohi) {
        __nv_bfloat162 h01 = __floats2bfloat162_rn(r.x, r.y);
        __nv_bfloat162 h23 = __floats2bfloat162_rn(r.z, r.w);
        float lx = r.x - __bfloat162float(h01.x);
        float ly = r.y - __bfloat162float(h01.y);
        float lz = r.z - __bfloat162float(h23.x);
        float lw = r.w - __bfloat162float(h23.y);
        __nv_bfloat162 l01 = __floats2bfloat162_rn(lx, ly);
        __nv_bfloat162 l23 = __floats2bfloat162_rn(lz, lw);
        uint2 uh, ul;
        uh.x = *(uint32_t*)&h01; uh.y = *(uint32_t*)&h23;
        ul.x = *(uint32_t*)&l01; ul.y = *(uint32_t*)&l23;
        ((uint2*)ohi)[(size_t)node * 32 + lane] = uh;
        ((uint2*)olo)[(size_t)node * 32 + lane] = ul;
    }
    if (pool) {
        int gidx = batch[node];
        atomicAdd((float4*)(pool + (size_t)gidx * NH + lane * 4), r);
        if (lane == 0) atomicAdd(&cnt[gidx], 1.f);
    }
}

// ---------------- final MLP + layernorm ----------------
__global__ void mlp_kernel(const float* __restrict__ pool, const float* __restrict__ cnt,
                           const float* __restrict__ w1, const float* __restrict__ b1,
                           const float* __restrict__ w2, const float* __restrict__ b2,
                           const float* __restrict__ lng, const float* __restrict__ lnb,
                           float* __restrict__ out) {
    int g = blockIdx.x;
    int t = threadIdx.x;
    __shared__ float p[NH];
    __shared__ float z1[2 * NH];
    __shared__ float rs[8], rq[8];
    float inv = 1.f / fmaxf(cnt[g], 1.f);
    if (t < NH) p[t] = pool[g * NH + t] * inv;
    __syncthreads();
    float a = 0.f;
#pragma unroll 8
    for (int k = 0; k < NH; k++) a += p[k] * w1[k * (2 * NH) + t];
    z1[t] = fmaxf(a + b1[t], 0.f);
    __syncthreads();
    float z = 0.f;
#pragma unroll 8
    for (int k = 0; k < 2 * NH; k++) z += z1[k] * w2[k * NO + t];
    z += b2[t];
    float v = z, v2 = z * z;
#pragma unroll
    for (int o = 16; o; o >>= 1) {
        v += __shfl_xor_sync(0xFFFFFFFFu, v, o);
        v2 += __shfl_xor_sync(0xFFFFFFFFu, v2, o);
    }
    int wid = t >> 5, lane = t & 31;
    if (lane == 0) { rs[wid] = v; rq[wid] = v2; }
    __syncthreads();
    if (wid == 0) {
        float sv = lane < 8 ? rs[lane] : 0.f;
        float sq = lane < 8 ? rq[lane] : 0.f;
#pragma unroll
        for (int o = 4; o; o >>= 1) {
            sv += __shfl_xor_sync(0xFFFFFFFFu, sv, o);
            sq += __shfl_xor_sync(0xFFFFFFFFu, sq, o);
        }
        if (lane == 0) { rs[0] = sv; rq[0] = sq; }
    }
    __syncthreads();
    float mu = rs[0] * (1.f / NO);
    float var = rq[0] * (1.f / NO) - mu * mu;
    out[g * NO + t] = (z - mu) * rsqrtf(var + 1e-5f) * lng[t] + lnb[t];
}

// ---------------- host ----------------
extern "C" void kernel_launch(void* const* d_in, const int* in_sizes, int n_in,
                              void* d_out, int out_size) {
    const float* x = (const float*)d_in[0];
    const int* ei = (const int*)d_in[1];
    const int* src = ei;
    const int* dst = ei + NE;
    const int* batch = (const int*)d_in[2];
    const float* Wl[4] = {(const float*)d_in[3], (const float*)d_in[7],
                          (const float*)d_in[11], (const float*)d_in[15]};
    const float* Wr[4] = {(const float*)d_in[4], (const float*)d_in[8],
                          (const float*)d_in[12], (const float*)d_in[16]};
    const float* att[4] = {(const float*)d_in[5], (const float*)d_in[9],
                           (const float*)d_in[13], (const float*)d_in[17]};
    const float* bb[4] = {(const float*)d_in[6], (const float*)d_in[10],
                          (const float*)d_in[14], (const float*)d_in[18]};
    const float* res_w0 = (const float*)d_in[19];
    const float* res_b0 = (const float*)d_in[20];
    const float* res_w2 = (const float*)d_in[21];
    const float* res_b2 = (const float*)d_in[22];
    const float* mh1_w = (const float*)d_in[23];
    const float* mh1_b = (const float*)d_in[24];
    const float* mh2_w = (const float*)d_in[25];
    const float* mh2_b = (const float*)d_in[26];
    const float* ln_g = (const float*)d_in[27];
    const float* ln_b = (const float*)d_in[28];
    float* out = (float*)d_out;

    float *xr, *h0, *h1, *pool, *cnt;
    __nv_bfloat16 *xlb, *h0hi, *h0lo, *h1hi, *h1lo, *xhi, *xlo, *bfh, *bfl, *brh, *brl;
    int *rowoff, *cursor, *csrc;
    cudaGetSymbolAddress((void**)&xlb, g_xlb);
    cudaGetSymbolAddress((void**)&xr, g_xr);
    cudaGetSymbolAddress((void**)&h0, g_h0);
    cudaGetSymbolAddress((void**)&h1, g_h1);
    cudaGetSymbolAddress((void**)&h0hi, g_h0hi);
    cudaGetSymbolAddress((void**)&h0lo, g_h0lo);
    cudaGetSymbolAddress((void**)&h1hi, g_h1hi);
    cudaGetSymbolAddress((void**)&h1lo, g_h1lo);
    cudaGetSymbolAddress((void**)&xhi, g_xhi);
    cudaGetSymbolAddress((void**)&xlo, g_xlo);
    cudaGetSymbolAddress((void**)&bfh, g_bfh);
    cudaGetSymbolAddress((void**)&bfl, g_bfl);
    cudaGetSymbolAddress((void**)&brh, g_brh);
    cudaGetSymbolAddress((void**)&brl, g_brl);
    cudaGetSymbolAddress((void**)&rowoff, g_rowoff);
    cudaGetSymbolAddress((void**)&cursor, g_cursor);
    cudaGetSymbolAddress((void**)&csrc, g_csrc);
    cudaGetSymbolAddress((void**)&pool, g_pool);
    cudaGetSymbolAddress((void**)&cnt, g_cnt);

    // ---- smem attrs (idempotent) ----
    const int SMEM_MM = 4 * 128 * 72 * 2;  // 73728
    cudaFuncSetAttribute(mm_gemm<64, 0>, cudaFuncAttributeMaxDynamicSharedMemorySize, SMEM_MM);
    cudaFuncSetAttribute(mm_gemm<128, 0>, cudaFuncAttributeMaxDynamicSharedMemorySize, SMEM_MM);
    cudaFuncSetAttribute(mm_gemm<128, 1>, cudaFuncAttributeMaxDynamicSharedMemorySize, SMEM_MM);

    const int Kd[4] = {NIN, NH, NH, NH};
    const int GT = NP / 128;  // 313
    dim3 gf(GT, 2), gr(GT, 1);
    const int AGG_BLK = (NN + 7) / 8;

    // ---- fork a side stream for the independent prologue chain ----
    cudaStream_t s2;
    cudaEvent_t evF, evJ;
    cudaStreamCreateWithFlags(&s2, cudaStreamNonBlocking);
    cudaEventCreateWithFlags(&evF, cudaEventDisableTiming);
    cudaEventCreateWithFlags(&evJ, cudaEventDisableTiming);
    cudaEventRecord(evF, 0);
    cudaStreamWaitEvent(s2, evF, 0);

    // s2: CSR build + pool init + packs for layers 2-4 and res
    cudaMemsetAsync(cursor, 0, NN * sizeof(int), s2);
    hist_kernel<<<(NE + 255) / 256, 256, 0, s2>>>(dst, cursor);
    scan_kernel<<<1, 1024, 0, s2>>>(cursor, rowoff, cursor);
    fill_kernel<<<(NE + 255) / 256, 256, 0, s2>>>(src, dst, cursor, csrc);
    cudaMemsetAsync(pool, 0, NG * NH * sizeof(float), s2);
    cudaMemsetAsync(cnt, 0, NG * sizeof(float), s2);
    for (int li = 1; li < 4; li++) {
        pack_fused_kernel<<<(256 * Kd[li] + 255) / 256, 256, 0, s2>>>(
            Wl[li], Wr[li], bfh + (size_t)li * 256 * 128, bfl + (size_t)li * 256 * 128, Kd[li]);
    }
    pack_res_kernel<<<(128 * 128 + 255) / 256, 256, 0, s2>>>(res_w0, brh, brl);
    pack_res_kernel<<<(128 * 128 + 255) / 256, 256, 0, s2>>>(res_w2, brh + 128 * 128,
                                                             brl + 128 * 128);
    cudaEventRecord(evJ, s2);

    // main stream: layer-1 dependencies + layer-1 GEMM (overlaps with s2)
    pack_fused_kernel<<<(256 * Kd[0] + 255) / 256, 256>>>(Wl[0], Wr[0], bfh, bfl, Kd[0]);
    split_x_kernel<<<(NN * NIN + 255) / 256, 256>>>(x, xhi, xlo);
    mm_gemm<64, 0><<<gf, 256, SMEM_MM>>>(xhi, xlo, bfh, bfl, nullptr, nullptr, xr, xlb, nullptr);

    // join: everything after needs CSR / packed weights
    cudaStreamWaitEvent(0, evJ, 0);

    // layer 1 agg + residual
    gat_agg_kernel<<<AGG_BLK, 256>>>(xlb, xr, rowoff, csrc, att[0], bb[0], h0, h0hi, h0lo,
                                     nullptr, nullptr, nullptr, 1.f);
    mm_gemm<128, 1><<<gr, 256, SMEM_MM>>>(h0hi, h0lo, brh, brl, res_b0, h0, h1, h1hi, h1lo);
    // layer 2 (agg out fp32 unused -> skip)
    mm_gemm<128, 0><<<gf, 256, SMEM_MM>>>(h1hi, h1lo, bfh + 256 * 128, bfl + 256 * 128, nullptr,
                                          nullptr, xr, xlb, nullptr);
    gat_agg_kernel<<<AGG_BLK, 256>>>(xlb, xr, rowoff, csrc, att[1], bb[1], nullptr, h0hi, h0lo,
                                     nullptr, nullptr, nullptr, 2.f);
    // layer 3
    mm_gemm<128, 0><<<gf, 256, SMEM_MM>>>(h0hi, h0lo, bfh + 2 * 256 * 128, bfl + 2 * 256 * 128,
                                          nullptr, nullptr, xr, xlb, nullptr);
    gat_agg_kernel<<<AGG_BLK, 256>>>(xlb, xr, rowoff, csrc, att[2], bb[2], h1, h1hi, h1lo,
                                     nullptr, nullptr, nullptr, 1.f);
    mm_gemm<128, 1><<<gr, 256, SMEM_MM>>>(h1hi, h1lo, brh + 128 * 128, brl + 128 * 128, res_b2,
                                          h1, h0, h0hi, h0lo);
    // layer 4 (agg fuses pooling; no h/hi/lo outputs)
    mm_gemm<128, 0><<<gf, 256, SMEM_MM>>>(h0hi, h0lo, bfh + 3 * 256 * 128, bfl + 3 * 256 * 128,
                                          nullptr, nullptr, xr, xlb, nullptr);
    gat_agg_kernel<<<AGG_BLK, 256>>>(xlb, xr, rowoff, csrc, att[3], bb[3], nullptr, nullptr,
                                     nullptr, batch, pool, cnt, 2.f);

    // MLP + layernorm
    mlp_kernel<<<NG, 256>>>(pool, cnt, mh1_w, mh1_b, mh2_w, mh2_b, ln_g, ln_b, out);
}

// round 9
// speedup vs baseline: 2.7813x; 1.1316x over previous
#include <cuda_runtime.h>
#include <cuda_bf16.h>
#include <math.h>
#include <stdint.h>

#define NN 40000
#define NP 40064          // padded rows (313 * 128)
#define NE 640000
#define NG 128
#define NIN 64
#define NH 128
#define NO 256

// ---------------- scratch (device globals; no allocation allowed) ----------------
__device__ __align__(16) __nv_bfloat16 g_xlb[NP * NH];   // xl in bf16 (gathered per edge)
__device__ float g_xr[NP * NH];                          // xr in fp32 (read per node)
__device__ __align__(16) __nv_bfloat16 g_hhi[NP * NH];   // agg output hi
__device__ __align__(16) __nv_bfloat16 g_hlo[NP * NH];   // agg output lo
__device__ __align__(16) __nv_bfloat16 g_xhi[NP * NIN];
__device__ __align__(16) __nv_bfloat16 g_xlo[NP * NIN];
__device__ __align__(16) __nv_bfloat16 g_bfh[4][256 * 128];  // per-layer effective [N,K] hi
__device__ __align__(16) __nv_bfloat16 g_bfl[4][256 * 128];  // lo
__device__ float g_beff[2][256];                             // folded residual bias terms
__device__ int   g_rowoff[NN + 1];
__device__ int   g_cursor[NN];
__device__ int   g_csrc[NE];
__device__ float g_pool[NG * NH];
__device__ float g_cnt[NG];

__device__ __forceinline__ float lrelu(float v) { return v > 0.f ? v : 0.2f * v; }

__device__ __forceinline__ uint32_t smem_u32(const void* p) {
    uint32_t a;
    asm("{ .reg .u64 t; cvta.to.shared.u64 t, %1; cvt.u32.u64 %0, t; }" : "=r"(a) : "l"(p));
    return a;
}
__device__ __forceinline__ void ldsm4(uint32_t* r, uint32_t addr) {
    asm volatile("ldmatrix.sync.aligned.m8n8.x4.shared.b16 {%0,%1,%2,%3}, [%4];"
                 : "=r"(r[0]), "=r"(r[1]), "=r"(r[2]), "=r"(r[3]) : "r"(addr));
}
__device__ __forceinline__ void mma_bf16(float* d, const uint32_t* a, uint32_t b0, uint32_t b1) {
    asm volatile(
        "mma.sync.aligned.m16n8k16.row.col.f32.bf16.bf16.f32 "
        "{%0,%1,%2,%3}, {%4,%5,%6,%7}, {%8,%9}, {%0,%1,%2,%3};"
        : "+f"(d[0]), "+f"(d[1]), "+f"(d[2]), "+f"(d[3])
        : "r"(a[0]), "r"(a[1]), "r"(a[2]), "r"(a[3]), "r"(b0), "r"(b1));
}
__device__ __forceinline__ void cp16(uint32_t dst, const void* src) {
    asm volatile("cp.async.cg.shared.global [%0], [%1], 16;" :: "r"(dst), "l"(src));
}
#define CP_COMMIT_WAIT() \
    asm volatile("cp.async.commit_group;\ncp.async.wait_group 0;" ::: "memory")

// ---------------- CSR build ----------------
__global__ void hist_kernel(const int* __restrict__ dst, int* __restrict__ cnt) {
    int i = blockIdx.x * blockDim.x + threadIdx.x;
    if (i < NE) atomicAdd(&cnt[dst[i]], 1);
}
__global__ void scan_kernel(const int* __restrict__ cnt, int* __restrict__ rowoff,
                            int* __restrict__ cursor) {
    __shared__ int s_carry;
    __shared__ int warpsums[32];
    int lane = threadIdx.x & 31, wid = threadIdx.x >> 5;
    if (threadIdx.x == 0) s_carry = 0;
    __syncthreads();
    for (int base = 0; base < NN; base += 1024) {
        int i = base + (int)threadIdx.x;
        int v = (i < NN) ? cnt[i] : 0;
        int x = v;
#pragma unroll
        for (int o = 1; o < 32; o <<= 1) {
            int y = __shfl_up_sync(0xFFFFFFFFu, x, o);
            if (lane >= o) x += y;
        }
        if (lane == 31) warpsums[wid] = x;
        __syncthreads();
        if (wid == 0) {
            int w = warpsums[lane];
#pragma unroll
            for (int o = 1; o < 32; o <<= 1) {
                int y = __shfl_up_sync(0xFFFFFFFFu, w, o);
                if (lane >= o) w += y;
            }
            warpsums[lane] = w;
        }
        __syncthreads();
        int incl = x + (wid > 0 ? warpsums[wid - 1] : 0) + s_carry;
        int excl = incl - v;
        if (i < NN) { rowoff[i] = excl; cursor[i] = excl; }
        __syncthreads();
        if (threadIdx.x == 1023) s_carry = incl;
        __syncthreads();
    }
    if (threadIdx.x == 0) rowoff[NN] = NE;
}
__global__ void fill_kernel(const int* __restrict__ src, const int* __restrict__ dst,
                            int* __restrict__ cursor, int* __restrict__ csrc) {
    int i = blockIdx.x * blockDim.x + threadIdx.x;
    if (i >= NE) return;
    int pos = atomicAdd(&cursor[dst[i]], 1);
    csrc[pos] = src[i];
}

// ---------------- weight pack+split (transposed to [N,K]) ----------------
__global__ void pack_fused_kernel(const float* __restrict__ Wl, const float* __restrict__ Wr,
                                  __nv_bfloat16* __restrict__ bh, __nv_bfloat16* __restrict__ bl,
                                  int K) {
    int i = blockIdx.x * blockDim.x + threadIdx.x;
    if (i >= 256 * K) return;
    int n = i / K, k = i % K;
    float v = (n < 128) ? Wl[k * 128 + n] : Wr[k * 128 + (n - 128)];
    __nv_bfloat16 h = __float2bfloat16(v);
    bh[i] = h;
    bl[i] = __float2bfloat16(v - __bfloat162float(h));
}
// Weff = (res_w + I) @ [Wl|Wr], stored [n*128 + k] split hi/lo. grid 128, block 256.
__global__ void weff_kernel(const float* __restrict__ res_w, const float* __restrict__ Wl,
                            const float* __restrict__ Wr, __nv_bfloat16* __restrict__ bh,
                            __nv_bfloat16* __restrict__ bl) {
    __shared__ float a[128];
    int r = blockIdx.x;
    int n = threadIdx.x;
    if (n < 128) {
        float v = res_w[r * 128 + n];
        if (n == r) v += 1.f;
        a[n] = v;
    }
    __syncthreads();
    const float* Wp = (n < 128) ? (Wl + n) : (Wr + (n - 128));
    float s = 0.f;
#pragma unroll 8
    for (int k = 0; k < 128; k++) s += a[k] * Wp[k * 128];
    __nv_bfloat16 h = __float2bfloat16(s);
    bh[n * 128 + r] = h;
    bl[n * 128 + r] = __float2bfloat16(s - __bfloat162float(h));
}
// beff[n] = res_b @ [Wl|Wr] column n. 1 block, 256 threads.
__global__ void beff_kernel(const float* __restrict__ res_b, const float* __restrict__ Wl,
                            const float* __restrict__ Wr, float* __restrict__ beff) {
    __shared__ float b[128];
    int n = threadIdx.x;
    if (n < 128) b[n] = res_b[n];
    __syncthreads();
    const float* Wp = (n < 128) ? (Wl + n) : (Wr + (n - 128));
    float s = 0.f;
#pragma unroll 8
    for (int k = 0; k < 128; k++) s += b[k] * Wp[k * 128];
    beff[n] = s;
}
__global__ void split_x_kernel(const float* __restrict__ x, __nv_bfloat16* __restrict__ hi,
                               __nv_bfloat16* __restrict__ lo) {
    int i = blockIdx.x * blockDim.x + threadIdx.x;
    if (i >= NN * NIN) return;
    float f = x[i];
    __nv_bfloat16 h = __float2bfloat16(f);
    hi[i] = h;
    lo[i] = __float2bfloat16(f - __bfloat162float(h));
}

// ---------------- tensor-core GEMM via mma.sync (bf16 3-term split) ----------------
// out cols 0-127 -> bf16 xl (ohi), cols 128-255 -> fp32 xr (outF); optional fp32 bias[256].
template <int K, bool FBIAS>
__global__ void __launch_bounds__(256, 2) mm_gemm(
    const __nv_bfloat16* __restrict__ Ah, const __nv_bfloat16* __restrict__ Al,
    const __nv_bfloat16* __restrict__ Bh, const __nv_bfloat16* __restrict__ Bl,
    const float* __restrict__ bias, float* __restrict__ outF,
    __nv_bfloat16* __restrict__ ohi) {
    extern __shared__ char smem[];
    constexpr int KC = 64, ST = 72;
    constexpr int TB = 128 * ST;
    __nv_bfloat16* sAh = (__nv_bfloat16*)smem;
    __nv_bfloat16* sAl = sAh + TB;
    __nv_bfloat16* sBh = sAl + TB;
    __nv_bfloat16* sBl = sBh + TB;
    int tid = threadIdx.x, lane = tid & 31, wid = tid >> 5;
    int warp_m = wid & 3, warp_n = wid >> 2;
    int bm = blockIdx.x * 128, bn = blockIdx.y * 128;
    const __nv_bfloat16* Bh_blk = Bh + (size_t)bn * K;
    const __nv_bfloat16* Bl_blk = Bl + (size_t)bn * K;

    float acc[2][8][4];
#pragma unroll
    for (int i = 0; i < 2; i++)
#pragma unroll
        for (int j = 0; j < 8; j++)
#pragma unroll
            for (int q = 0; q < 4; q++) acc[i][j][q] = 0.f;

    int g = lane >> 3, lr = lane & 7;
    int frow = lr + ((g & 1) << 3);
    int fcol = (g >> 1) << 3;

    for (int kc = 0; kc < K; kc += KC) {
        if (kc) __syncthreads();
#pragma unroll
        for (int idx = tid; idx < 1024; idx += 256) {
            int r = idx >> 3, c = (idx & 7) * 8;
            cp16(smem_u32(&sAh[r * ST + c]), &Ah[(size_t)(bm + r) * K + kc + c]);
            cp16(smem_u32(&sAl[r * ST + c]), &Al[(size_t)(bm + r) * K + kc + c]);
            cp16(smem_u32(&sBh[r * ST + c]), &Bh_blk[(size_t)r * K + kc + c]);
            cp16(smem_u32(&sBl[r * ST + c]), &Bl_blk[(size_t)r * K + kc + c]);
        }
        CP_COMMIT_WAIT();
        __syncthreads();
#pragma unroll
        for (int ks = 0; ks < 4; ks++) {
            int kcol = ks * 16 + fcol;
            uint32_t ah0[4], ah1[4], al0[4], al1[4];
            ldsm4(ah0, smem_u32(&sAh[(warp_m * 32 + frow) * ST + kcol]));
            ldsm4(ah1, smem_u32(&sAh[(warp_m * 32 + 16 + frow) * ST + kcol]));
            ldsm4(al0, smem_u32(&sAl[(warp_m * 32 + frow) * ST + kcol]));
            ldsm4(al1, smem_u32(&sAl[(warp_m * 32 + 16 + frow) * ST + kcol]));
#pragma unroll
            for (int tp = 0; tp < 4; tp++) {
                int brow = warp_n * 64 + tp * 16 + frow;
                uint32_t bh[4], bl[4];
                ldsm4(bh, smem_u32(&sBh[brow * ST + kcol]));
                ldsm4(bl, smem_u32(&sBl[brow * ST + kcol]));
                mma_bf16(acc[0][tp * 2 + 0], ah0, bh[0], bh[2]);
                mma_bf16(acc[0][tp * 2 + 1], ah0, bh[1], bh[3]);
                mma_bf16(acc[1][tp * 2 + 0], ah1, bh[0], bh[2]);
                mma_bf16(acc[1][tp * 2 + 1], ah1, bh[1], bh[3]);
                mma_bf16(acc[0][tp * 2 + 0], ah0, bl[0], bl[2]);
                mma_bf16(acc[0][tp * 2 + 1], ah0, bl[1], bl[3]);
                mma_bf16(acc[1][tp * 2 + 0], ah1, bl[0], bl[2]);
                mma_bf16(acc[1][tp * 2 + 1], ah1, bl[1], bl[3]);
                mma_bf16(acc[0][tp * 2 + 0], al0, bh[0], bh[2]);
                mma_bf16(acc[0][tp * 2 + 1], al0, bh[1], bh[3]);
                mma_bf16(acc[1][tp * 2 + 0], al1, bh[0], bh[2]);
                mma_bf16(acc[1][tp * 2 + 1], al1, bh[1], bh[3]);
            }
        }
    }

    int lr4 = lane >> 2, lc = (lane & 3) * 2;
#pragma unroll
    for (int tm = 0; tm < 2; tm++) {
#pragma unroll
        for (int half = 0; half < 2; half++) {
            int row = bm + warp_m * 32 + tm * 16 + lr4 + half * 8;
#pragma unroll
            for (int tn = 0; tn < 8; tn++) {
                int gc = bn + warp_n * 64 + tn * 8 + lc;
                float v0 = acc[tm][tn][half * 2 + 0];
                float v1 = acc[tm][tn][half * 2 + 1];
                if (FBIAS) { v0 += bias[gc]; v1 += bias[gc + 1]; }
                if (gc < 128) {  // xl half -> bf16
                    __nv_bfloat162 hv = __floats2bfloat162_rn(v0, v1);
                    *(uint32_t*)&ohi[(size_t)row * NH + gc] = *(uint32_t*)&hv;
                } else {         // xr half -> fp32
                    *(float2*)&outF[(size_t)row * NH + (gc - 128)] = make_float2(v0, v1);
                }
            }
        }
    }
}

// ---------------- fused GAT aggregation: warp per node, online softmax ----------------
__device__ __forceinline__ void ol_merge(float& m, float& s, float4& a, float e,
                                         const float4& x) {
    float d = e - m;
    float t = __expf(-fabsf(d));
    bool gt = d > 0.f;
    float fo = gt ? t : 1.f;
    float fe = gt ? 1.f : t;
    m = gt ? e : m;
    s = s * fo + fe;
    a.x = a.x * fo + fe * x.x;
    a.y = a.y * fo + fe * x.y;
    a.z = a.z * fo + fe * x.z;
    a.w = a.w * fo + fe * x.w;
}
__device__ __forceinline__ float4 bf2f4(uint2 u) {
    __nv_bfloat162 p0 = *(__nv_bfloat162*)&u.x;
    __nv_bfloat162 p1 = *(__nv_bfloat162*)&u.y;
    float4 r;
    r.x = __bfloat162float(p0.x);
    r.y = __bfloat162float(p0.y);
    r.z = __bfloat162float(p1.x);
    r.w = __bfloat162float(p1.y);
    return r;
}
__global__ void gat_agg_kernel(const __nv_bfloat16* __restrict__ xlb,
                               const float* __restrict__ xr, const int* __restrict__ rowoff,
                               const int* __restrict__ csrc, const float* __restrict__ att,
                               const float* __restrict__ bias,
                               __nv_bfloat16* __restrict__ ohi, __nv_bfloat16* __restrict__ olo,
                               const int* __restrict__ batch, float* __restrict__ pool,
                               float* __restrict__ cnt, float scale) {
    int node = blockIdx.x * 8 + (threadIdx.x >> 5);
    if (node >= NN) return;
    int lane = threadIdx.x & 31;
    const uint2* XB = (const uint2*)xlb;
    float4 xr4 = ((const float4*)xr)[(size_t)node * 32 + lane];
    float4 t = ((const float4*)att)[lane];
    int k = rowoff[node];
    int end = rowoff[node + 1];
    float m0 = -3.0e38f, s0 = 0.f, m1 = -3.0e38f, s1 = 0.f;
    float4 a0 = {0.f, 0.f, 0.f, 0.f}, a1 = {0.f, 0.f, 0.f, 0.f};
    for (; k + 4 <= end; k += 4) {
        int sa = csrc[k], sb = csrc[k + 1], sc = csrc[k + 2], sd = csrc[k + 3];
        float4 xA = bf2f4(XB[(size_t)sa * 32 + lane]);
        float4 xB = bf2f4(XB[(size_t)sb * 32 + lane]);
        float4 xC = bf2f4(XB[(size_t)sc * 32 + lane]);
        float4 xD = bf2f4(XB[(size_t)sd * 32 + lane]);
        float eA = lrelu(xA.x + xr4.x) * t.x + lrelu(xA.y + xr4.y) * t.y +
                   lrelu(xA.z + xr4.z) * t.z + lrelu(xA.w + xr4.w) * t.w;
        float eB = lrelu(xB.x + xr4.x) * t.x + lrelu(xB.y + xr4.y) * t.y +
                   lrelu(xB.z + xr4.z) * t.z + lrelu(xB.w + xr4.w) * t.w;
        float eC = lrelu(xC.x + xr4.x) * t.x + lrelu(xC.y + xr4.y) * t.y +
                   lrelu(xC.z + xr4.z) * t.z + lrelu(xC.w + xr4.w) * t.w;
        float eD = lrelu(xD.x + xr4.x) * t.x + lrelu(xD.y + xr4.y) * t.y +
                   lrelu(xD.z + xr4.z) * t.z + lrelu(xD.w + xr4.w) * t.w;
#pragma unroll
        for (int o = 16; o; o >>= 1) {
            eA += __shfl_xor_sync(0xFFFFFFFFu, eA, o);
            eB += __shfl_xor_sync(0xFFFFFFFFu, eB, o);
            eC += __shfl_xor_sync(0xFFFFFFFFu, eC, o);
            eD += __shfl_xor_sync(0xFFFFFFFFu, eD, o);
        }
        ol_merge(m0, s0, a0, eA, xA);
        ol_merge(m1, s1, a1, eB, xB);
        ol_merge(m0, s0, a0, eC, xC);
        ol_merge(m1, s1, a1, eD, xD);
    }
    for (; k < end; k++) {
        int sa = csrc[k];
        float4 xA = bf2f4(XB[(size_t)sa * 32 + lane]);
        float eA = lrelu(xA.x + xr4.x) * t.x + lrelu(xA.y + xr4.y) * t.y +
                   lrelu(xA.z + xr4.z) * t.z + lrelu(xA.w + xr4.w) * t.w;
#pragma unroll
        for (int o = 16; o; o >>= 1) eA += __shfl_xor_sync(0xFFFFFFFFu, eA, o);
        ol_merge(m0, s0, a0, eA, xA);
    }
    float m = fmaxf(m0, m1);
    float f0 = __expf(m0 - m), f1 = __expf(m1 - m);
    float s = s0 * f0 + s1 * f1;
    float inv = 1.f / (s + 1e-16f);
    float4 b4 = ((const float4*)bias)[lane];
    float4 r;
    r.x = fmaxf((a0.x * f0 + a1.x * f1) * inv + b4.x, 0.f) * scale;
    r.y = fmaxf((a0.y * f0 + a1.y * f1) * inv + b4.y, 0.f) * scale;
    r.z = fmaxf((a0.z * f0 + a1.z * f1) * inv + b4.z, 0.f) * scale;
    r.w = fmaxf((a0.w * f0 + a1.w * f1) * inv + b4.w, 0.f) * scale;
    if (ohi) {
        __nv_bfloat162 h01 = __floats2bfloat162_rn(r.x, r.y);
        __nv_bfloat162 h23 = __floats2bfloat162_rn(r.z, r.w);
        float lx = r.x - __bfloat162float(h01.x);
        float ly = r.y - __bfloat162float(h01.y);
        float lz = r.z - __bfloat162float(h23.x);
        float lw = r.w - __bfloat162float(h23.y);
        __nv_bfloat162 l01 = __floats2bfloat162_rn(lx, ly);
        __nv_bfloat162 l23 = __floats2bfloat162_rn(lz, lw);
        uint2 uh, ul;
        uh.x = *(uint32_t*)&h01; uh.y = *(uint32_t*)&h23;
        ul.x = *(uint32_t*)&l01; ul.y = *(uint32_t*)&l23;
        ((uint2*)ohi)[(size_t)node * 32 + lane] = uh;
        ((uint2*)olo)[(size_t)node * 32 + lane] = ul;
    }
    if (pool) {
        int gidx = batch[node];
        atomicAdd((float4*)(pool + (size_t)gidx * NH + lane * 4), r);
        if (lane == 0) atomicAdd(&cnt[gidx], 1.f);
    }
}

// ---------------- final MLP + layernorm ----------------
__global__ void mlp_kernel(const float* __restrict__ pool, const float* __restrict__ cnt,
                           const float* __restrict__ w1, const float* __restrict__ b1,
                           const float* __restrict__ w2, const float* __restrict__ b2,
                           const float* __restrict__ lng, const float* __restrict__ lnb,
                           float* __restrict__ out) {
    int g = blockIdx.x;
    int t = threadIdx.x;
    __shared__ float p[NH];
    __shared__ float z1[2 * NH];
    __shared__ float rs[8], rq[8];
    float inv = 1.f / fmaxf(cnt[g], 1.f);
    if (t < NH) p[t] = pool[g * NH + t] * inv;
    __syncthreads();
    float a = 0.f;
#pragma unroll 8
    for (int k = 0; k < NH; k++) a += p[k] * w1[k * (2 * NH) + t];
    z1[t] = fmaxf(a + b1[t], 0.f);
    __syncthreads();
    float z = 0.f;
#pragma unroll 8
    for (int k = 0; k < 2 * NH; k++) z += z1[k] * w2[k * NO + t];
    z += b2[t];
    float v = z, v2 = z * z;
#pragma unroll
    for (int o = 16; o; o >>= 1) {
        v += __shfl_xor_sync(0xFFFFFFFFu, v, o);
        v2 += __shfl_xor_sync(0xFFFFFFFFu, v2, o);
    }
    int wid = t >> 5, lane = t & 31;
    if (lane == 0) { rs[wid] = v; rq[wid] = v2; }
    __syncthreads();
    if (wid == 0) {
        float sv = lane < 8 ? rs[lane] : 0.f;
        float sq = lane < 8 ? rq[lane] : 0.f;
#pragma unroll
        for (int o = 4; o; o >>= 1) {
            sv += __shfl_xor_sync(0xFFFFFFFFu, sv, o);
            sq += __shfl_xor_sync(0xFFFFFFFFu, sq, o);
        }
        if (lane == 0) { rs[0] = sv; rq[0] = sq; }
    }
    __syncthreads();
    float mu = rs[0] * (1.f / NO);
    float var = rq[0] * (1.f / NO) - mu * mu;
    out[g * NO + t] = (z - mu) * rsqrtf(var + 1e-5f) * lng[t] + lnb[t];
}

// ---------------- host ----------------
extern "C" void kernel_launch(void* const* d_in, const int* in_sizes, int n_in,
                              void* d_out, int out_size) {
    const float* x = (const float*)d_in[0];
    const int* ei = (const int*)d_in[1];
    const int* src = ei;
    const int* dst = ei + NE;
    const int* batch = (const int*)d_in[2];
    const float* Wl[4] = {(const float*)d_in[3], (const float*)d_in[7],
                          (const float*)d_in[11], (const float*)d_in[15]};
    const float* Wr[4] = {(const float*)d_in[4], (const float*)d_in[8],
                          (const float*)d_in[12], (const float*)d_in[16]};
    const float* att[4] = {(const float*)d_in[5], (const float*)d_in[9],
                           (const float*)d_in[13], (const float*)d_in[17]};
    const float* bb[4] = {(const float*)d_in[6], (const float*)d_in[10],
                          (const float*)d_in[14], (const float*)d_in[18]};
    const float* res_w0 = (const float*)d_in[19];
    const float* res_b0 = (const float*)d_in[20];
    const float* res_w2 = (const float*)d_in[21];
    const float* res_b2 = (const float*)d_in[22];
    const float* mh1_w = (const float*)d_in[23];
    const float* mh1_b = (const float*)d_in[24];
    const float* mh2_w = (const float*)d_in[25];
    const float* mh2_b = (const float*)d_in[26];
    const float* ln_g = (const float*)d_in[27];
    const float* ln_b = (const float*)d_in[28];
    float* out = (float*)d_out;

    float *xr, *pool, *cnt, *beff;
    __nv_bfloat16 *xlb, *hhi, *hlo, *xhi, *xlo, *bfh, *bfl;
    int *rowoff, *cursor, *csrc;
    cudaGetSymbolAddress((void**)&xlb, g_xlb);
    cudaGetSymbolAddress((void**)&xr, g_xr);
    cudaGetSymbolAddress((void**)&hhi, g_hhi);
    cudaGetSymbolAddress((void**)&hlo, g_hlo);
    cudaGetSymbolAddress((void**)&xhi, g_xhi);
    cudaGetSymbolAddress((void**)&xlo, g_xlo);
    cudaGetSymbolAddress((void**)&bfh, g_bfh);
    cudaGetSymbolAddress((void**)&bfl, g_bfl);
    cudaGetSymbolAddress((void**)&beff, g_beff);
    cudaGetSymbolAddress((void**)&rowoff, g_rowoff);
    cudaGetSymbolAddress((void**)&cursor, g_cursor);
    cudaGetSymbolAddress((void**)&csrc, g_csrc);
    cudaGetSymbolAddress((void**)&pool, g_pool);
    cudaGetSymbolAddress((void**)&cnt, g_cnt);

    // ---- smem attrs (idempotent) ----
    const int SMEM_MM = 4 * 128 * 72 * 2;  // 73728
    cudaFuncSetAttribute(mm_gemm<64, false>, cudaFuncAttributeMaxDynamicSharedMemorySize,
                         SMEM_MM);
    cudaFuncSetAttribute(mm_gemm<128, false>, cudaFuncAttributeMaxDynamicSharedMemorySize,
                         SMEM_MM);
    cudaFuncSetAttribute(mm_gemm<128, true>, cudaFuncAttributeMaxDynamicSharedMemorySize,
                         SMEM_MM);

    const int GT = NP / 128;  // 313
    dim3 gf(GT, 2);
    const int AGG_BLK = (NN + 7) / 8;
    const int SLOT = 256 * 128;

    // ---- fork a side stream for the independent prologue chain ----
    cudaStream_t s2;
    cudaEvent_t evF, evJ;
    cudaStreamCreateWithFlags(&s2, cudaStreamNonBlocking);
    cudaEventCreateWithFlags(&evF, cudaEventDisableTiming);
    cudaEventCreateWithFlags(&evJ, cudaEventDisableTiming);
    cudaEventRecord(evF, 0);
    cudaStreamWaitEvent(s2, evF, 0);

    // s2: CSR build + pool init + effective-weight precompute (layers 2..4)
    cudaMemsetAsync(cursor, 0, NN * sizeof(int), s2);
    hist_kernel<<<(NE + 255) / 256, 256, 0, s2>>>(dst, cursor);
    scan_kernel<<<1, 1024, 0, s2>>>(cursor, rowoff, cursor);
    fill_kernel<<<(NE + 255) / 256, 256, 0, s2>>>(src, dst, cursor, csrc);
    cudaMemsetAsync(pool, 0, NG * NH * sizeof(float), s2);
    cudaMemsetAsync(cnt, 0, NG * sizeof(float), s2);
    // slot1 = (res_w0+I)@[Wl2|Wr2]; beff0 = res_b0@[Wl2|Wr2]
    weff_kernel<<<128, 256, 0, s2>>>(res_w0, Wl[1], Wr[1], bfh + SLOT, bfl + SLOT);
    beff_kernel<<<1, 256, 0, s2>>>(res_b0, Wl[1], Wr[1], beff);
    // slot2 = plain [Wl3|Wr3]
    pack_fused_kernel<<<(256 * NH + 255) / 256, 256, 0, s2>>>(Wl[2], Wr[2], bfh + 2 * SLOT,
                                                              bfl + 2 * SLOT, NH);
    // slot3 = (res_w2+I)@[Wl4|Wr4]; beff1 = res_b2@[Wl4|Wr4]
    weff_kernel<<<128, 256, 0, s2>>>(res_w2, Wl[3], Wr[3], bfh + 3 * SLOT, bfl + 3 * SLOT);
    beff_kernel<<<1, 256, 0, s2>>>(res_b2, Wl[3], Wr[3], beff + 256);
    cudaEventRecord(evJ, s2);

    // main stream: layer-1 dependencies + layer-1 GEMM (overlaps with s2)
    pack_fused_kernel<<<(256 * NIN + 255) / 256, 256>>>(Wl[0], Wr[0], bfh, bfl, NIN);
    split_x_kernel<<<(NN * NIN + 255) / 256, 256>>>(x, xhi, xlo);
    mm_gemm<64, false><<<gf, 256, SMEM_MM>>>(xhi, xlo, bfh, bfl, nullptr, xr, xlb);

    // join
    cudaStreamWaitEvent(0, evJ, 0);

    // layer 1 agg (residual folded into layer-2 weights)
    gat_agg_kernel<<<AGG_BLK, 256>>>(xlb, xr, rowoff, csrc, att[0], bb[0], hhi, hlo, nullptr,
                                     nullptr, nullptr, 1.f);
    // layer 2 (effective weights include residual fold + beff bias)
    mm_gemm<128, true><<<gf, 256, SMEM_MM>>>(hhi, hlo, bfh + SLOT, bfl + SLOT, beff, xr, xlb);
    gat_agg_kernel<<<AGG_BLK, 256>>>(xlb, xr, rowoff, csrc, att[1], bb[1], hhi, hlo, nullptr,
                                     nullptr, nullptr, 2.f);
    // layer 3
    mm_gemm<128, false><<<gf, 256, SMEM_MM>>>(hhi, hlo, bfh + 2 * SLOT, bfl + 2 * SLOT, nullptr,
                                              xr, xlb);
    gat_agg_kernel<<<AGG_BLK, 256>>>(xlb, xr, rowoff, csrc, att[2], bb[2], hhi, hlo, nullptr,
                                     nullptr, nullptr, 1.f);
    // layer 4 (residual folded; agg fuses pooling)
    mm_gemm<128, true><<<gf, 256, SMEM_MM>>>(hhi, hlo, bfh + 3 * SLOT, bfl + 3 * SLOT,
                                             beff + 256, xr, xlb);
    gat_agg_kernel<<<AGG_BLK, 256>>>(xlb, xr, rowoff, csrc, att[3], bb[3], nullptr, nullptr,
                                     batch, pool, cnt, 2.f);

    // MLP + layernorm
    mlp_kernel<<<NG, 256>>>(pool, cnt, mh1_w, mh1_b, mh2_w, mh2_b, ln_g, ln_b, out);
}

// round 11
// speedup vs baseline: 3.2365x; 1.1637x over previous
#include <cuda_runtime.h>
#include <cuda_bf16.h>
#include <math.h>
#include <stdint.h>

#define NN 40000
#define NP 40064          // padded rows (313 * 128)
#define NE 640000
#define NG 128
#define NIN 64
#define NH 128
#define NO 256

// ---------------- scratch (device globals; no allocation allowed) ----------------
__device__ __align__(16) __nv_bfloat16 g_xlb[NP * NH];   // xl in bf16 (gathered per edge)
__device__ float g_xr[NP * NH];                          // xr in fp32 (read per node)
__device__ __align__(16) __nv_bfloat16 g_hb[NP * NH];    // agg output (bf16 activations)
__device__ __align__(16) __nv_bfloat16 g_xb[NP * NIN];   // input x in bf16
__device__ __align__(16) __nv_bfloat16 g_bfh[4][256 * 128];  // per-layer effective [N,K] hi
__device__ __align__(16) __nv_bfloat16 g_bfl[4][256 * 128];  // lo
__device__ float g_beff[2][256];                             // folded residual bias terms
__device__ int   g_rowoff[NN + 1];
__device__ int   g_cursor[NN];
__device__ int   g_csrc[NE];
__device__ float g_pool[NG * NH];
__device__ float g_cnt[NG];

__device__ __forceinline__ float lrelu(float v) { return v > 0.f ? v : 0.2f * v; }

__device__ __forceinline__ uint32_t smem_u32(const void* p) {
    uint32_t a;
    asm("{ .reg .u64 t; cvta.to.shared.u64 t, %1; cvt.u32.u64 %0, t; }" : "=r"(a) : "l"(p));
    return a;
}
__device__ __forceinline__ void ldsm4(uint32_t* r, uint32_t addr) {
    asm volatile("ldmatrix.sync.aligned.m8n8.x4.shared.b16 {%0,%1,%2,%3}, [%4];"
                 : "=r"(r[0]), "=r"(r[1]), "=r"(r[2]), "=r"(r[3]) : "r"(addr));
}
__device__ __forceinline__ void mma_bf16(float* d, const uint32_t* a, uint32_t b0, uint32_t b1) {
    asm volatile(
        "mma.sync.aligned.m16n8k16.row.col.f32.bf16.bf16.f32 "
        "{%0,%1,%2,%3}, {%4,%5,%6,%7}, {%8,%9}, {%0,%1,%2,%3};"
        : "+f"(d[0]), "+f"(d[1]), "+f"(d[2]), "+f"(d[3])
        : "r"(a[0]), "r"(a[1]), "r"(a[2]), "r"(a[3]), "r"(b0), "r"(b1));
}
__device__ __forceinline__ void cp16(uint32_t dst, const void* src) {
    asm volatile("cp.async.cg.shared.global [%0], [%1], 16;" :: "r"(dst), "l"(src));
}
#define CP_COMMIT_WAIT() \
    asm volatile("cp.async.commit_group;\ncp.async.wait_group 0;" ::: "memory")

// ---------------- CSR build ----------------
__global__ void hist_kernel(const int* __restrict__ dst, int* __restrict__ cnt) {
    int i = blockIdx.x * blockDim.x + threadIdx.x;
    if (i < NE) atomicAdd(&cnt[dst[i]], 1);
}
__global__ void scan_kernel(const int* __restrict__ cnt, int* __restrict__ rowoff,
                            int* __restrict__ cursor) {
    __shared__ int s_carry;
    __shared__ int warpsums[32];
    int lane = threadIdx.x & 31, wid = threadIdx.x >> 5;
    if (threadIdx.x == 0) s_carry = 0;
    __syncthreads();
    for (int base = 0; base < NN; base += 1024) {
        int i = base + (int)threadIdx.x;
        int v = (i < NN) ? cnt[i] : 0;
        int x = v;
#pragma unroll
        for (int o = 1; o < 32; o <<= 1) {
            int y = __shfl_up_sync(0xFFFFFFFFu, x, o);
            if (lane >= o) x += y;
        }
        if (lane == 31) warpsums[wid] = x;
        __syncthreads();
        if (wid == 0) {
            int w = warpsums[lane];
#pragma unroll
            for (int o = 1; o < 32; o <<= 1) {
                int y = __shfl_up_sync(0xFFFFFFFFu, w, o);
                if (lane >= o) w += y;
            }
            warpsums[lane] = w;
        }
        __syncthreads();
        int incl = x + (wid > 0 ? warpsums[wid - 1] : 0) + s_carry;
        int excl = incl - v;
        if (i < NN) { rowoff[i] = excl; cursor[i] = excl; }
        __syncthreads();
        if (threadIdx.x == 1023) s_carry = incl;
        __syncthreads();
    }
    if (threadIdx.x == 0) rowoff[NN] = NE;
}
__global__ void fill_kernel(const int* __restrict__ src, const int* __restrict__ dst,
                            int* __restrict__ cursor, int* __restrict__ csrc) {
    int i = blockIdx.x * blockDim.x + threadIdx.x;
    if (i >= NE) return;
    int pos = atomicAdd(&cursor[dst[i]], 1);
    csrc[pos] = src[i];
}

// ---------------- weight pack+split (transposed to [N,K]) ----------------
__global__ void pack_fused_kernel(const float* __restrict__ Wl, const float* __restrict__ Wr,
                                  __nv_bfloat16* __restrict__ bh, __nv_bfloat16* __restrict__ bl,
                                  int K) {
    int i = blockIdx.x * blockDim.x + threadIdx.x;
    if (i >= 256 * K) return;
    int n = i / K, k = i % K;
    float v = (n < 128) ? Wl[k * 128 + n] : Wr[k * 128 + (n - 128)];
    __nv_bfloat16 h = __float2bfloat16(v);
    bh[i] = h;
    bl[i] = __float2bfloat16(v - __bfloat162float(h));
}
// Weff = (res_w + I) @ [Wl|Wr], stored [n*128 + k] split hi/lo. grid 128, block 256.
__global__ void weff_kernel(const float* __restrict__ res_w, const float* __restrict__ Wl,
                            const float* __restrict__ Wr, __nv_bfloat16* __restrict__ bh,
                            __nv_bfloat16* __restrict__ bl) {
    __shared__ float a[128];
    int r = blockIdx.x;
    int n = threadIdx.x;
    if (n < 128) {
        float v = res_w[r * 128 + n];
        if (n == r) v += 1.f;
        a[n] = v;
    }
    __syncthreads();
    const float* Wp = (n < 128) ? (Wl + n) : (Wr + (n - 128));
    float s = 0.f;
#pragma unroll 8
    for (int k = 0; k < 128; k++) s += a[k] * Wp[k * 128];
    __nv_bfloat16 h = __float2bfloat16(s);
    bh[n * 128 + r] = h;
    bl[n * 128 + r] = __float2bfloat16(s - __bfloat162float(h));
}
// beff[n] = res_b @ [Wl|Wr] column n. 1 block, 256 threads.
__global__ void beff_kernel(const float* __restrict__ res_b, const float* __restrict__ Wl,
                            const float* __restrict__ Wr, float* __restrict__ beff) {
    __shared__ float b[128];
    int n = threadIdx.x;
    if (n < 128) b[n] = res_b[n];
    __syncthreads();
    const float* Wp = (n < 128) ? (Wl + n) : (Wr + (n - 128));
    float s = 0.f;
#pragma unroll 8
    for (int k = 0; k < 128; k++) s += b[k] * Wp[k * 128];
    beff[n] = s;
}
__global__ void split_x_kernel(const float* __restrict__ x, __nv_bfloat16* __restrict__ hi) {
    int i = blockIdx.x * blockDim.x + threadIdx.x;
    if (i >= NN * NIN) return;
    hi[i] = __float2bfloat16(x[i]);
}

// ---------------- tensor-core GEMM via mma.sync (2-term: Abf16 x (Bhi+Blo)) ----------------
// out cols 0-127 -> bf16 xl (ohi), cols 128-255 -> fp32 xr (outF); optional fp32 bias[256].
template <int K, bool FBIAS>
__global__ void __launch_bounds__(256, 2) mm_gemm(
    const __nv_bfloat16* __restrict__ Ab,
    const __nv_bfloat16* __restrict__ Bh, const __nv_bfloat16* __restrict__ Bl,
    const float* __restrict__ bias, float* __restrict__ outF,
    __nv_bfloat16* __restrict__ ohi) {
    extern __shared__ char smem[];
    constexpr int KC = 64, ST = 72;
    constexpr int TB = 128 * ST;
    __nv_bfloat16* sA = (__nv_bfloat16*)smem;
    __nv_bfloat16* sBh = sA + TB;
    __nv_bfloat16* sBl = sBh + TB;
    int tid = threadIdx.x, lane = tid & 31, wid = tid >> 5;
    int warp_m = wid & 3, warp_n = wid >> 2;
    int bm = blockIdx.x * 128, bn = blockIdx.y * 128;
    const __nv_bfloat16* Bh_blk = Bh + (size_t)bn * K;
    const __nv_bfloat16* Bl_blk = Bl + (size_t)bn * K;

    float acc[2][8][4];
#pragma unroll
    for (int i = 0; i < 2; i++)
#pragma unroll
        for (int j = 0; j < 8; j++)
#pragma unroll
            for (int q = 0; q < 4; q++) acc[i][j][q] = 0.f;

    int g = lane >> 3, lr = lane & 7;
    int frow = lr + ((g & 1) << 3);
    int fcol = (g >> 1) << 3;

    for (int kc = 0; kc < K; kc += KC) {
        if (kc) __syncthreads();
#pragma unroll
        for (int idx = tid; idx < 1024; idx += 256) {
            int r = idx >> 3, c = (idx & 7) * 8;
            cp16(smem_u32(&sA[r * ST + c]), &Ab[(size_t)(bm + r) * K + kc + c]);
            cp16(smem_u32(&sBh[r * ST + c]), &Bh_blk[(size_t)r * K + kc + c]);
            cp16(smem_u32(&sBl[r * ST + c]), &Bl_blk[(size_t)r * K + kc + c]);
        }
        CP_COMMIT_WAIT();
        __syncthreads();
#pragma unroll
        for (int ks = 0; ks < 4; ks++) {
            int kcol = ks * 16 + fcol;
            uint32_t ah0[4], ah1[4];
            ldsm4(ah0, smem_u32(&sA[(warp_m * 32 + frow) * ST + kcol]));
            ldsm4(ah1, smem_u32(&sA[(warp_m * 32 + 16 + frow) * ST + kcol]));
#pragma unroll
            for (int tp = 0; tp < 4; tp++) {
                int brow = warp_n * 64 + tp * 16 + frow;
                uint32_t bh[4], bl[4];
                ldsm4(bh, smem_u32(&sBh[brow * ST + kcol]));
                ldsm4(bl, smem_u32(&sBl[brow * ST + kcol]));
                mma_bf16(acc[0][tp * 2 + 0], ah0, bh[0], bh[2]);
                mma_bf16(acc[0][tp * 2 + 1], ah0, bh[1], bh[3]);
                mma_bf16(acc[1][tp * 2 + 0], ah1, bh[0], bh[2]);
                mma_bf16(acc[1][tp * 2 + 1], ah1, bh[1], bh[3]);
                mma_bf16(acc[0][tp * 2 + 0], ah0, bl[0], bl[2]);
                mma_bf16(acc[0][tp * 2 + 1], ah0, bl[1], bl[3]);
                mma_bf16(acc[1][tp * 2 + 0], ah1, bl[0], bl[2]);
                mma_bf16(acc[1][tp * 2 + 1], ah1, bl[1], bl[3]);
            }
        }
    }

    int lr4 = lane >> 2, lc = (lane & 3) * 2;
#pragma unroll
    for (int tm = 0; tm < 2; tm++) {
#pragma unroll
        for (int half = 0; half < 2; half++) {
            int row = bm + warp_m * 32 + tm * 16 + lr4 + half * 8;
#pragma unroll
            for (int tn = 0; tn < 8; tn++) {
                int gc = bn + warp_n * 64 + tn * 8 + lc;
                float v0 = acc[tm][tn][half * 2 + 0];
                float v1 = acc[tm][tn][half * 2 + 1];
                if (FBIAS) { v0 += bias[gc]; v1 += bias[gc + 1]; }
                if (gc < 128) {  // xl half -> bf16
                    __nv_bfloat162 hv = __floats2bfloat162_rn(v0, v1);
                    *(uint32_t*)&ohi[(size_t)row * NH + gc] = *(uint32_t*)&hv;
                } else {         // xr half -> fp32
                    *(float2*)&outF[(size_t)row * NH + (gc - 128)] = make_float2(v0, v1);
                }
            }
        }
    }
}

// ---------------- fused GAT aggregation: warp per node, online softmax ----------------
__device__ __forceinline__ void ol_merge(float& m, float& s, float4& a, float e,
                                         const float4& x) {
    float d = e - m;
    float t = __expf(-fabsf(d));
    bool gt = d > 0.f;
    float fo = gt ? t : 1.f;
    float fe = gt ? 1.f : t;
    m = gt ? e : m;
    s = s * fo + fe;
    a.x = a.x * fo + fe * x.x;
    a.y = a.y * fo + fe * x.y;
    a.z = a.z * fo + fe * x.z;
    a.w = a.w * fo + fe * x.w;
}
__device__ __forceinline__ float4 bf2f4(uint2 u) {
    __nv_bfloat162 p0 = *(__nv_bfloat162*)&u.x;
    __nv_bfloat162 p1 = *(__nv_bfloat162*)&u.y;
    float4 r;
    r.x = __bfloat162float(p0.x);
    r.y = __bfloat162float(p0.y);
    r.z = __bfloat162float(p1.x);
    r.w = __bfloat162float(p1.y);
    return r;
}
__global__ void gat_agg_kernel(const __nv_bfloat16* __restrict__ xlb,
                               const float* __restrict__ xr, const int* __restrict__ rowoff,
                               const int* __restrict__ csrc, const float* __restrict__ att,
                               const float* __restrict__ bias,
                               __nv_bfloat16* __restrict__ ohi,
                               const int* __restrict__ batch, float* __restrict__ pool,
                               float* __restrict__ cnt, float scale) {
    int node = blockIdx.x * 8 + (threadIdx.x >> 5);
    if (node >= NN) return;
    int lane = threadIdx.x & 31;
    const uint2* XB = (const uint2*)xlb;
    float4 xr4 = ((const float4*)xr)[(size_t)node * 32 + lane];
    float4 t = ((const float4*)att)[lane];
    int k = rowoff[node];
    int end = rowoff[node + 1];
    float m0 = -3.0e38f, s0 = 0.f, m1 = -3.0e38f, s1 = 0.f;
    float4 a0 = {0.f, 0.f, 0.f, 0.f}, a1 = {0.f, 0.f, 0.f, 0.f};
    for (; k + 4 <= end; k += 4) {
        int sa = csrc[k], sb = csrc[k + 1], sc = csrc[k + 2], sd = csrc[k + 3];
        float4 xA = bf2f4(XB[(size_t)sa * 32 + lane]);
        float4 xB = bf2f4(XB[(size_t)sb * 32 + lane]);
        float4 xC = bf2f4(XB[(size_t)sc * 32 + lane]);
        float4 xD = bf2f4(XB[(size_t)sd * 32 + lane]);
        float eA = lrelu(xA.x + xr4.x) * t.x + lrelu(xA.y + xr4.y) * t.y +
                   lrelu(xA.z + xr4.z) * t.z + lrelu(xA.w + xr4.w) * t.w;
        float eB = lrelu(xB.x + xr4.x) * t.x + lrelu(xB.y + xr4.y) * t.y +
                   lrelu(xB.z + xr4.z) * t.z + lrelu(xB.w + xr4.w) * t.w;
        float eC = lrelu(xC.x + xr4.x) * t.x + lrelu(xC.y + xr4.y) * t.y +
                   lrelu(xC.z + xr4.z) * t.z + lrelu(xC.w + xr4.w) * t.w;
        float eD = lrelu(xD.x + xr4.x) * t.x + lrelu(xD.y + xr4.y) * t.y +
                   lrelu(xD.z + xr4.z) * t.z + lrelu(xD.w + xr4.w) * t.w;
#pragma unroll
        for (int o = 16; o; o >>= 1) {
            eA += __shfl_xor_sync(0xFFFFFFFFu, eA, o);
            eB += __shfl_xor_sync(0xFFFFFFFFu, eB, o);
            eC += __shfl_xor_sync(0xFFFFFFFFu, eC, o);
            eD += __shfl_xor_sync(0xFFFFFFFFu, eD, o);
        }
        ol_merge(m0, s0, a0, eA, xA);
        ol_merge(m1, s1, a1, eB, xB);
        ol_merge(m0, s0, a0, eC, xC);
        ol_merge(m1, s1, a1, eD, xD);
    }
    for (; k < end; k++) {
        int sa = csrc[k];
        float4 xA = bf2f4(XB[(size_t)sa * 32 + lane]);
        float eA = lrelu(xA.x + xr4.x) * t.x + lrelu(xA.y + xr4.y) * t.y +
                   lrelu(xA.z + xr4.z) * t.z + lrelu(xA.w + xr4.w) * t.w;
#pragma unroll
        for (int o = 16; o; o >>= 1) eA += __shfl_xor_sync(0xFFFFFFFFu, eA, o);
        ol_merge(m0, s0, a0, eA, xA);
    }
    float m = fmaxf(m0, m1);
    float f0 = __expf(m0 - m), f1 = __expf(m1 - m);
    float s = s0 * f0 + s1 * f1;
    float inv = 1.f / (s + 1e-16f);
    float4 b4 = ((const float4*)bias)[lane];
    float4 r;
    r.x = fmaxf((a0.x * f0 + a1.x * f1) * inv + b4.x, 0.f) * scale;
    r.y = fmaxf((a0.y * f0 + a1.y * f1) * inv + b4.y, 0.f) * scale;
    r.z = fmaxf((a0.z * f0 + a1.z * f1) * inv + b4.z, 0.f) * scale;
    r.w = fmaxf((a0.w * f0 + a1.w * f1) * inv + b4.w, 0.f) * scale;
    if (ohi) {
        __nv_bfloat162 h01 = __floats2bfloat162_rn(r.x, r.y);
        __nv_bfloat162 h23 = __floats2bfloat162_rn(r.z, r.w);
        uint2 uh;
        uh.x = *(uint32_t*)&h01;
        uh.y = *(uint32_t*)&h23;
        ((uint2*)ohi)[(size_t)node * 32 + lane] = uh;
    }
    if (pool) {
        int gidx = batch[node];
        atomicAdd((float4*)(pool + (size_t)gidx * NH + lane * 4), r);
        if (lane == 0) atomicAdd(&cnt[gidx], 1.f);
    }
}

// ---------------- final MLP + layernorm ----------------
__global__ void mlp_kernel(const float* __restrict__ pool, const float* __restrict__ cnt,
                           const float* __restrict__ w1, const float* __restrict__ b1,
                           const float* __restrict__ w2, const float* __restrict__ b2,
                           const float* __restrict__ lng, const float* __restrict__ lnb,
                           float* __restrict__ out) {
    int g = blockIdx.x;
    int t = threadIdx.x;
    __shared__ float p[NH];
    __shared__ float z1[2 * NH];
    __shared__ float rs[8], rq[8];
    float inv = 1.f / fmaxf(cnt[g], 1.f);
    if (t < NH) p[t] = pool[g * NH + t] * inv;
    __syncthreads();
    float a = 0.f;
#pragma unroll 8
    for (int k = 0; k < NH; k++) a += p[k] * w1[k * (2 * NH) + t];
    z1[t] = fmaxf(a + b1[t], 0.f);
    __syncthreads();
    float z = 0.f;
#pragma unroll 8
    for (int k = 0; k < 2 * NH; k++) z += z1[k] * w2[k * NO + t];
    z += b2[t];
    float v = z, v2 = z * z;
#pragma unroll
    for (int o = 16; o; o >>= 1) {
        v += __shfl_xor_sync(0xFFFFFFFFu, v, o);
        v2 += __shfl_xor_sync(0xFFFFFFFFu, v2, o);
    }
    int wid = t >> 5, lane = t & 31;
    if (lane == 0) { rs[wid] = v; rq[wid] = v2; }
    __syncthreads();
    if (wid == 0) {
        float sv = lane < 8 ? rs[lane] : 0.f;
        float sq = lane < 8 ? rq[lane] : 0.f;
#pragma unroll
        for (int o = 4; o; o >>= 1) {
            sv += __shfl_xor_sync(0xFFFFFFFFu, sv, o);
            sq += __shfl_xor_sync(0xFFFFFFFFu, sq, o);
        }
        if (lane == 0) { rs[0] = sv; rq[0] = sq; }
    }
    __syncthreads();
    float mu = rs[0] * (1.f / NO);
    float var = rq[0] * (1.f / NO) - mu * mu;
    out[g * NO + t] = (z - mu) * rsqrtf(var + 1e-5f) * lng[t] + lnb[t];
}

// ---------------- host ----------------
extern "C" void kernel_launch(void* const* d_in, const int* in_sizes, int n_in,
                              void* d_out, int out_size) {
    const float* x = (const float*)d_in[0];
    const int* ei = (const int*)d_in[1];
    const int* src = ei;
    const int* dst = ei + NE;
    const int* batch = (const int*)d_in[2];
    const float* Wl[4] = {(const float*)d_in[3], (const float*)d_in[7],
                          (const float*)d_in[11], (const float*)d_in[15]};
    const float* Wr[4] = {(const float*)d_in[4], (const float*)d_in[8],
                          (const float*)d_in[12], (const float*)d_in[16]};
    const float* att[4] = {(const float*)d_in[5], (const float*)d_in[9],
                           (const float*)d_in[13], (const float*)d_in[17]};
    const float* bb[4] = {(const float*)d_in[6], (const float*)d_in[10],
                          (const float*)d_in[14], (const float*)d_in[18]};
    const float* res_w0 = (const float*)d_in[19];
    const float* res_b0 = (const float*)d_in[20];
    const float* res_w2 = (const float*)d_in[21];
    const float* res_b2 = (const float*)d_in[22];
    const float* mh1_w = (const float*)d_in[23];
    const float* mh1_b = (const float*)d_in[24];
    const float* mh2_w = (const float*)d_in[25];
    const float* mh2_b = (const float*)d_in[26];
    const float* ln_g = (const float*)d_in[27];
    const float* ln_b = (const float*)d_in[28];
    float* out = (float*)d_out;

    float *xr, *pool, *cnt, *beff;
    __nv_bfloat16 *xlb, *hb, *xb, *bfh, *bfl;
    int *rowoff, *cursor, *csrc;
    cudaGetSymbolAddress((void**)&xlb, g_xlb);
    cudaGetSymbolAddress((void**)&xr, g_xr);
    cudaGetSymbolAddress((void**)&hb, g_hb);
    cudaGetSymbolAddress((void**)&xb, g_xb);
    cudaGetSymbolAddress((void**)&bfh, g_bfh);
    cudaGetSymbolAddress((void**)&bfl, g_bfl);
    cudaGetSymbolAddress((void**)&beff, g_beff);
    cudaGetSymbolAddress((void**)&rowoff, g_rowoff);
    cudaGetSymbolAddress((void**)&cursor, g_cursor);
    cudaGetSymbolAddress((void**)&csrc, g_csrc);
    cudaGetSymbolAddress((void**)&pool, g_pool);
    cudaGetSymbolAddress((void**)&cnt, g_cnt);

    // ---- smem attrs (idempotent) ----
    const int SMEM_MM = 3 * 128 * 72 * 2;  // 55296
    cudaFuncSetAttribute(mm_gemm<64, false>, cudaFuncAttributeMaxDynamicSharedMemorySize,
                         SMEM_MM);
    cudaFuncSetAttribute(mm_gemm<128, false>, cudaFuncAttributeMaxDynamicSharedMemorySize,
                         SMEM_MM);
    cudaFuncSetAttribute(mm_gemm<128, true>, cudaFuncAttributeMaxDynamicSharedMemorySize,
                         SMEM_MM);

    const int GT = NP / 128;  // 313
    dim3 gf(GT, 2);
    const int AGG_BLK = (NN + 7) / 8;
    const int SLOT = 256 * 128;

    // ---- single side stream (R9-proven topology): CSR chain then weight prep ----
    cudaStream_t s2;
    cudaEvent_t evF, evJ2, evJ3;
    cudaStreamCreateWithFlags(&s2, cudaStreamNonBlocking);
    cudaEventCreateWithFlags(&evF, cudaEventDisableTiming);
    cudaEventCreateWithFlags(&evJ2, cudaEventDisableTiming);
    cudaEventCreateWithFlags(&evJ3, cudaEventDisableTiming);
    cudaEventRecord(evF, 0);
    cudaStreamWaitEvent(s2, evF, 0);

    // s2 (phase A): CSR build + pool init -> evJ2
    cudaMemsetAsync(cursor, 0, NN * sizeof(int), s2);
    hist_kernel<<<(NE + 255) / 256, 256, 0, s2>>>(dst, cursor);
    scan_kernel<<<1, 1024, 0, s2>>>(cursor, rowoff, cursor);
    fill_kernel<<<(NE + 255) / 256, 256, 0, s2>>>(src, dst, cursor, csrc);
    cudaMemsetAsync(pool, 0, NG * NH * sizeof(float), s2);
    cudaMemsetAsync(cnt, 0, NG * sizeof(float), s2);
    cudaEventRecord(evJ2, s2);

    // s2 (phase B): effective weights for layers 2..4 -> evJ3
    weff_kernel<<<128, 256, 0, s2>>>(res_w0, Wl[1], Wr[1], bfh + SLOT, bfl + SLOT);
    beff_kernel<<<1, 256, 0, s2>>>(res_b0, Wl[1], Wr[1], beff);
    pack_fused_kernel<<<(256 * NH + 255) / 256, 256, 0, s2>>>(Wl[2], Wr[2], bfh + 2 * SLOT,
                                                              bfl + 2 * SLOT, NH);
    weff_kernel<<<128, 256, 0, s2>>>(res_w2, Wl[3], Wr[3], bfh + 3 * SLOT, bfl + 3 * SLOT);
    beff_kernel<<<1, 256, 0, s2>>>(res_b2, Wl[3], Wr[3], beff + 256);
    cudaEventRecord(evJ3, s2);

    // main stream: layer-1 dependencies + layer-1 GEMM (overlaps with s2)
    pack_fused_kernel<<<(256 * NIN + 255) / 256, 256>>>(Wl[0], Wr[0], bfh, bfl, NIN);
    split_x_kernel<<<(NN * NIN + 255) / 256, 256>>>(x, xb);
    mm_gemm<64, false><<<gf, 256, SMEM_MM>>>(xb, bfh, bfl, nullptr, xr, xlb);

    // join CSR before first agg; join weights before layer-2 GEMM
    cudaStreamWaitEvent(0, evJ2, 0);
    gat_agg_kernel<<<AGG_BLK, 256>>>(xlb, xr, rowoff, csrc, att[0], bb[0], hb, nullptr, nullptr,
                                     nullptr, 1.f);
    cudaStreamWaitEvent(0, evJ3, 0);
    // layer 2 (residual folded into effective weights + beff bias)
    mm_gemm<128, true><<<gf, 256, SMEM_MM>>>(hb, bfh + SLOT, bfl + SLOT, beff, xr, xlb);
    gat_agg_kernel<<<AGG_BLK, 256>>>(xlb, xr, rowoff, csrc, att[1], bb[1], hb, nullptr, nullptr,
                                     nullptr, 2.f);
    // layer 3
    mm_gemm<128, false><<<gf, 256, SMEM_MM>>>(hb, bfh + 2 * SLOT, bfl + 2 * SLOT, nullptr, xr,
                                              xlb);
    gat_agg_kernel<<<AGG_BLK, 256>>>(xlb, xr, rowoff, csrc, att[2], bb[2], hb, nullptr, nullptr,
                                     nullptr, 1.f);
    // layer 4 (residual folded; agg fuses pooling)
    mm_gemm<128, true><<<gf, 256, SMEM_MM>>>(hb, bfh + 3 * SLOT, bfl + 3 * SLOT, beff + 256, xr,
                                             xlb);
    gat_agg_kernel<<<AGG_BLK, 256>>>(xlb, xr, rowoff, csrc, att[3], bb[3], nullptr, batch, pool,
                                     cnt, 2.f);

    // MLP + layernorm
    mlp_kernel<<<NG, 256>>>(pool, cnt, mh1_w, mh1_b, mh2_w, mh2_b, ln_g, ln_b, out);
}